// round 13
// baseline (speedup 1.0000x reference)
#include <cuda_runtime.h>
#include <cuda_fp16.h>
#include <math.h>
#include <stdint.h>

// ---------------- problem constants ----------------
#define BB   8
#define SS   577
#define DD   768
#define HH   12
#define HDIM 64
#define PP   576
#define KWIN 32
#define MLPD 3072
#define NROWS (BB*SS)        // 4616
#define SCALE_ATT 0.125f
#define TEMP_INV  10.0f

#define TBM 128
#define TBN 128
#define TBK 32
#define W20  20
#define W136 136

__device__ __forceinline__ void cp16(void* dst_smem, const void* src, int srcsize) {
    uint32_t d = (uint32_t)__cvta_generic_to_shared(dst_smem);
    asm volatile("cp.async.cg.shared.global [%0], [%1], 16, %2;"
                 :: "r"(d), "l"(src), "r"(srcsize));
}
__device__ __forceinline__ void mma_f16(float* d, const uint32_t* a, const uint32_t* b) {
    asm volatile(
        "mma.sync.aligned.m16n8k16.row.col.f32.f16.f16.f32 "
        "{%0,%1,%2,%3}, {%4,%5,%6,%7}, {%8,%9}, {%0,%1,%2,%3};"
        : "+f"(d[0]), "+f"(d[1]), "+f"(d[2]), "+f"(d[3])
        : "r"(a[0]), "r"(a[1]), "r"(a[2]), "r"(a[3]), "r"(b[0]), "r"(b[1]));
}
__device__ __forceinline__ void ldsm_x4(uint32_t* r, const void* smem_ptr) {
    uint32_t a = (uint32_t)__cvta_generic_to_shared(smem_ptr);
    asm volatile("ldmatrix.sync.aligned.m8n8.x4.shared.b16 {%0,%1,%2,%3}, [%4];"
                 : "=r"(r[0]), "=r"(r[1]), "=r"(r[2]), "=r"(r[3]) : "r"(a));
}
__device__ __forceinline__ void ldsm_x2(uint32_t* r, const void* smem_ptr) {
    uint32_t a = (uint32_t)__cvta_generic_to_shared(smem_ptr);
    asm volatile("ldmatrix.sync.aligned.m8n8.x2.shared.b16 {%0,%1}, [%2];"
                 : "=r"(r[0]), "=r"(r[1]) : "r"(a));
}
__device__ __forceinline__ void split1(float v, __half& h, __half& l) {
    h = __float2half(v);
    l = __float2half(v - __half2float(h));
}

// ---------------- scratch (device globals) ----------------
__device__ __half g_xnh  [(size_t)BB*SS*DD];
__device__ __half g_xnl  [(size_t)BB*SS*DD];
__device__ float  g_qk   [(size_t)BB*PP*2*DD];
__device__ __half g_qh   [(size_t)BB*PP*DD];
__device__ __half g_ql   [(size_t)BB*PP*DD];
__device__ __half g_kh   [(size_t)BB*PP*DD];
__device__ __half g_kl   [(size_t)BB*PP*DD];
__device__ float  g_scores[(size_t)BB*PP*PP];
__device__ float  g_qkv  [(size_t)BB*SS*3*DD];
__device__ __half g_attn [(size_t)BB*SS*DD];
__device__ float  g_x1   [(size_t)BB*SS*DD];
__device__ __half g_xn2  [(size_t)BB*SS*DD];
__device__ __half g_h    [(size_t)BB*SS*MLPD];
__device__ __half g_rqkv [(size_t)DD*3*DD];
__device__ __half g_rproj[(size_t)DD*DD];
__device__ __half g_rm1  [(size_t)DD*MLPD];
__device__ __half g_rm2  [(size_t)MLPD*DD];
__device__ __half g_wqkh [(size_t)DD*2*DD];
__device__ __half g_wqkl [(size_t)DD*2*DD];
__device__ float  g_bqk  [(size_t)2*DD];

// ---------------- pack big-gemm weights ------------
#define PK_QKV_B  (DD*3*DD/2048)
#define PK_PROJ_B (DD*DD/2048)
#define PK_M1_B   (DD*MLPD/2048)
#define PK_M2_B   (MLPD*DD/2048)
#define PK_BLKS   (PK_QKV_B+PK_PROJ_B+PK_M1_B+PK_M2_B)

__global__ __launch_bounds__(256) void pack_all_kernel(
    const float* __restrict__ wqkv, __half* __restrict__ rqkv,
    const float* __restrict__ wproj, __half* __restrict__ rproj,
    const float* __restrict__ wm1, __half* __restrict__ rm1,
    const float* __restrict__ wm2, __half* __restrict__ rm2)
{
    int bx = blockIdx.x;
    const float* src; __half* dst; int N; long base;
    if (bx < PK_QKV_B)                       { src = wqkv;  dst = rqkv;  N = 3*DD; base = bx; }
    else if (bx < PK_QKV_B+PK_PROJ_B)        { src = wproj; dst = rproj; N = DD;   base = bx-PK_QKV_B; }
    else if (bx < PK_QKV_B+PK_PROJ_B+PK_M1_B){ src = wm1;   dst = rm1;   N = MLPD; base = bx-PK_QKV_B-PK_PROJ_B; }
    else                                     { src = wm2;   dst = rm2;   N = DD;   base = bx-PK_QKV_B-PK_PROJ_B-PK_M1_B; }
    long id = base*256 + threadIdx.x;
    int npg = N/4;
    long k2 = id / npg;
    int  n  = (int)(id % npg) * 4;
    float4 e = *reinterpret_cast<const float4*>(src + (2*k2  )*N + n);
    float4 o = *reinterpret_cast<const float4*>(src + (2*k2+1)*N + n);
    __half2 out[4];
    out[0] = __floats2half2_rn(e.x, o.x);
    out[1] = __floats2half2_rn(e.y, o.y);
    out[2] = __floats2half2_rn(e.z, o.z);
    out[3] = __floats2half2_rn(e.w, o.w);
    *reinterpret_cast<uint4*>(dst + (k2*N + n)*2) = *reinterpret_cast<uint4*>(out);
}

// ---------------- pack routing weights ----------------
#define PKQK_W_B ((DD/2)*(2*DD)/1024)   // 576
__global__ __launch_bounds__(256) void pack_qk_kernel(
    const float* __restrict__ wq, const float* __restrict__ wk,
    const float* __restrict__ bq, const float* __restrict__ bk,
    __half* __restrict__ wh, __half* __restrict__ wl, float* __restrict__ bqk)
{
    int bx = blockIdx.x;
    if (bx == PKQK_W_B) {
        for (int i = threadIdx.x; i < 2*DD; i += 256)
            bqk[i] = (i < DD) ? bq[i] : bk[i - DD];
        return;
    }
    const int N2 = 2*DD;
    long id = (long)bx*256 + threadIdx.x;
    long k2 = id / (N2/4);
    int  n  = (int)(id % (N2/4)) * 4;
    const float* src = (n < DD) ? wq : wk;
    int nn = (n < DD) ? n : n - DD;
    float4 e = *reinterpret_cast<const float4*>(src + (2*k2  )*DD + nn);
    float4 o = *reinterpret_cast<const float4*>(src + (2*k2+1)*DD + nn);
    __half2 oh[4], ol[4];
    #pragma unroll
    for (int u = 0; u < 4; u++) {
        float ev = (&e.x)[u], ov = (&o.x)[u];
        __half eh, el, ohh, oll;
        split1(ev, eh, el); split1(ov, ohh, oll);
        oh[u] = __halves2half2(eh, ohh);
        ol[u] = __halves2half2(el, oll);
    }
    *reinterpret_cast<uint4*>(wh + (k2*N2 + n)*2) = *reinterpret_cast<uint4*>(oh);
    *reinterpret_cast<uint4*>(wl + (k2*N2 + n)*2) = *reinterpret_cast<uint4*>(ol);
}

// ---------------- LayerNorm: fp16 hi out + optional fp16 lo out ------------
__global__ __launch_bounds__(256) void ln_kernel(
    const float* __restrict__ x, const float* __restrict__ g,
    const float* __restrict__ b, __half* __restrict__ yh,
    __half* __restrict__ yl)
{
    int row = blockIdx.x;
    const float* xr = x + (long)row*DD;
    float s = 0.f, sq = 0.f;
    for (int d = threadIdx.x; d < DD; d += 256) {
        float v = xr[d]; s += v; sq += v*v;
    }
    __shared__ float rs[256], rq[256];
    rs[threadIdx.x] = s; rq[threadIdx.x] = sq;
    __syncthreads();
    for (int o = 128; o > 0; o >>= 1) {
        if (threadIdx.x < o) { rs[threadIdx.x] += rs[threadIdx.x+o]; rq[threadIdx.x] += rq[threadIdx.x+o]; }
        __syncthreads();
    }
    __shared__ float mean_s, rstd_s;
    if (threadIdx.x == 0) {
        float mean = rs[0] / (float)DD;
        float var  = rq[0] / (float)DD - mean*mean;
        mean_s = mean;
        rstd_s = rsqrtf(var + 1e-5f);
    }
    __syncthreads();
    float mean = mean_s, rstd = rstd_s;
    __half* yhb = yh + (long)row*DD;
    __half* ylb = yl ? (yl + (long)row*DD) : nullptr;
    for (int d = threadIdx.x; d < DD; d += 256) {
        float v = (xr[d]-mean)*rstd*g[d] + b[d];
        __half h = __float2half(v);
        yhb[d] = h;
        if (ylb) ylb[d] = __float2half(v - __half2float(h));
    }
}

// ---------------- L2 normalize q||k rows + split into hi/lo fp16 -----------
__global__ __launch_bounds__(256) void l2norm_split_kernel(
    const float* __restrict__ qk,
    __half* __restrict__ qh, __half* __restrict__ ql,
    __half* __restrict__ kh, __half* __restrict__ kl)
{
    int row = blockIdx.x;
    int isK = row >= BB*PP;
    int r   = isK ? row - BB*PP : row;
    const float* xr = qk + (long)r*(2*DD) + (isK ? DD : 0);
    float sq = 0.f;
    for (int d = threadIdx.x; d < DD; d += 256) { float v = xr[d]; sq += v*v; }
    __shared__ float rq[256];
    rq[threadIdx.x] = sq;
    __syncthreads();
    for (int o = 128; o > 0; o >>= 1) {
        if (threadIdx.x < o) rq[threadIdx.x] += rq[threadIdx.x+o];
        __syncthreads();
    }
    __shared__ float inv_s;
    if (threadIdx.x == 0) inv_s = 1.0f / fmaxf(sqrtf(rq[0]), 1e-12f);
    __syncthreads();
    float inv = inv_s;
    __half* oh = (isK ? kh : qh) + (long)r*DD;
    __half* ol = (isK ? kl : ql) + (long)r*DD;
    for (int d = threadIdx.x; d < DD; d += 256) {
        float v = xr[d]*inv;
        __half h = __float2half(v);
        oh[d] = h;
        ol[d] = __float2half(v - __half2float(h));
    }
}

// ---------------- fp16 HMMA body: TBK=32, 3-stage, ldmatrix A --------------
template<int EPI>
__device__ __forceinline__ void hmma_body(
    uint32_t (*As)[TBM][W20], uint32_t (*Bs)[16][W136],
    const __half* __restrict__ A, const __half* __restrict__ B2,
    void* __restrict__ Cv, int M, int N, int K, int lda,
    const float* __restrict__ bias, const float* __restrict__ resid,
    int bm, int bn)
{
    int tid  = threadIdx.x;
    int wid  = tid >> 5, lane = tid & 31;
    int wr   = wid & 1;
    int wc   = wid >> 1;
    int g    = lane >> 2;
    int t    = lane & 3;
    int rsel = (lane & 7) + ((lane >> 3) & 1)*8;
    int wsel = (lane >> 4)*4;

    float acc[4][4][4];
    #pragma unroll
    for (int i = 0; i < 4; i++)
        #pragma unroll
        for (int j = 0; j < 4; j++)
            #pragma unroll
            for (int r = 0; r < 4; r++) acc[i][j][r] = 0.f;

    auto load_stage = [&](int buf, int k0) {
        #pragma unroll
        for (int i = 0; i < 2; i++) {
            int id = i*256 + tid;
            int row = id >> 2, c = id & 3;
            int m = bm + row;
            cp16(&As[buf][row][c*4], A + (long)m*lda + k0 + c*8, m < M ? 16 : 0);
        }
        #pragma unroll
        for (int i = 0; i < 2; i++) {
            int id = i*256 + tid;
            int row = id >> 5, c = id & 31;
            cp16(&Bs[buf][row][c*4],
                 B2 + ((long)((k0>>1) + row)*N + bn + c*4)*2, 16);
        }
        asm volatile("cp.async.commit_group;");
    };

    int KT = K >> 5;
    load_stage(0, 0);
    load_stage(1, TBK);
    for (int kt = 0; kt < KT; kt++) {
        if (kt + 2 < KT) asm volatile("cp.async.wait_group 1;");
        else             asm volatile("cp.async.wait_group 0;");
        __syncthreads();
        if (kt + 2 < KT) load_stage((kt+2)%3, (kt+2)*TBK);
        int buf = kt % 3;

        #pragma unroll
        for (int ka = 0; ka < 2; ka++) {
            int kw = ka*8;
            uint32_t afrag[4][4];
            #pragma unroll
            for (int ma = 0; ma < 4; ma++)
                ldsm_x4(afrag[ma], &As[buf][wr*64 + ma*16 + rsel][kw + wsel]);
            uint32_t bfrag[4][2];
            #pragma unroll
            for (int na = 0; na < 4; na++) {
                int c = wc*32 + na*8 + g;
                bfrag[na][0] = Bs[buf][kw + t    ][c];
                bfrag[na][1] = Bs[buf][kw + t + 4][c];
            }
            #pragma unroll
            for (int ma = 0; ma < 4; ma++)
                #pragma unroll
                for (int na = 0; na < 4; na++)
                    mma_f16(acc[ma][na], afrag[ma], bfrag[na]);
        }
    }

    #pragma unroll
    for (int ma = 0; ma < 4; ma++) {
        int row0 = bm + wr*64 + ma*16 + g;
        #pragma unroll
        for (int na = 0; na < 4; na++) {
            int col = bn + wc*32 + na*8 + 2*t;
            float b0 = bias[col], b1 = bias[col+1];
            #pragma unroll
            for (int hh = 0; hh < 2; hh++) {
                int row = row0 + hh*8;
                if (row >= M) continue;
                float v0 = acc[ma][na][hh*2+0] + b0;
                float v1 = acc[ma][na][hh*2+1] + b1;
                if (EPI == 3) {
                    v0 = 0.5f*v0*(1.0f + erff(v0*0.7071067811865475f));
                    v1 = 0.5f*v1*(1.0f + erff(v1*0.7071067811865475f));
                    *reinterpret_cast<__half2*>((__half*)Cv + (long)row*N + col) =
                        __floats2half2_rn(v0, v1);
                } else {
                    if (EPI == 2) {
                        v0 += resid[(long)row*N + col];
                        v1 += resid[(long)row*N + col + 1];
                    }
                    *reinterpret_cast<float2*>((float*)Cv + (long)row*N + col) =
                        make_float2(v0, v1);
                }
            }
        }
    }
}

// ---------------- double-fp16 (3-MMA) NN body, ldmatrix A ------------------
__device__ __forceinline__ void hmma3_nn_body(
    uint32_t (*Ah)[TBM][W20], uint32_t (*Al)[TBM][W20],
    uint32_t (*Bh)[16][W136], uint32_t (*Bl)[16][W136],
    const __half* __restrict__ Axh, const __half* __restrict__ Axl,
    const __half* __restrict__ Bwh, const __half* __restrict__ Bwl,
    float* __restrict__ C, int M, int N, int K, int lda, int ldc,
    const float* __restrict__ bias, int bm, int bn)
{
    int tid = threadIdx.x, wid = tid >> 5, lane = tid & 31;
    int wr = wid & 1, wc = wid >> 1, g = lane >> 2, t = lane & 3;
    int rsel = (lane & 7) + ((lane >> 3) & 1)*8;
    int wsel = (lane >> 4)*4;

    float acc[4][4][4];
    #pragma unroll
    for (int i = 0; i < 4; i++)
        #pragma unroll
        for (int j = 0; j < 4; j++)
            #pragma unroll
            for (int r = 0; r < 4; r++) acc[i][j][r] = 0.f;

    auto load_stage = [&](int buf, int k0) {
        #pragma unroll
        for (int i = 0; i < 2; i++) {
            int id = i*256 + tid;
            int row = id >> 2, c = id & 3;
            int m = bm + row;
            cp16(&Ah[buf][row][c*4], Axh + (long)m*lda + k0 + c*8, m < M ? 16 : 0);
            cp16(&Al[buf][row][c*4], Axl + (long)m*lda + k0 + c*8, m < M ? 16 : 0);
        }
        #pragma unroll
        for (int i = 0; i < 2; i++) {
            int id = i*256 + tid;
            int row = id >> 5, c = id & 31;
            long off = ((long)((k0>>1) + row)*N + bn + c*4)*2;
            cp16(&Bh[buf][row][c*4], Bwh + off, 16);
            cp16(&Bl[buf][row][c*4], Bwl + off, 16);
        }
        asm volatile("cp.async.commit_group;");
    };

    int KT = K >> 5;
    load_stage(0, 0);
    for (int kt = 0; kt < KT; kt++) {
        asm volatile("cp.async.wait_group 0;");
        __syncthreads();
        if (kt + 1 < KT) load_stage((kt+1)&1, (kt+1)*TBK);
        int buf = kt & 1;

        #pragma unroll
        for (int ka = 0; ka < 2; ka++) {
            int kw = ka*8;
            uint32_t bh[4][2], bl[4][2];
            #pragma unroll
            for (int na = 0; na < 4; na++) {
                int c = wc*32 + na*8 + g;
                bh[na][0] = Bh[buf][kw + t][c];  bh[na][1] = Bh[buf][kw + t + 4][c];
                bl[na][0] = Bl[buf][kw + t][c];  bl[na][1] = Bl[buf][kw + t + 4][c];
            }
            #pragma unroll
            for (int ma = 0; ma < 4; ma++) {
                uint32_t ah[4], al[4];
                ldsm_x4(ah, &Ah[buf][wr*64 + ma*16 + rsel][kw + wsel]);
                ldsm_x4(al, &Al[buf][wr*64 + ma*16 + rsel][kw + wsel]);
                #pragma unroll
                for (int na = 0; na < 4; na++) {
                    mma_f16(acc[ma][na], ah, bh[na]);
                    mma_f16(acc[ma][na], ah, bl[na]);
                    mma_f16(acc[ma][na], al, bh[na]);
                }
            }
        }
    }

    #pragma unroll
    for (int ma = 0; ma < 4; ma++) {
        int row0 = bm + wr*64 + ma*16 + g;
        #pragma unroll
        for (int na = 0; na < 4; na++) {
            int col = bn + wc*32 + na*8 + 2*t;
            float b0 = bias[col], b1 = bias[col+1];
            #pragma unroll
            for (int hh = 0; hh < 2; hh++) {
                int row = row0 + hh*8;
                if (row >= M) continue;
                *reinterpret_cast<float2*>(C + (long)row*ldc + col) =
                    make_float2(acc[ma][na][hh*2+0] + b0, acc[ma][na][hh*2+1] + b1);
            }
        }
    }
}

// ---------------- double-fp16 (3-MMA) TN body, ldmatrix A+B ----------------
__device__ __forceinline__ void hmma3_tn_body(
    uint32_t (*Ah)[TBM][W20], uint32_t (*Al)[TBM][W20],
    uint32_t (*Bh)[TBM][W20], uint32_t (*Bl)[TBM][W20],
    const __half* __restrict__ Axh, const __half* __restrict__ Axl,
    const __half* __restrict__ Bxh, const __half* __restrict__ Bxl,
    float* __restrict__ C, int M, int N, int K,
    const float* __restrict__ posb, int bm, int bn)
{
    int tid = threadIdx.x, wid = tid >> 5, lane = tid & 31;
    int wr = wid & 1, wc = wid >> 1, g = lane >> 2, t = lane & 3;
    int rsel  = (lane & 7) + ((lane >> 3) & 1)*8;
    int wsel  = (lane >> 4)*4;
    int rsel2 = lane & 7;
    int wsel2 = ((lane >> 3) & 1)*4;

    float acc[4][4][4];
    #pragma unroll
    for (int i = 0; i < 4; i++)
        #pragma unroll
        for (int j = 0; j < 4; j++)
            #pragma unroll
            for (int r = 0; r < 4; r++) acc[i][j][r] = 0.f;

    auto load_stage = [&](int buf, int k0) {
        #pragma unroll
        for (int i = 0; i < 2; i++) {
            int id = i*256 + tid;
            int row = id >> 2, c = id & 3;
            int m = bm + row;
            cp16(&Ah[buf][row][c*4], Axh + (long)m*K + k0 + c*8, m < M ? 16 : 0);
            cp16(&Al[buf][row][c*4], Axl + (long)m*K + k0 + c*8, m < M ? 16 : 0);
        }
        #pragma unroll
        for (int i = 0; i < 2; i++) {
            int id = i*256 + tid;
            int row = id >> 2, c = id & 3;
            int n = bn + row;
            cp16(&Bh[buf][row][c*4], Bxh + (long)n*K + k0 + c*8, n < N ? 16 : 0);
            cp16(&Bl[buf][row][c*4], Bxl + (long)n*K + k0 + c*8, n < N ? 16 : 0);
        }
        asm volatile("cp.async.commit_group;");
    };

    int KT = K >> 5;
    load_stage(0, 0);
    for (int kt = 0; kt < KT; kt++) {
        asm volatile("cp.async.wait_group 0;");
        __syncthreads();
        if (kt + 1 < KT) load_stage((kt+1)&1, (kt+1)*TBK);
        int buf = kt & 1;

        #pragma unroll
        for (int ka = 0; ka < 2; ka++) {
            int kw = ka*8;
            uint32_t bh[4][2], bl[4][2];
            #pragma unroll
            for (int na = 0; na < 4; na++) {
                ldsm_x2(bh[na], &Bh[buf][wc*32 + na*8 + rsel2][kw + wsel2]);
                ldsm_x2(bl[na], &Bl[buf][wc*32 + na*8 + rsel2][kw + wsel2]);
            }
            #pragma unroll
            for (int ma = 0; ma < 4; ma++) {
                uint32_t ah[4], al[4];
                ldsm_x4(ah, &Ah[buf][wr*64 + ma*16 + rsel][kw + wsel]);
                ldsm_x4(al, &Al[buf][wr*64 + ma*16 + rsel][kw + wsel]);
                #pragma unroll
                for (int na = 0; na < 4; na++) {
                    mma_f16(acc[ma][na], ah, bh[na]);
                    mma_f16(acc[ma][na], ah, bl[na]);
                    mma_f16(acc[ma][na], al, bh[na]);
                }
            }
        }
    }

    #pragma unroll
    for (int ma = 0; ma < 4; ma++) {
        int row0 = bm + wr*64 + ma*16 + g;
        #pragma unroll
        for (int na = 0; na < 4; na++) {
            int col = bn + wc*32 + na*8 + 2*t;
            if (col >= N) continue;
            #pragma unroll
            for (int hh = 0; hh < 2; hh++) {
                int row = row0 + hh*8;
                if (row >= M) continue;
                float v0 = acc[ma][na][hh*2+0] + posb[(long)row*N + col];
                float v1 = acc[ma][na][hh*2+1] + posb[(long)row*N + col + 1];
                if (row == col)   v0 = -1e9f;
                if (row == col+1) v1 = -1e9f;
                *reinterpret_cast<float2*>(C + (long)row*N + col) =
                    make_float2(v0*TEMP_INV, v1*TEMP_INV);
            }
        }
    }
}

// ---------------- shared-memory aggregates (16B aligned) -------------------
union __align__(16) Smem1 {
    struct { uint32_t As[3][TBM][W20]; uint32_t Bs[3][16][W136]; } h;
    struct { uint32_t Ah[2][TBM][W20]; uint32_t Al[2][TBM][W20];
             uint32_t Bh[2][16][W136]; uint32_t Bl[2][16][W136]; } h3;
};
struct __align__(16) Smem2 {
    uint32_t Ah[2][TBM][W20]; uint32_t Al[2][TBM][W20];
    uint32_t Bh[2][TBM][W20]; uint32_t Bl[2][TBM][W20];
};

// ---------------- standalone fp16 GEMM (proj/mlp) ----------------
template<int EPI>
__global__ __launch_bounds__(256, 2) void hmma_nn_kernel(
    const __half* __restrict__ A, const __half* __restrict__ B2,
    void* __restrict__ C, int M, int N, int K, int lda,
    const float* __restrict__ bias, const float* __restrict__ resid)
{
    __shared__ Smem1 sm;
    hmma_body<EPI>(sm.h.As, sm.h.Bs, A, B2, C, M, N, K, lda, bias, resid,
                   blockIdx.y*TBM, blockIdx.x*TBN);
}

// ---------------- CLS attention body ----------------
__device__ void cls_attn_body(const float* __restrict__ qkv,
                              __half* __restrict__ attn, int blk)
{
    int b = blk / HH, h = blk % HH;
    const float* base = qkv + (long)b*SS*3*DD;
    int tid = threadIdx.x;
    __shared__ float qv[HDIM];
    __shared__ float sc[SS];
    __shared__ float red[256];
    __shared__ float m_s, z_s;
    if (tid < HDIM) qv[tid] = base[h*HDIM + tid];
    __syncthreads();

    float lmax = -INFINITY;
    for (int k = tid; k < SS; k += 256) {
        const float* kr = base + (long)k*3*DD + DD + h*HDIM;
        float dot = 0.f;
        #pragma unroll
        for (int d = 0; d < HDIM; d++) dot = fmaf(qv[d], kr[d], dot);
        float s = dot * SCALE_ATT;
        sc[k] = s;
        lmax = fmaxf(lmax, s);
    }
    red[tid] = lmax;
    __syncthreads();
    for (int o = 128; o > 0; o >>= 1) {
        if (tid < o) red[tid] = fmaxf(red[tid], red[tid+o]);
        __syncthreads();
    }
    if (tid == 0) m_s = red[0];
    __syncthreads();
    float m = m_s, lsum = 0.f;
    for (int k = tid; k < SS; k += 256) {
        float e = expf(sc[k]-m); sc[k] = e; lsum += e;
    }
    red[tid] = lsum;
    __syncthreads();
    for (int o = 128; o > 0; o >>= 1) {
        if (tid < o) red[tid] += red[tid+o];
        __syncthreads();
    }
    if (tid == 0) z_s = red[0];
    __syncthreads();
    float zinv = 1.0f / z_s;

    int d = tid & 63, part = tid >> 6;
    float acc = 0.f;
    for (int k = part; k < SS; k += 4)
        acc = fmaf(sc[k], base[(long)k*3*DD + 2*DD + h*HDIM + d], acc);
    __shared__ float ro[4][HDIM];
    ro[part][d] = acc;
    __syncthreads();
    if (tid < HDIM)
        attn[((long)b*SS)*DD + h*HDIM + tid] =
            __float2half((ro[0][tid]+ro[1][tid]+ro[2][tid]+ro[3][tid]) * zinv);
}

// ---------------- fused: routing scores (hmma3 TN) + CLS attention ---------
#define SC_NX ((PP+127)/128)                  // 5
#define SC_MY ((PP+127)/128)                  // 5
#define SC_BLKS (SC_NX*SC_MY*BB)              // 200

__global__ __launch_bounds__(256, 2) void fused_scores_cls_kernel(
    const __half* __restrict__ qh, const __half* __restrict__ ql,
    const __half* __restrict__ kh, const __half* __restrict__ kl,
    float* __restrict__ scores, const float* __restrict__ posb,
    const float* __restrict__ qkv, __half* __restrict__ attn)
{
    int bx = blockIdx.x;
    if (bx < SC_BLKS) {
        __shared__ Smem2 sm;
        int nx = bx % SC_NX;
        int my = (bx / SC_NX) % SC_MY;
        int bz = bx / (SC_NX*SC_MY);
        hmma3_tn_body(sm.Ah, sm.Al, sm.Bh, sm.Bl,
                      qh + (long)bz*PP*DD, ql + (long)bz*PP*DD,
                      kh + (long)bz*PP*DD, kl + (long)bz*PP*DD,
                      scores + (long)bz*PP*PP, PP, PP, DD,
                      posb, my*128, nx*128);
    } else {
        cls_attn_body(qkv, attn, bx - SC_BLKS);
    }
}

// ---------------- fused: QKV (hmma) + q||k routing proj (hmma3 NN) ---------
#define QKV_NX  (3*DD/TBN)                    // 18
#define QKV_MY  ((NROWS+TBM-1)/TBM)           // 37
#define QKV_BLKS (QKV_NX*QKV_MY)              // 666
#define QK2_NX  (2*DD/TBN)                    // 12
#define QK2_MY  ((PP+TBM-1)/TBM)              // 5
#define QK2_BLKS (QK2_NX*QK2_MY*BB)           // 480

__global__ __launch_bounds__(256, 2) void fused_qkv_qkproj_kernel(
    const __half* __restrict__ xnh, const __half* __restrict__ xnl,
    const __half* __restrict__ rqkv, const float* __restrict__ b_qkv,
    float* __restrict__ qkvb,
    const __half* __restrict__ wqkh, const __half* __restrict__ wqkl,
    const float* __restrict__ bqk, float* __restrict__ qk)
{
    __shared__ Smem1 sm;
    int bx = blockIdx.x;
    if (bx < QKV_BLKS) {
        int bn = (bx % QKV_NX)*TBN, bm = (bx / QKV_NX)*TBM;
        hmma_body<0>(sm.h.As, sm.h.Bs, xnh, rqkv, qkvb,
                     NROWS, 3*DD, DD, DD, b_qkv, nullptr, bm, bn);
    } else {
        int rel = bx - QKV_BLKS;
        int nx = rel % QK2_NX;
        int my = (rel / QK2_NX) % QK2_MY;
        int bz = rel / (QK2_NX*QK2_MY);
        hmma3_nn_body(sm.h3.Ah, sm.h3.Al, sm.h3.Bh, sm.h3.Bl,
                      xnh + (long)bz*SS*DD + DD,
                      xnl + (long)bz*SS*DD + DD,
                      wqkh, wqkl,
                      qk + (long)bz*PP*2*DD, PP, 2*DD, DD, DD, 2*DD,
                      bqk, my*128, nx*128);
    }
}

// ---------------- FUSED: top-32 + 12-head patch attention per (b,p) --------
__global__ __launch_bounds__(384) void route_attn_kernel(
    const float* __restrict__ scores, const float* __restrict__ qkv,
    __half* __restrict__ attn)
{
    int id = blockIdx.x;                  // b*PP + p
    int p = id % PP;
    int b = id / PP;
    int tid = threadIdx.x;
    int wid = tid >> 5, lane = tid & 31;
    const float* base = qkv + (long)b*SS*3*DD;

    __shared__ float qs[DD];              // full q row (all 12 heads)
    __shared__ int   sr[KWIN];
    __shared__ float slogw[KWIN];

    // all threads: preload q row (768 floats) — independent of topk
    qs[tid]       = base[(long)(p+1)*3*DD + tid];
    qs[tid + 384] = base[(long)(p+1)*3*DD + tid + 384];

    // warp 0: register top-32 + log-softmax (identical algorithm to R12)
    if (wid == 0) {
        const float* srw = scores + (long)id*PP;
        float v[18];
        #pragma unroll
        for (int j = 0; j < 18; j++) v[j] = srw[j*32 + lane];

        float myTop = 0.f;
        for (int tt = 0; tt < KWIN; tt++) {
            float bv = -INFINITY; int bj = 0;
            #pragma unroll
            for (int j = 0; j < 18; j++)
                if (v[j] > bv) { bv = v[j]; bj = j; }
            int bi = bj*32 + lane;
            #pragma unroll
            for (int o = 16; o > 0; o >>= 1) {
                float ov = __shfl_xor_sync(0xffffffffu, bv, o);
                int   oi = __shfl_xor_sync(0xffffffffu, bi, o);
                if (ov > bv || (ov == bv && oi < bi)) { bv = ov; bi = oi; }
            }
            if (lane == (bi & 31)) v[bi >> 5] = -INFINITY;
            if (lane == tt) myTop = bv;
            if (lane == 0)  sr[tt] = bi;
        }
        float m = __shfl_sync(0xffffffffu, myTop, 0);
        float e = expf(myTop - m);
        float z = e;
        #pragma unroll
        for (int o = 16; o > 0; o >>= 1) z += __shfl_xor_sync(0xffffffffu, z, o);
        float lse = m + logf(z);
        slogw[lane] = fmaxf(myTop - lse, -10.0f);
    }
    __syncthreads();

    // warp h (0..11): patch attention for head h over the 32 routed keys
    int h = wid;
    int k = lane;
    const float* kr = base + (long)(sr[k]+1)*3*DD + DD + h*HDIM;
    float dot = 0.f;
    #pragma unroll
    for (int d = 0; d < HDIM; d++) dot = fmaf(qs[h*HDIM + d], kr[d], dot);
    float s = dot * SCALE_ATT + slogw[k];
    float m = s;
    #pragma unroll
    for (int o = 16; o > 0; o >>= 1) m = fmaxf(m, __shfl_xor_sync(0xffffffffu, m, o));
    float e = expf(s - m);
    float z = e;
    #pragma unroll
    for (int o = 16; o > 0; o >>= 1) z += __shfl_xor_sync(0xffffffffu, z, o);
    float a = e / z;

    float acc0 = 0.f, acc1 = 0.f;
    #pragma unroll 8
    for (int kk = 0; kk < KWIN; kk++) {
        float av = __shfl_sync(0xffffffffu, a, kk);
        const float* vr = base + (long)(sr[kk]+1)*3*DD + 2*DD + h*HDIM;
        acc0 = fmaf(av, vr[lane],      acc0);
        acc1 = fmaf(av, vr[lane + 32], acc1);
    }
    __half* orow = attn + ((long)b*SS + p+1)*DD + h*HDIM;
    orow[lane]      = __float2half(acc0);
    orow[lane + 32] = __float2half(acc1);
}

// ---------------- launcher ----------------
extern "C" void kernel_launch(void* const* d_in, const int* in_sizes, int n_in,
                              void* d_out, int out_size)
{
    const float* x      = (const float*)d_in[0];
    const float* g1     = (const float*)d_in[1];
    const float* b1     = (const float*)d_in[2];
    const float* wq     = (const float*)d_in[3];
    const float* bq     = (const float*)d_in[4];
    const float* wk     = (const float*)d_in[5];
    const float* bk     = (const float*)d_in[6];
    const float* posb   = (const float*)d_in[7];
    const float* w_qkv  = (const float*)d_in[8];
    const float* b_qkv  = (const float*)d_in[9];
    const float* w_proj = (const float*)d_in[10];
    const float* b_proj = (const float*)d_in[11];
    const float* g2     = (const float*)d_in[12];
    const float* b2     = (const float*)d_in[13];
    const float* w_mlp1 = (const float*)d_in[14];
    const float* b_mlp1 = (const float*)d_in[15];
    const float* w_mlp2 = (const float*)d_in[16];
    const float* b_mlp2 = (const float*)d_in[17];
    float* out = (float*)d_out;

    float *qk, *scores, *qkvb, *x1, *bqk;
    __half *xnh, *xnl, *qh, *ql, *kh, *kl, *attn, *xn2, *hbuf;
    __half *rqkv, *rproj, *rm1, *rm2, *wqkh, *wqkl;
    cudaGetSymbolAddress((void**)&xnh,    g_xnh);
    cudaGetSymbolAddress((void**)&xnl,    g_xnl);
    cudaGetSymbolAddress((void**)&qk,     g_qk);
    cudaGetSymbolAddress((void**)&qh,     g_qh);
    cudaGetSymbolAddress((void**)&ql,     g_ql);
    cudaGetSymbolAddress((void**)&kh,     g_kh);
    cudaGetSymbolAddress((void**)&kl,     g_kl);
    cudaGetSymbolAddress((void**)&scores, g_scores);
    cudaGetSymbolAddress((void**)&qkvb,   g_qkv);
    cudaGetSymbolAddress((void**)&attn,   g_attn);
    cudaGetSymbolAddress((void**)&x1,     g_x1);
    cudaGetSymbolAddress((void**)&xn2,    g_xn2);
    cudaGetSymbolAddress((void**)&hbuf,   g_h);
    cudaGetSymbolAddress((void**)&rqkv,   g_rqkv);
    cudaGetSymbolAddress((void**)&rproj,  g_rproj);
    cudaGetSymbolAddress((void**)&rm1,    g_rm1);
    cudaGetSymbolAddress((void**)&rm2,    g_rm2);
    cudaGetSymbolAddress((void**)&wqkh,   g_wqkh);
    cudaGetSymbolAddress((void**)&wqkl,   g_wqkl);
    cudaGetSymbolAddress((void**)&bqk,    g_bqk);

    // 0. weight prep
    pack_all_kernel<<<PK_BLKS, 256>>>(w_qkv, rqkv, w_proj, rproj,
                                      w_mlp1, rm1, w_mlp2, rm2);
    pack_qk_kernel<<<PKQK_W_B + 1, 256>>>(wq, wk, bq, bk, wqkh, wqkl, bqk);

    // 1. LN1 -> hi + lo fp16
    ln_kernel<<<NROWS, 256>>>(x, g1, b1, xnh, xnl);

    // 2. FUSED: QKV (fp16 HMMA) + q||k routing projection (double-fp16 3-MMA)
    fused_qkv_qkproj_kernel<<<QKV_BLKS + QK2_BLKS, 256>>>(
        xnh, xnl, rqkv, b_qkv, qkvb, wqkh, wqkl, bqk, qk);

    // 3. l2 normalize + split q,k into hi/lo fp16
    l2norm_split_kernel<<<2*BB*PP, 256>>>(qk, qh, ql, kh, kl);

    // 4. FUSED: routing scores (double-fp16 TN) + CLS attention
    fused_scores_cls_kernel<<<SC_BLKS + BB*HH, 256>>>(
        qh, ql, kh, kl, scores, posb, qkvb, attn);

    // 5. FUSED: top-32 + log-softmax + 12-head patch attention
    route_attn_kernel<<<BB*PP, 384>>>(scores, qkvb, attn);

    // 6. proj + residual x (fp16 HMMA, fp32 out)
    {
        dim3 grid(DD/TBN, (NROWS+TBM-1)/TBM);
        hmma_nn_kernel<2><<<grid, 256>>>(attn, rproj, x1, NROWS, DD, DD, DD,
                                         b_proj, x);
    }
    // 7. LN2 (fp16 hi only, feeds MLP1)
    ln_kernel<<<NROWS, 256>>>(x1, g2, b2, xn2, nullptr);

    // 8. MLP1 + exact GELU (fp16 HMMA, fp16 out)
    {
        dim3 grid(MLPD/TBN, (NROWS+TBM-1)/TBM);
        hmma_nn_kernel<3><<<grid, 256>>>(xn2, rm1, hbuf, NROWS, MLPD, DD, DD,
                                         b_mlp1, nullptr);
    }
    // 9. MLP2 + residual x1 -> out (fp16 HMMA, fp32 out)
    {
        dim3 grid(DD/TBN, (NROWS+TBM-1)/TBM);
        hmma_nn_kernel<2><<<grid, 256>>>(hbuf, rm2, out, NROWS, DD, MLPD, MLPD,
                                         b_mlp2, x1);
    }
}

// round 14
// speedup vs baseline: 1.0486x; 1.0486x over previous
#include <cuda_runtime.h>
#include <cuda_fp16.h>
#include <math.h>
#include <stdint.h>

// ---------------- problem constants ----------------
#define BB   8
#define SS   577
#define DD   768
#define HH   12
#define HDIM 64
#define PP   576
#define KWIN 32
#define MLPD 3072
#define NROWS (BB*SS)        // 4616
#define SCALE_ATT 0.125f
#define TEMP_INV  10.0f

#define TBM 128
#define TBN 128
#define W20  20
#define W36  36     // TBK=64 A-tile row words: 32 data + 4 pad
#define W136 136

__device__ __forceinline__ void cp16(void* dst_smem, const void* src, int srcsize) {
    uint32_t d = (uint32_t)__cvta_generic_to_shared(dst_smem);
    asm volatile("cp.async.cg.shared.global [%0], [%1], 16, %2;"
                 :: "r"(d), "l"(src), "r"(srcsize));
}
__device__ __forceinline__ void mma_f16(float* d, const uint32_t* a, const uint32_t* b) {
    asm volatile(
        "mma.sync.aligned.m16n8k16.row.col.f32.f16.f16.f32 "
        "{%0,%1,%2,%3}, {%4,%5,%6,%7}, {%8,%9}, {%0,%1,%2,%3};"
        : "+f"(d[0]), "+f"(d[1]), "+f"(d[2]), "+f"(d[3])
        : "r"(a[0]), "r"(a[1]), "r"(a[2]), "r"(a[3]), "r"(b[0]), "r"(b[1]));
}
__device__ __forceinline__ void ldsm_x4(uint32_t* r, const void* smem_ptr) {
    uint32_t a = (uint32_t)__cvta_generic_to_shared(smem_ptr);
    asm volatile("ldmatrix.sync.aligned.m8n8.x4.shared.b16 {%0,%1,%2,%3}, [%4];"
                 : "=r"(r[0]), "=r"(r[1]), "=r"(r[2]), "=r"(r[3]) : "r"(a));
}
__device__ __forceinline__ void ldsm_x2(uint32_t* r, const void* smem_ptr) {
    uint32_t a = (uint32_t)__cvta_generic_to_shared(smem_ptr);
    asm volatile("ldmatrix.sync.aligned.m8n8.x2.shared.b16 {%0,%1}, [%2];"
                 : "=r"(r[0]), "=r"(r[1]) : "r"(a));
}
__device__ __forceinline__ void split1(float v, __half& h, __half& l) {
    h = __float2half(v);
    l = __float2half(v - __half2float(h));
}

// ---------------- scratch (device globals) ----------------
__device__ __half g_xnh  [(size_t)BB*SS*DD];
__device__ __half g_xnl  [(size_t)BB*SS*DD];
__device__ float  g_qk   [(size_t)BB*PP*2*DD];
__device__ __half g_qh   [(size_t)BB*PP*DD];
__device__ __half g_ql   [(size_t)BB*PP*DD];
__device__ __half g_kh   [(size_t)BB*PP*DD];
__device__ __half g_kl   [(size_t)BB*PP*DD];
__device__ float  g_scores[(size_t)BB*PP*PP];
__device__ int    g_routes[(size_t)BB*PP*KWIN];
__device__ float  g_logw  [(size_t)BB*PP*KWIN];
__device__ float  g_qkv  [(size_t)BB*SS*3*DD];
__device__ __half g_attn [(size_t)BB*SS*DD];
__device__ float  g_x1   [(size_t)BB*SS*DD];
__device__ __half g_xn2  [(size_t)BB*SS*DD];
__device__ __half g_h    [(size_t)BB*SS*MLPD];
__device__ __half g_rqkv [(size_t)DD*3*DD];
__device__ __half g_rproj[(size_t)DD*DD];
__device__ __half g_rm1  [(size_t)DD*MLPD];
__device__ __half g_rm2  [(size_t)MLPD*DD];
__device__ __half g_wqkh [(size_t)DD*2*DD];
__device__ __half g_wqkl [(size_t)DD*2*DD];
__device__ float  g_bqk  [(size_t)2*DD];

// ---------------- pack big-gemm weights ------------
#define PK_QKV_B  (DD*3*DD/2048)
#define PK_PROJ_B (DD*DD/2048)
#define PK_M1_B   (DD*MLPD/2048)
#define PK_M2_B   (MLPD*DD/2048)
#define PK_BLKS   (PK_QKV_B+PK_PROJ_B+PK_M1_B+PK_M2_B)

__global__ __launch_bounds__(256) void pack_all_kernel(
    const float* __restrict__ wqkv, __half* __restrict__ rqkv,
    const float* __restrict__ wproj, __half* __restrict__ rproj,
    const float* __restrict__ wm1, __half* __restrict__ rm1,
    const float* __restrict__ wm2, __half* __restrict__ rm2)
{
    int bx = blockIdx.x;
    const float* src; __half* dst; int N; long base;
    if (bx < PK_QKV_B)                       { src = wqkv;  dst = rqkv;  N = 3*DD; base = bx; }
    else if (bx < PK_QKV_B+PK_PROJ_B)        { src = wproj; dst = rproj; N = DD;   base = bx-PK_QKV_B; }
    else if (bx < PK_QKV_B+PK_PROJ_B+PK_M1_B){ src = wm1;   dst = rm1;   N = MLPD; base = bx-PK_QKV_B-PK_PROJ_B; }
    else                                     { src = wm2;   dst = rm2;   N = DD;   base = bx-PK_QKV_B-PK_PROJ_B-PK_M1_B; }
    long id = base*256 + threadIdx.x;
    int npg = N/4;
    long k2 = id / npg;
    int  n  = (int)(id % npg) * 4;
    float4 e = *reinterpret_cast<const float4*>(src + (2*k2  )*N + n);
    float4 o = *reinterpret_cast<const float4*>(src + (2*k2+1)*N + n);
    __half2 out[4];
    out[0] = __floats2half2_rn(e.x, o.x);
    out[1] = __floats2half2_rn(e.y, o.y);
    out[2] = __floats2half2_rn(e.z, o.z);
    out[3] = __floats2half2_rn(e.w, o.w);
    *reinterpret_cast<uint4*>(dst + (k2*N + n)*2) = *reinterpret_cast<uint4*>(out);
}

// ---------------- pack routing weights ----------------
#define PKQK_W_B ((DD/2)*(2*DD)/1024)   // 576
__global__ __launch_bounds__(256) void pack_qk_kernel(
    const float* __restrict__ wq, const float* __restrict__ wk,
    const float* __restrict__ bq, const float* __restrict__ bk,
    __half* __restrict__ wh, __half* __restrict__ wl, float* __restrict__ bqk)
{
    int bx = blockIdx.x;
    if (bx == PKQK_W_B) {
        for (int i = threadIdx.x; i < 2*DD; i += 256)
            bqk[i] = (i < DD) ? bq[i] : bk[i - DD];
        return;
    }
    const int N2 = 2*DD;
    long id = (long)bx*256 + threadIdx.x;
    long k2 = id / (N2/4);
    int  n  = (int)(id % (N2/4)) * 4;
    const float* src = (n < DD) ? wq : wk;
    int nn = (n < DD) ? n : n - DD;
    float4 e = *reinterpret_cast<const float4*>(src + (2*k2  )*DD + nn);
    float4 o = *reinterpret_cast<const float4*>(src + (2*k2+1)*DD + nn);
    __half2 oh[4], ol[4];
    #pragma unroll
    for (int u = 0; u < 4; u++) {
        float ev = (&e.x)[u], ov = (&o.x)[u];
        __half eh, el, ohh, oll;
        split1(ev, eh, el); split1(ov, ohh, oll);
        oh[u] = __halves2half2(eh, ohh);
        ol[u] = __halves2half2(el, oll);
    }
    *reinterpret_cast<uint4*>(wh + (k2*N2 + n)*2) = *reinterpret_cast<uint4*>(oh);
    *reinterpret_cast<uint4*>(wl + (k2*N2 + n)*2) = *reinterpret_cast<uint4*>(ol);
}

// ---------------- LayerNorm: fp16 hi out + optional fp16 lo out ------------
__global__ __launch_bounds__(256) void ln_kernel(
    const float* __restrict__ x, const float* __restrict__ g,
    const float* __restrict__ b, __half* __restrict__ yh,
    __half* __restrict__ yl)
{
    int row = blockIdx.x;
    const float* xr = x + (long)row*DD;
    float s = 0.f, sq = 0.f;
    for (int d = threadIdx.x; d < DD; d += 256) {
        float v = xr[d]; s += v; sq += v*v;
    }
    __shared__ float rs[256], rq[256];
    rs[threadIdx.x] = s; rq[threadIdx.x] = sq;
    __syncthreads();
    for (int o = 128; o > 0; o >>= 1) {
        if (threadIdx.x < o) { rs[threadIdx.x] += rs[threadIdx.x+o]; rq[threadIdx.x] += rq[threadIdx.x+o]; }
        __syncthreads();
    }
    __shared__ float mean_s, rstd_s;
    if (threadIdx.x == 0) {
        float mean = rs[0] / (float)DD;
        float var  = rq[0] / (float)DD - mean*mean;
        mean_s = mean;
        rstd_s = rsqrtf(var + 1e-5f);
    }
    __syncthreads();
    float mean = mean_s, rstd = rstd_s;
    __half* yhb = yh + (long)row*DD;
    __half* ylb = yl ? (yl + (long)row*DD) : nullptr;
    for (int d = threadIdx.x; d < DD; d += 256) {
        float v = (xr[d]-mean)*rstd*g[d] + b[d];
        __half h = __float2half(v);
        yhb[d] = h;
        if (ylb) ylb[d] = __float2half(v - __half2float(h));
    }
}

// ---------------- L2 normalize q||k rows + split into hi/lo fp16 -----------
__global__ __launch_bounds__(256) void l2norm_split_kernel(
    const float* __restrict__ qk,
    __half* __restrict__ qh, __half* __restrict__ ql,
    __half* __restrict__ kh, __half* __restrict__ kl)
{
    int row = blockIdx.x;
    int isK = row >= BB*PP;
    int r   = isK ? row - BB*PP : row;
    const float* xr = qk + (long)r*(2*DD) + (isK ? DD : 0);
    float sq = 0.f;
    for (int d = threadIdx.x; d < DD; d += 256) { float v = xr[d]; sq += v*v; }
    __shared__ float rq[256];
    rq[threadIdx.x] = sq;
    __syncthreads();
    for (int o = 128; o > 0; o >>= 1) {
        if (threadIdx.x < o) rq[threadIdx.x] += rq[threadIdx.x+o];
        __syncthreads();
    }
    __shared__ float inv_s;
    if (threadIdx.x == 0) inv_s = 1.0f / fmaxf(sqrtf(rq[0]), 1e-12f);
    __syncthreads();
    float inv = inv_s;
    __half* oh = (isK ? kh : qh) + (long)r*DD;
    __half* ol = (isK ? kl : ql) + (long)r*DD;
    for (int d = threadIdx.x; d < DD; d += 256) {
        float v = xr[d]*inv;
        __half h = __float2half(v);
        oh[d] = h;
        ol[d] = __float2half(v - __half2float(h));
    }
}

// ---------------- fp16 HMMA body: TBK=64, 2-stage, ldmatrix A --------------
// EPI: 0 = +bias (fp32 C) ; 2 = +bias+resid (fp32 C) ; 3 = +bias+GELU (fp16 C)
template<int EPI>
__device__ __forceinline__ void hmma_body(
    uint32_t (*As)[TBM][W36], uint32_t (*Bs)[32][W136],
    const __half* __restrict__ A, const __half* __restrict__ B2,
    void* __restrict__ Cv, int M, int N, int K, int lda,
    const float* __restrict__ bias, const float* __restrict__ resid,
    int bm, int bn)
{
    int tid  = threadIdx.x;
    int wid  = tid >> 5, lane = tid & 31;
    int wr   = wid & 1;
    int wc   = wid >> 1;
    int g    = lane >> 2;
    int t    = lane & 3;
    int rsel = (lane & 7) + ((lane >> 3) & 1)*8;
    int wsel = (lane >> 4)*4;

    float acc[4][4][4];
    #pragma unroll
    for (int i = 0; i < 4; i++)
        #pragma unroll
        for (int j = 0; j < 4; j++)
            #pragma unroll
            for (int r = 0; r < 4; r++) acc[i][j][r] = 0.f;

    auto load_stage = [&](int buf, int k0) {
        // A: 128 rows x 64 halves = 1024 x 16B chunks
        #pragma unroll
        for (int i = 0; i < 4; i++) {
            int id = i*256 + tid;
            int row = id >> 3, c = id & 7;
            int m = bm + row;
            cp16(&As[buf][row][c*4], A + (long)m*lda + k0 + c*8, m < M ? 16 : 0);
        }
        // B: 32 k-pair rows x 128 half2 = 1024 x 16B chunks
        #pragma unroll
        for (int i = 0; i < 4; i++) {
            int id = i*256 + tid;
            int row = id >> 5, c = id & 31;
            cp16(&Bs[buf][row][c*4],
                 B2 + ((long)((k0>>1) + row)*N + bn + c*4)*2, 16);
        }
        asm volatile("cp.async.commit_group;");
    };

    int KT = K >> 6;
    load_stage(0, 0);
    for (int kt = 0; kt < KT; kt++) {
        asm volatile("cp.async.wait_group 0;");
        __syncthreads();
        if (kt + 1 < KT) load_stage((kt+1)&1, (kt+1)*64);
        int buf = kt & 1;

        #pragma unroll
        for (int ka = 0; ka < 4; ka++) {          // four k16 steps per TBK=64
            int kw = ka*8;
            uint32_t afrag[4][4];
            #pragma unroll
            for (int ma = 0; ma < 4; ma++)
                ldsm_x4(afrag[ma], &As[buf][wr*64 + ma*16 + rsel][kw + wsel]);
            uint32_t bfrag[4][2];
            #pragma unroll
            for (int na = 0; na < 4; na++) {
                int c = wc*32 + na*8 + g;
                bfrag[na][0] = Bs[buf][kw + t    ][c];
                bfrag[na][1] = Bs[buf][kw + t + 4][c];
            }
            #pragma unroll
            for (int ma = 0; ma < 4; ma++)
                #pragma unroll
                for (int na = 0; na < 4; na++)
                    mma_f16(acc[ma][na], afrag[ma], bfrag[na]);
        }
    }

    #pragma unroll
    for (int ma = 0; ma < 4; ma++) {
        int row0 = bm + wr*64 + ma*16 + g;
        #pragma unroll
        for (int na = 0; na < 4; na++) {
            int col = bn + wc*32 + na*8 + 2*t;
            float b0 = bias[col], b1 = bias[col+1];
            #pragma unroll
            for (int hh = 0; hh < 2; hh++) {
                int row = row0 + hh*8;
                if (row >= M) continue;
                float v0 = acc[ma][na][hh*2+0] + b0;
                float v1 = acc[ma][na][hh*2+1] + b1;
                if (EPI == 3) {
                    v0 = 0.5f*v0*(1.0f + erff(v0*0.7071067811865475f));
                    v1 = 0.5f*v1*(1.0f + erff(v1*0.7071067811865475f));
                    *reinterpret_cast<__half2*>((__half*)Cv + (long)row*N + col) =
                        __floats2half2_rn(v0, v1);
                } else {
                    if (EPI == 2) {
                        v0 += resid[(long)row*N + col];
                        v1 += resid[(long)row*N + col + 1];
                    }
                    *reinterpret_cast<float2*>((float*)Cv + (long)row*N + col) =
                        make_float2(v0, v1);
                }
            }
        }
    }
}

// ---------------- double-fp16 (3-MMA) NN body, TBK=32, ldmatrix A ----------
__device__ __forceinline__ void hmma3_nn_body(
    uint32_t (*Ah)[TBM][W20], uint32_t (*Al)[TBM][W20],
    uint32_t (*Bh)[16][W136], uint32_t (*Bl)[16][W136],
    const __half* __restrict__ Axh, const __half* __restrict__ Axl,
    const __half* __restrict__ Bwh, const __half* __restrict__ Bwl,
    float* __restrict__ C, int M, int N, int K, int lda, int ldc,
    const float* __restrict__ bias, int bm, int bn)
{
    int tid = threadIdx.x, wid = tid >> 5, lane = tid & 31;
    int wr = wid & 1, wc = wid >> 1, g = lane >> 2, t = lane & 3;
    int rsel = (lane & 7) + ((lane >> 3) & 1)*8;
    int wsel = (lane >> 4)*4;

    float acc[4][4][4];
    #pragma unroll
    for (int i = 0; i < 4; i++)
        #pragma unroll
        for (int j = 0; j < 4; j++)
            #pragma unroll
            for (int r = 0; r < 4; r++) acc[i][j][r] = 0.f;

    auto load_stage = [&](int buf, int k0) {
        #pragma unroll
        for (int i = 0; i < 2; i++) {
            int id = i*256 + tid;
            int row = id >> 2, c = id & 3;
            int m = bm + row;
            cp16(&Ah[buf][row][c*4], Axh + (long)m*lda + k0 + c*8, m < M ? 16 : 0);
            cp16(&Al[buf][row][c*4], Axl + (long)m*lda + k0 + c*8, m < M ? 16 : 0);
        }
        #pragma unroll
        for (int i = 0; i < 2; i++) {
            int id = i*256 + tid;
            int row = id >> 5, c = id & 31;
            long off = ((long)((k0>>1) + row)*N + bn + c*4)*2;
            cp16(&Bh[buf][row][c*4], Bwh + off, 16);
            cp16(&Bl[buf][row][c*4], Bwl + off, 16);
        }
        asm volatile("cp.async.commit_group;");
    };

    int KT = K >> 5;
    load_stage(0, 0);
    for (int kt = 0; kt < KT; kt++) {
        asm volatile("cp.async.wait_group 0;");
        __syncthreads();
        if (kt + 1 < KT) load_stage((kt+1)&1, (kt+1)*32);
        int buf = kt & 1;

        #pragma unroll
        for (int ka = 0; ka < 2; ka++) {
            int kw = ka*8;
            uint32_t bh[4][2], bl[4][2];
            #pragma unroll
            for (int na = 0; na < 4; na++) {
                int c = wc*32 + na*8 + g;
                bh[na][0] = Bh[buf][kw + t][c];  bh[na][1] = Bh[buf][kw + t + 4][c];
                bl[na][0] = Bl[buf][kw + t][c];  bl[na][1] = Bl[buf][kw + t + 4][c];
            }
            #pragma unroll
            for (int ma = 0; ma < 4; ma++) {
                uint32_t ah[4], al[4];
                ldsm_x4(ah, &Ah[buf][wr*64 + ma*16 + rsel][kw + wsel]);
                ldsm_x4(al, &Al[buf][wr*64 + ma*16 + rsel][kw + wsel]);
                #pragma unroll
                for (int na = 0; na < 4; na++) {
                    mma_f16(acc[ma][na], ah, bh[na]);
                    mma_f16(acc[ma][na], ah, bl[na]);
                    mma_f16(acc[ma][na], al, bh[na]);
                }
            }
        }
    }

    #pragma unroll
    for (int ma = 0; ma < 4; ma++) {
        int row0 = bm + wr*64 + ma*16 + g;
        #pragma unroll
        for (int na = 0; na < 4; na++) {
            int col = bn + wc*32 + na*8 + 2*t;
            float b0 = bias[col], b1 = bias[col+1];
            #pragma unroll
            for (int hh = 0; hh < 2; hh++) {
                int row = row0 + hh*8;
                if (row >= M) continue;
                *reinterpret_cast<float2*>(C + (long)row*ldc + col) =
                    make_float2(acc[ma][na][hh*2+0] + b0, acc[ma][na][hh*2+1] + b1);
            }
        }
    }
}

// ---------------- double-fp16 (3-MMA) TN body, TBK=32, ldmatrix A+B --------
__device__ __forceinline__ void hmma3_tn_body(
    uint32_t (*Ah)[TBM][W20], uint32_t (*Al)[TBM][W20],
    uint32_t (*Bh)[TBM][W20], uint32_t (*Bl)[TBM][W20],
    const __half* __restrict__ Axh, const __half* __restrict__ Axl,
    const __half* __restrict__ Bxh, const __half* __restrict__ Bxl,
    float* __restrict__ C, int M, int N, int K,
    const float* __restrict__ posb, int bm, int bn)
{
    int tid = threadIdx.x, wid = tid >> 5, lane = tid & 31;
    int wr = wid & 1, wc = wid >> 1, g = lane >> 2, t = lane & 3;
    int rsel  = (lane & 7) + ((lane >> 3) & 1)*8;
    int wsel  = (lane >> 4)*4;
    int rsel2 = lane & 7;
    int wsel2 = ((lane >> 3) & 1)*4;

    float acc[4][4][4];
    #pragma unroll
    for (int i = 0; i < 4; i++)
        #pragma unroll
        for (int j = 0; j < 4; j++)
            #pragma unroll
            for (int r = 0; r < 4; r++) acc[i][j][r] = 0.f;

    auto load_stage = [&](int buf, int k0) {
        #pragma unroll
        for (int i = 0; i < 2; i++) {
            int id = i*256 + tid;
            int row = id >> 2, c = id & 3;
            int m = bm + row;
            cp16(&Ah[buf][row][c*4], Axh + (long)m*K + k0 + c*8, m < M ? 16 : 0);
            cp16(&Al[buf][row][c*4], Axl + (long)m*K + k0 + c*8, m < M ? 16 : 0);
        }
        #pragma unroll
        for (int i = 0; i < 2; i++) {
            int id = i*256 + tid;
            int row = id >> 2, c = id & 3;
            int n = bn + row;
            cp16(&Bh[buf][row][c*4], Bxh + (long)n*K + k0 + c*8, n < N ? 16 : 0);
            cp16(&Bl[buf][row][c*4], Bxl + (long)n*K + k0 + c*8, n < N ? 16 : 0);
        }
        asm volatile("cp.async.commit_group;");
    };

    int KT = K >> 5;
    load_stage(0, 0);
    for (int kt = 0; kt < KT; kt++) {
        asm volatile("cp.async.wait_group 0;");
        __syncthreads();
        if (kt + 1 < KT) load_stage((kt+1)&1, (kt+1)*32);
        int buf = kt & 1;

        #pragma unroll
        for (int ka = 0; ka < 2; ka++) {
            int kw = ka*8;
            uint32_t bh[4][2], bl[4][2];
            #pragma unroll
            for (int na = 0; na < 4; na++) {
                ldsm_x2(bh[na], &Bh[buf][wc*32 + na*8 + rsel2][kw + wsel2]);
                ldsm_x2(bl[na], &Bl[buf][wc*32 + na*8 + rsel2][kw + wsel2]);
            }
            #pragma unroll
            for (int ma = 0; ma < 4; ma++) {
                uint32_t ah[4], al[4];
                ldsm_x4(ah, &Ah[buf][wr*64 + ma*16 + rsel][kw + wsel]);
                ldsm_x4(al, &Al[buf][wr*64 + ma*16 + rsel][kw + wsel]);
                #pragma unroll
                for (int na = 0; na < 4; na++) {
                    mma_f16(acc[ma][na], ah, bh[na]);
                    mma_f16(acc[ma][na], ah, bl[na]);
                    mma_f16(acc[ma][na], al, bh[na]);
                }
            }
        }
    }

    #pragma unroll
    for (int ma = 0; ma < 4; ma++) {
        int row0 = bm + wr*64 + ma*16 + g;
        #pragma unroll
        for (int na = 0; na < 4; na++) {
            int col = bn + wc*32 + na*8 + 2*t;
            if (col >= N) continue;
            #pragma unroll
            for (int hh = 0; hh < 2; hh++) {
                int row = row0 + hh*8;
                if (row >= M) continue;
                float v0 = acc[ma][na][hh*2+0] + posb[(long)row*N + col];
                float v1 = acc[ma][na][hh*2+1] + posb[(long)row*N + col + 1];
                if (row == col)   v0 = -1e9f;
                if (row == col+1) v1 = -1e9f;
                *reinterpret_cast<float2*>(C + (long)row*N + col) =
                    make_float2(v0*TEMP_INV, v1*TEMP_INV);
            }
        }
    }
}

// ---------------- shared-memory aggregates (16B aligned) -------------------
union __align__(16) Smem1 {
    struct { uint32_t As[2][TBM][W36]; uint32_t Bs[2][32][W136]; } h;     // 71680 B
    struct { uint32_t Ah[2][TBM][W20]; uint32_t Al[2][TBM][W20];
             uint32_t Bh[2][16][W136]; uint32_t Bl[2][16][W136]; } h3;    // 75776 B
};
struct __align__(16) Smem2 {
    uint32_t Ah[2][TBM][W20]; uint32_t Al[2][TBM][W20];
    uint32_t Bh[2][TBM][W20]; uint32_t Bl[2][TBM][W20];
};

// ---------------- standalone fp16 GEMM (proj/mlp) ----------------
template<int EPI>
__global__ __launch_bounds__(256, 2) void hmma_nn_kernel(
    const __half* __restrict__ A, const __half* __restrict__ B2,
    void* __restrict__ C, int M, int N, int K, int lda,
    const float* __restrict__ bias, const float* __restrict__ resid)
{
    __shared__ Smem1 sm;
    hmma_body<EPI>(sm.h.As, sm.h.Bs, A, B2, C, M, N, K, lda, bias, resid,
                   blockIdx.y*TBM, blockIdx.x*TBN);
}

// ---------------- CLS attention body ----------------
__device__ void cls_attn_body(const float* __restrict__ qkv,
                              __half* __restrict__ attn, int blk)
{
    int b = blk / HH, h = blk % HH;
    const float* base = qkv + (long)b*SS*3*DD;
    int tid = threadIdx.x;
    __shared__ float qv[HDIM];
    __shared__ float sc[SS];
    __shared__ float red[256];
    __shared__ float m_s, z_s;
    if (tid < HDIM) qv[tid] = base[h*HDIM + tid];
    __syncthreads();

    float lmax = -INFINITY;
    for (int k = tid; k < SS; k += 256) {
        const float* kr = base + (long)k*3*DD + DD + h*HDIM;
        float dot = 0.f;
        #pragma unroll
        for (int d = 0; d < HDIM; d++) dot = fmaf(qv[d], kr[d], dot);
        float s = dot * SCALE_ATT;
        sc[k] = s;
        lmax = fmaxf(lmax, s);
    }
    red[tid] = lmax;
    __syncthreads();
    for (int o = 128; o > 0; o >>= 1) {
        if (tid < o) red[tid] = fmaxf(red[tid], red[tid+o]);
        __syncthreads();
    }
    if (tid == 0) m_s = red[0];
    __syncthreads();
    float m = m_s, lsum = 0.f;
    for (int k = tid; k < SS; k += 256) {
        float e = expf(sc[k]-m); sc[k] = e; lsum += e;
    }
    red[tid] = lsum;
    __syncthreads();
    for (int o = 128; o > 0; o >>= 1) {
        if (tid < o) red[tid] += red[tid+o];
        __syncthreads();
    }
    if (tid == 0) z_s = red[0];
    __syncthreads();
    float zinv = 1.0f / z_s;

    int d = tid & 63, part = tid >> 6;
    float acc = 0.f;
    for (int k = part; k < SS; k += 4)
        acc = fmaf(sc[k], base[(long)k*3*DD + 2*DD + h*HDIM + d], acc);
    __shared__ float ro[4][HDIM];
    ro[part][d] = acc;
    __syncthreads();
    if (tid < HDIM)
        attn[((long)b*SS)*DD + h*HDIM + tid] =
            __float2half((ro[0][tid]+ro[1][tid]+ro[2][tid]+ro[3][tid]) * zinv);
}

// ---------------- fused: routing scores (hmma3 TN) + CLS attention ---------
#define SC_NX ((PP+127)/128)                  // 5
#define SC_MY ((PP+127)/128)                  // 5
#define SC_BLKS (SC_NX*SC_MY*BB)              // 200

__global__ __launch_bounds__(256, 2) void fused_scores_cls_kernel(
    const __half* __restrict__ qh, const __half* __restrict__ ql,
    const __half* __restrict__ kh, const __half* __restrict__ kl,
    float* __restrict__ scores, const float* __restrict__ posb,
    const float* __restrict__ qkv, __half* __restrict__ attn)
{
    int bx = blockIdx.x;
    if (bx < SC_BLKS) {
        __shared__ Smem2 sm;
        int nx = bx % SC_NX;
        int my = (bx / SC_NX) % SC_MY;
        int bz = bx / (SC_NX*SC_MY);
        hmma3_tn_body(sm.Ah, sm.Al, sm.Bh, sm.Bl,
                      qh + (long)bz*PP*DD, ql + (long)bz*PP*DD,
                      kh + (long)bz*PP*DD, kl + (long)bz*PP*DD,
                      scores + (long)bz*PP*PP, PP, PP, DD,
                      posb, my*128, nx*128);
    } else {
        cls_attn_body(qkv, attn, bx - SC_BLKS);
    }
}

// ---------------- fused: QKV (hmma) + q||k routing proj (hmma3 NN) ---------
#define QKV_NX  (3*DD/TBN)                    // 18
#define QKV_MY  ((NROWS+TBM-1)/TBM)           // 37
#define QKV_BLKS (QKV_NX*QKV_MY)              // 666
#define QK2_NX  (2*DD/TBN)                    // 12
#define QK2_MY  ((PP+TBM-1)/TBM)              // 5
#define QK2_BLKS (QK2_NX*QK2_MY*BB)           // 480

__global__ __launch_bounds__(256, 2) void fused_qkv_qkproj_kernel(
    const __half* __restrict__ xnh, const __half* __restrict__ xnl,
    const __half* __restrict__ rqkv, const float* __restrict__ b_qkv,
    float* __restrict__ qkvb,
    const __half* __restrict__ wqkh, const __half* __restrict__ wqkl,
    const float* __restrict__ bqk, float* __restrict__ qk)
{
    __shared__ Smem1 sm;
    int bx = blockIdx.x;
    if (bx < QKV_BLKS) {
        int bn = (bx % QKV_NX)*TBN, bm = (bx / QKV_NX)*TBM;
        hmma_body<0>(sm.h.As, sm.h.Bs, xnh, rqkv, qkvb,
                     NROWS, 3*DD, DD, DD, b_qkv, nullptr, bm, bn);
    } else {
        int rel = bx - QKV_BLKS;
        int nx = rel % QK2_NX;
        int my = (rel / QK2_NX) % QK2_MY;
        int bz = rel / (QK2_NX*QK2_MY);
        hmma3_nn_body(sm.h3.Ah, sm.h3.Al, sm.h3.Bh, sm.h3.Bl,
                      xnh + (long)bz*SS*DD + DD,
                      xnl + (long)bz*SS*DD + DD,
                      wqkh, wqkl,
                      qk + (long)bz*PP*2*DD, PP, 2*DD, DD, DD, 2*DD,
                      bqk, my*128, nx*128);
    }
}

// ---------------- warp-per-row top-32 + log-softmax weights ----------------
__global__ __launch_bounds__(256) void topk_warp_kernel(
    const float* __restrict__ scores, int* __restrict__ routes,
    float* __restrict__ logw)
{
    int warp = blockIdx.x*8 + (threadIdx.x >> 5);
    int lane = threadIdx.x & 31;
    const float* srw = scores + (long)warp*PP;
    float v[18];
    #pragma unroll
    for (int j = 0; j < 18; j++) v[j] = srw[j*32 + lane];

    float myTop = 0.f;
    for (int tt = 0; tt < KWIN; tt++) {
        float bv = -INFINITY; int bj = 0;
        #pragma unroll
        for (int j = 0; j < 18; j++)
            if (v[j] > bv) { bv = v[j]; bj = j; }
        int bi = bj*32 + lane;
        #pragma unroll
        for (int o = 16; o > 0; o >>= 1) {
            float ov = __shfl_xor_sync(0xffffffffu, bv, o);
            int   oi = __shfl_xor_sync(0xffffffffu, bi, o);
            if (ov > bv || (ov == bv && oi < bi)) { bv = ov; bi = oi; }
        }
        if (lane == (bi & 31)) v[bi >> 5] = -INFINITY;
        if (lane == tt) myTop = bv;
        if (lane == 0)  routes[(long)warp*KWIN + tt] = bi;
    }
    float m = __shfl_sync(0xffffffffu, myTop, 0);
    float e = expf(myTop - m);
    float z = e;
    #pragma unroll
    for (int o = 16; o > 0; o >>= 1) z += __shfl_xor_sync(0xffffffffu, z, o);
    float lse = m + logf(z);
    logw[(long)warp*KWIN + lane] = fmaxf(myTop - lse, -10.0f);
}

// ---------------- Patch attention (gathered 32-key windows) ----------------
__global__ __launch_bounds__(64) void patch_attn_kernel(
    const float* __restrict__ qkv, const int* __restrict__ routes,
    const float* __restrict__ logw, __half* __restrict__ attn)
{
    int id = blockIdx.x;
    int p = id % PP;
    int h = (id / PP) % HH;
    int b = id / (PP*HH);
    const float* base = qkv + (long)b*SS*3*DD;
    int tid = threadIdx.x;

    __shared__ float qs[HDIM];
    __shared__ int   sr[KWIN];
    __shared__ float sa[KWIN];
    __shared__ float part[2][KWIN];

    qs[tid] = base[(long)(p+1)*3*DD + h*HDIM + tid];
    if (tid < KWIN) sr[tid] = routes[((long)b*PP + p)*KWIN + tid];
    __syncthreads();

    int k = tid & 31, half_ = tid >> 5;
    const float* kr = base + (long)(sr[k]+1)*3*DD + DD + h*HDIM + half_*32;
    float dot = 0.f;
    #pragma unroll
    for (int d = 0; d < 32; d++) dot = fmaf(qs[half_*32+d], kr[d], dot);
    part[half_][k] = dot;
    __syncthreads();

    if (tid < KWIN) {
        float s = (part[0][k]+part[1][k]) * SCALE_ATT
                + logw[((long)b*PP + p)*KWIN + k];
        float m = s;
        #pragma unroll
        for (int o = 16; o > 0; o >>= 1) m = fmaxf(m, __shfl_xor_sync(0xffffffffu, m, o));
        float e = expf(s-m);
        float z = e;
        #pragma unroll
        for (int o = 16; o > 0; o >>= 1) z += __shfl_xor_sync(0xffffffffu, z, o);
        sa[k] = e / z;
    }
    __syncthreads();

    float acc = 0.f;
    #pragma unroll 8
    for (int kk = 0; kk < KWIN; kk++)
        acc = fmaf(sa[kk], base[(long)(sr[kk]+1)*3*DD + 2*DD + h*HDIM + tid], acc);
    attn[((long)b*SS + p+1)*DD + h*HDIM + tid] = __float2half(acc);
}

// ---------------- launcher ----------------
extern "C" void kernel_launch(void* const* d_in, const int* in_sizes, int n_in,
                              void* d_out, int out_size)
{
    const float* x      = (const float*)d_in[0];
    const float* g1     = (const float*)d_in[1];
    const float* b1     = (const float*)d_in[2];
    const float* wq     = (const float*)d_in[3];
    const float* bq     = (const float*)d_in[4];
    const float* wk     = (const float*)d_in[5];
    const float* bk     = (const float*)d_in[6];
    const float* posb   = (const float*)d_in[7];
    const float* w_qkv  = (const float*)d_in[8];
    const float* b_qkv  = (const float*)d_in[9];
    const float* w_proj = (const float*)d_in[10];
    const float* b_proj = (const float*)d_in[11];
    const float* g2     = (const float*)d_in[12];
    const float* b2     = (const float*)d_in[13];
    const float* w_mlp1 = (const float*)d_in[14];
    const float* b_mlp1 = (const float*)d_in[15];
    const float* w_mlp2 = (const float*)d_in[16];
    const float* b_mlp2 = (const float*)d_in[17];
    float* out = (float*)d_out;

    float *qk, *scores, *logw, *qkvb, *x1, *bqk;
    __half *xnh, *xnl, *qh, *ql, *kh, *kl, *attn, *xn2, *hbuf;
    __half *rqkv, *rproj, *rm1, *rm2, *wqkh, *wqkl;
    int *routes;
    cudaGetSymbolAddress((void**)&xnh,    g_xnh);
    cudaGetSymbolAddress((void**)&xnl,    g_xnl);
    cudaGetSymbolAddress((void**)&qk,     g_qk);
    cudaGetSymbolAddress((void**)&qh,     g_qh);
    cudaGetSymbolAddress((void**)&ql,     g_ql);
    cudaGetSymbolAddress((void**)&kh,     g_kh);
    cudaGetSymbolAddress((void**)&kl,     g_kl);
    cudaGetSymbolAddress((void**)&scores, g_scores);
    cudaGetSymbolAddress((void**)&routes, g_routes);
    cudaGetSymbolAddress((void**)&logw,   g_logw);
    cudaGetSymbolAddress((void**)&qkvb,   g_qkv);
    cudaGetSymbolAddress((void**)&attn,   g_attn);
    cudaGetSymbolAddress((void**)&x1,     g_x1);
    cudaGetSymbolAddress((void**)&xn2,    g_xn2);
    cudaGetSymbolAddress((void**)&hbuf,   g_h);
    cudaGetSymbolAddress((void**)&rqkv,   g_rqkv);
    cudaGetSymbolAddress((void**)&rproj,  g_rproj);
    cudaGetSymbolAddress((void**)&rm1,    g_rm1);
    cudaGetSymbolAddress((void**)&rm2,    g_rm2);
    cudaGetSymbolAddress((void**)&wqkh,   g_wqkh);
    cudaGetSymbolAddress((void**)&wqkl,   g_wqkl);
    cudaGetSymbolAddress((void**)&bqk,    g_bqk);

    // 0. weight prep
    pack_all_kernel<<<PK_BLKS, 256>>>(w_qkv, rqkv, w_proj, rproj,
                                      w_mlp1, rm1, w_mlp2, rm2);
    pack_qk_kernel<<<PKQK_W_B + 1, 256>>>(wq, wk, bq, bk, wqkh, wqkl, bqk);

    // 1. LN1 -> hi + lo fp16
    ln_kernel<<<NROWS, 256>>>(x, g1, b1, xnh, xnl);

    // 2. FUSED: QKV (fp16 HMMA, TBK=64) + q||k routing projection (3-MMA)
    fused_qkv_qkproj_kernel<<<QKV_BLKS + QK2_BLKS, 256>>>(
        xnh, xnl, rqkv, b_qkv, qkvb, wqkh, wqkl, bqk, qk);

    // 3. l2 normalize + split q,k into hi/lo fp16
    l2norm_split_kernel<<<2*BB*PP, 256>>>(qk, qh, ql, kh, kl);

    // 4. FUSED: routing scores (double-fp16 TN) + CLS attention
    fused_scores_cls_kernel<<<SC_BLKS + BB*HH, 256>>>(
        qh, ql, kh, kl, scores, posb, qkvb, attn);

    // 5. top-32 + log-softmax weights (warp per row)
    topk_warp_kernel<<<BB*PP/8, 256>>>(scores, routes, logw);

    // 6. patch attention
    patch_attn_kernel<<<BB*HH*PP, 64>>>(qkvb, routes, logw, attn);

    // 7. proj + residual x (fp16 HMMA TBK=64, fp32 out)
    {
        dim3 grid(DD/TBN, (NROWS+TBM-1)/TBM);
        hmma_nn_kernel<2><<<grid, 256>>>(attn, rproj, x1, NROWS, DD, DD, DD,
                                         b_proj, x);
    }
    // 8. LN2 (fp16 hi only, feeds MLP1)
    ln_kernel<<<NROWS, 256>>>(x1, g2, b2, xn2, nullptr);

    // 9. MLP1 + exact GELU (fp16 HMMA TBK=64, fp16 out)
    {
        dim3 grid(MLPD/TBN, (NROWS+TBM-1)/TBM);
        hmma_nn_kernel<3><<<grid, 256>>>(xn2, rm1, hbuf, NROWS, MLPD, DD, DD,
                                         b_mlp1, nullptr);
    }
    // 10. MLP2 + residual x1 -> out (fp16 HMMA TBK=64, fp32 out)
    {
        dim3 grid(DD/TBN, (NROWS+TBM-1)/TBM);
        hmma_nn_kernel<2><<<grid, 256>>>(hbuf, rm2, out, NROWS, DD, MLPD, MLPD,
                                         b_mlp2, x1);
    }
}

// round 15
// speedup vs baseline: 1.0624x; 1.0132x over previous
#include <cuda_runtime.h>
#include <cuda_fp16.h>
#include <math.h>
#include <stdint.h>

// ---------------- problem constants ----------------
#define BB   8
#define SS   577
#define DD   768
#define HH   12
#define HDIM 64
#define PP   576
#define KWIN 32
#define MLPD 3072
#define NROWS (BB*SS)        // 4616
#define SCALE_ATT 0.125f
#define TEMP_INV  10.0f

#define TBM 128
#define TBN 128
#define TBK 32
#define W20  20
#define W136 136

__device__ __forceinline__ void cp16(void* dst_smem, const void* src, int srcsize) {
    uint32_t d = (uint32_t)__cvta_generic_to_shared(dst_smem);
    asm volatile("cp.async.cg.shared.global [%0], [%1], 16, %2;"
                 :: "r"(d), "l"(src), "r"(srcsize));
}
__device__ __forceinline__ void mma_f16(float* d, const uint32_t* a, const uint32_t* b) {
    asm volatile(
        "mma.sync.aligned.m16n8k16.row.col.f32.f16.f16.f32 "
        "{%0,%1,%2,%3}, {%4,%5,%6,%7}, {%8,%9}, {%0,%1,%2,%3};"
        : "+f"(d[0]), "+f"(d[1]), "+f"(d[2]), "+f"(d[3])
        : "r"(a[0]), "r"(a[1]), "r"(a[2]), "r"(a[3]), "r"(b[0]), "r"(b[1]));
}
__device__ __forceinline__ void ldsm_x4(uint32_t* r, const void* smem_ptr) {
    uint32_t a = (uint32_t)__cvta_generic_to_shared(smem_ptr);
    asm volatile("ldmatrix.sync.aligned.m8n8.x4.shared.b16 {%0,%1,%2,%3}, [%4];"
                 : "=r"(r[0]), "=r"(r[1]), "=r"(r[2]), "=r"(r[3]) : "r"(a));
}
__device__ __forceinline__ void ldsm_x2(uint32_t* r, const void* smem_ptr) {
    uint32_t a = (uint32_t)__cvta_generic_to_shared(smem_ptr);
    asm volatile("ldmatrix.sync.aligned.m8n8.x2.shared.b16 {%0,%1}, [%2];"
                 : "=r"(r[0]), "=r"(r[1]) : "r"(a));
}
__device__ __forceinline__ void split1(float v, __half& h, __half& l) {
    h = __float2half(v);
    l = __float2half(v - __half2float(h));
}

// ---------------- scratch (device globals) ----------------
__device__ __half g_xnh  [(size_t)BB*SS*DD];
__device__ __half g_xnl  [(size_t)BB*SS*DD];
__device__ float  g_qk   [(size_t)BB*PP*2*DD];
__device__ __half g_qh   [(size_t)BB*PP*DD];
__device__ __half g_ql   [(size_t)BB*PP*DD];
__device__ __half g_kh   [(size_t)BB*PP*DD];
__device__ __half g_kl   [(size_t)BB*PP*DD];
__device__ float  g_scores[(size_t)BB*PP*PP];
__device__ int    g_routes[(size_t)BB*PP*KWIN];
__device__ float  g_logw  [(size_t)BB*PP*KWIN];
__device__ float  g_qkv  [(size_t)BB*SS*3*DD];
__device__ __half g_attn [(size_t)BB*SS*DD];
__device__ float  g_x1   [(size_t)BB*SS*DD];
__device__ __half g_xn2  [(size_t)BB*SS*DD];
__device__ __half g_h    [(size_t)BB*SS*MLPD];
__device__ __half g_rqkv [(size_t)DD*3*DD];
__device__ __half g_rproj[(size_t)DD*DD];
__device__ __half g_rm1  [(size_t)DD*MLPD];
__device__ __half g_rm2  [(size_t)MLPD*DD];
__device__ __half g_wqkh [(size_t)DD*2*DD];
__device__ __half g_wqkl [(size_t)DD*2*DD];
__device__ float  g_bqk  [(size_t)2*DD];

// ---------------- pack big-gemm weights ------------
#define PK_QKV_B  (DD*3*DD/2048)
#define PK_PROJ_B (DD*DD/2048)
#define PK_M1_B   (DD*MLPD/2048)
#define PK_M2_B   (MLPD*DD/2048)
#define PK_BLKS   (PK_QKV_B+PK_PROJ_B+PK_M1_B+PK_M2_B)

__global__ __launch_bounds__(256) void pack_all_kernel(
    const float* __restrict__ wqkv, __half* __restrict__ rqkv,
    const float* __restrict__ wproj, __half* __restrict__ rproj,
    const float* __restrict__ wm1, __half* __restrict__ rm1,
    const float* __restrict__ wm2, __half* __restrict__ rm2)
{
    int bx = blockIdx.x;
    const float* src; __half* dst; int N; long base;
    if (bx < PK_QKV_B)                       { src = wqkv;  dst = rqkv;  N = 3*DD; base = bx; }
    else if (bx < PK_QKV_B+PK_PROJ_B)        { src = wproj; dst = rproj; N = DD;   base = bx-PK_QKV_B; }
    else if (bx < PK_QKV_B+PK_PROJ_B+PK_M1_B){ src = wm1;   dst = rm1;   N = MLPD; base = bx-PK_QKV_B-PK_PROJ_B; }
    else                                     { src = wm2;   dst = rm2;   N = DD;   base = bx-PK_QKV_B-PK_PROJ_B-PK_M1_B; }
    long id = base*256 + threadIdx.x;
    int npg = N/4;
    long k2 = id / npg;
    int  n  = (int)(id % npg) * 4;
    float4 e = *reinterpret_cast<const float4*>(src + (2*k2  )*N + n);
    float4 o = *reinterpret_cast<const float4*>(src + (2*k2+1)*N + n);
    __half2 out[4];
    out[0] = __floats2half2_rn(e.x, o.x);
    out[1] = __floats2half2_rn(e.y, o.y);
    out[2] = __floats2half2_rn(e.z, o.z);
    out[3] = __floats2half2_rn(e.w, o.w);
    *reinterpret_cast<uint4*>(dst + (k2*N + n)*2) = *reinterpret_cast<uint4*>(out);
}

// ---------------- pack routing weights ----------------
#define PKQK_W_B ((DD/2)*(2*DD)/1024)   // 576
__global__ __launch_bounds__(256) void pack_qk_kernel(
    const float* __restrict__ wq, const float* __restrict__ wk,
    const float* __restrict__ bq, const float* __restrict__ bk,
    __half* __restrict__ wh, __half* __restrict__ wl, float* __restrict__ bqk)
{
    int bx = blockIdx.x;
    if (bx == PKQK_W_B) {
        for (int i = threadIdx.x; i < 2*DD; i += 256)
            bqk[i] = (i < DD) ? bq[i] : bk[i - DD];
        return;
    }
    const int N2 = 2*DD;
    long id = (long)bx*256 + threadIdx.x;
    long k2 = id / (N2/4);
    int  n  = (int)(id % (N2/4)) * 4;
    const float* src = (n < DD) ? wq : wk;
    int nn = (n < DD) ? n : n - DD;
    float4 e = *reinterpret_cast<const float4*>(src + (2*k2  )*DD + nn);
    float4 o = *reinterpret_cast<const float4*>(src + (2*k2+1)*DD + nn);
    __half2 oh[4], ol[4];
    #pragma unroll
    for (int u = 0; u < 4; u++) {
        float ev = (&e.x)[u], ov = (&o.x)[u];
        __half eh, el, ohh, oll;
        split1(ev, eh, el); split1(ov, ohh, oll);
        oh[u] = __halves2half2(eh, ohh);
        ol[u] = __halves2half2(el, oll);
    }
    *reinterpret_cast<uint4*>(wh + (k2*N2 + n)*2) = *reinterpret_cast<uint4*>(oh);
    *reinterpret_cast<uint4*>(wl + (k2*N2 + n)*2) = *reinterpret_cast<uint4*>(ol);
}

// ---------------- LayerNorm: fp16 hi out + optional fp16 lo out ------------
__global__ __launch_bounds__(256) void ln_kernel(
    const float* __restrict__ x, const float* __restrict__ g,
    const float* __restrict__ b, __half* __restrict__ yh,
    __half* __restrict__ yl)
{
    int row = blockIdx.x;
    const float* xr = x + (long)row*DD;
    float s = 0.f, sq = 0.f;
    for (int d = threadIdx.x; d < DD; d += 256) {
        float v = xr[d]; s += v; sq += v*v;
    }
    __shared__ float rs[256], rq[256];
    rs[threadIdx.x] = s; rq[threadIdx.x] = sq;
    __syncthreads();
    for (int o = 128; o > 0; o >>= 1) {
        if (threadIdx.x < o) { rs[threadIdx.x] += rs[threadIdx.x+o]; rq[threadIdx.x] += rq[threadIdx.x+o]; }
        __syncthreads();
    }
    __shared__ float mean_s, rstd_s;
    if (threadIdx.x == 0) {
        float mean = rs[0] / (float)DD;
        float var  = rq[0] / (float)DD - mean*mean;
        mean_s = mean;
        rstd_s = rsqrtf(var + 1e-5f);
    }
    __syncthreads();
    float mean = mean_s, rstd = rstd_s;
    __half* yhb = yh + (long)row*DD;
    __half* ylb = yl ? (yl + (long)row*DD) : nullptr;
    for (int d = threadIdx.x; d < DD; d += 256) {
        float v = (xr[d]-mean)*rstd*g[d] + b[d];
        __half h = __float2half(v);
        yhb[d] = h;
        if (ylb) ylb[d] = __float2half(v - __half2float(h));
    }
}

// ---------------- L2 normalize q||k rows + split into hi/lo fp16 -----------
__global__ __launch_bounds__(256) void l2norm_split_kernel(
    const float* __restrict__ qk,
    __half* __restrict__ qh, __half* __restrict__ ql,
    __half* __restrict__ kh, __half* __restrict__ kl)
{
    int row = blockIdx.x;
    int isK = row >= BB*PP;
    int r   = isK ? row - BB*PP : row;
    const float* xr = qk + (long)r*(2*DD) + (isK ? DD : 0);
    float sq = 0.f;
    for (int d = threadIdx.x; d < DD; d += 256) { float v = xr[d]; sq += v*v; }
    __shared__ float rq[256];
    rq[threadIdx.x] = sq;
    __syncthreads();
    for (int o = 128; o > 0; o >>= 1) {
        if (threadIdx.x < o) rq[threadIdx.x] += rq[threadIdx.x+o];
        __syncthreads();
    }
    __shared__ float inv_s;
    if (threadIdx.x == 0) inv_s = 1.0f / fmaxf(sqrtf(rq[0]), 1e-12f);
    __syncthreads();
    float inv = inv_s;
    __half* oh = (isK ? kh : qh) + (long)r*DD;
    __half* ol = (isK ? kl : ql) + (long)r*DD;
    for (int d = threadIdx.x; d < DD; d += 256) {
        float v = xr[d]*inv;
        __half h = __float2half(v);
        oh[d] = h;
        ol[d] = __float2half(v - __half2float(h));
    }
}

// ---------------- fp16 HMMA body: TBK=32, 3-stage, ldmatrix A --------------
// EPI: 0 = +bias (fp32 C) ; 2 = +bias+resid (fp32 C) ; 3 = +bias+GELU (fp16 C)
template<int EPI>
__device__ __forceinline__ void hmma_body(
    uint32_t (*As)[TBM][W20], uint32_t (*Bs)[16][W136],
    const __half* __restrict__ A, const __half* __restrict__ B2,
    void* __restrict__ Cv, int M, int N, int K, int lda,
    const float* __restrict__ bias, const float* __restrict__ resid,
    int bm, int bn)
{
    int tid  = threadIdx.x;
    int wid  = tid >> 5, lane = tid & 31;
    int wr   = wid & 1;
    int wc   = wid >> 1;
    int g    = lane >> 2;
    int t    = lane & 3;
    int rsel = (lane & 7) + ((lane >> 3) & 1)*8;
    int wsel = (lane >> 4)*4;

    float acc[4][4][4];
    #pragma unroll
    for (int i = 0; i < 4; i++)
        #pragma unroll
        for (int j = 0; j < 4; j++)
            #pragma unroll
            for (int r = 0; r < 4; r++) acc[i][j][r] = 0.f;

    auto load_stage = [&](int buf, int k0) {
        #pragma unroll
        for (int i = 0; i < 2; i++) {
            int id = i*256 + tid;
            int row = id >> 2, c = id & 3;
            int m = bm + row;
            cp16(&As[buf][row][c*4], A + (long)m*lda + k0 + c*8, m < M ? 16 : 0);
        }
        #pragma unroll
        for (int i = 0; i < 2; i++) {
            int id = i*256 + tid;
            int row = id >> 5, c = id & 31;
            cp16(&Bs[buf][row][c*4],
                 B2 + ((long)((k0>>1) + row)*N + bn + c*4)*2, 16);
        }
        asm volatile("cp.async.commit_group;");
    };

    int KT = K >> 5;
    load_stage(0, 0);
    load_stage(1, TBK);
    for (int kt = 0; kt < KT; kt++) {
        if (kt + 2 < KT) asm volatile("cp.async.wait_group 1;");
        else             asm volatile("cp.async.wait_group 0;");
        __syncthreads();
        if (kt + 2 < KT) load_stage((kt+2)%3, (kt+2)*TBK);
        int buf = kt % 3;

        #pragma unroll
        for (int ka = 0; ka < 2; ka++) {
            int kw = ka*8;
            uint32_t afrag[4][4];
            #pragma unroll
            for (int ma = 0; ma < 4; ma++)
                ldsm_x4(afrag[ma], &As[buf][wr*64 + ma*16 + rsel][kw + wsel]);
            uint32_t bfrag[4][2];
            #pragma unroll
            for (int na = 0; na < 4; na++) {
                int c = wc*32 + na*8 + g;
                bfrag[na][0] = Bs[buf][kw + t    ][c];
                bfrag[na][1] = Bs[buf][kw + t + 4][c];
            }
            #pragma unroll
            for (int ma = 0; ma < 4; ma++)
                #pragma unroll
                for (int na = 0; na < 4; na++)
                    mma_f16(acc[ma][na], afrag[ma], bfrag[na]);
        }
    }

    #pragma unroll
    for (int ma = 0; ma < 4; ma++) {
        int row0 = bm + wr*64 + ma*16 + g;
        #pragma unroll
        for (int na = 0; na < 4; na++) {
            int col = bn + wc*32 + na*8 + 2*t;
            float b0 = bias[col], b1 = bias[col+1];
            #pragma unroll
            for (int hh = 0; hh < 2; hh++) {
                int row = row0 + hh*8;
                if (row >= M) continue;
                float v0 = acc[ma][na][hh*2+0] + b0;
                float v1 = acc[ma][na][hh*2+1] + b1;
                if (EPI == 3) {
                    v0 = 0.5f*v0*(1.0f + erff(v0*0.7071067811865475f));
                    v1 = 0.5f*v1*(1.0f + erff(v1*0.7071067811865475f));
                    *reinterpret_cast<__half2*>((__half*)Cv + (long)row*N + col) =
                        __floats2half2_rn(v0, v1);
                } else {
                    if (EPI == 2) {
                        v0 += resid[(long)row*N + col];
                        v1 += resid[(long)row*N + col + 1];
                    }
                    *reinterpret_cast<float2*>((float*)Cv + (long)row*N + col) =
                        make_float2(v0, v1);
                }
            }
        }
    }
}

// ---------------- double-fp16 (3-MMA) NN body, ldmatrix A ------------------
__device__ __forceinline__ void hmma3_nn_body(
    uint32_t (*Ah)[TBM][W20], uint32_t (*Al)[TBM][W20],
    uint32_t (*Bh)[16][W136], uint32_t (*Bl)[16][W136],
    const __half* __restrict__ Axh, const __half* __restrict__ Axl,
    const __half* __restrict__ Bwh, const __half* __restrict__ Bwl,
    float* __restrict__ C, int M, int N, int K, int lda, int ldc,
    const float* __restrict__ bias, int bm, int bn)
{
    int tid = threadIdx.x, wid = tid >> 5, lane = tid & 31;
    int wr = wid & 1, wc = wid >> 1, g = lane >> 2, t = lane & 3;
    int rsel = (lane & 7) + ((lane >> 3) & 1)*8;
    int wsel = (lane >> 4)*4;

    float acc[4][4][4];
    #pragma unroll
    for (int i = 0; i < 4; i++)
        #pragma unroll
        for (int j = 0; j < 4; j++)
            #pragma unroll
            for (int r = 0; r < 4; r++) acc[i][j][r] = 0.f;

    auto load_stage = [&](int buf, int k0) {
        #pragma unroll
        for (int i = 0; i < 2; i++) {
            int id = i*256 + tid;
            int row = id >> 2, c = id & 3;
            int m = bm + row;
            cp16(&Ah[buf][row][c*4], Axh + (long)m*lda + k0 + c*8, m < M ? 16 : 0);
            cp16(&Al[buf][row][c*4], Axl + (long)m*lda + k0 + c*8, m < M ? 16 : 0);
        }
        #pragma unroll
        for (int i = 0; i < 2; i++) {
            int id = i*256 + tid;
            int row = id >> 5, c = id & 31;
            long off = ((long)((k0>>1) + row)*N + bn + c*4)*2;
            cp16(&Bh[buf][row][c*4], Bwh + off, 16);
            cp16(&Bl[buf][row][c*4], Bwl + off, 16);
        }
        asm volatile("cp.async.commit_group;");
    };

    int KT = K >> 5;
    load_stage(0, 0);
    for (int kt = 0; kt < KT; kt++) {
        asm volatile("cp.async.wait_group 0;");
        __syncthreads();
        if (kt + 1 < KT) load_stage((kt+1)&1, (kt+1)*TBK);
        int buf = kt & 1;

        #pragma unroll
        for (int ka = 0; ka < 2; ka++) {
            int kw = ka*8;
            uint32_t bh[4][2], bl[4][2];
            #pragma unroll
            for (int na = 0; na < 4; na++) {
                int c = wc*32 + na*8 + g;
                bh[na][0] = Bh[buf][kw + t][c];  bh[na][1] = Bh[buf][kw + t + 4][c];
                bl[na][0] = Bl[buf][kw + t][c];  bl[na][1] = Bl[buf][kw + t + 4][c];
            }
            #pragma unroll
            for (int ma = 0; ma < 4; ma++) {
                uint32_t ah[4], al[4];
                ldsm_x4(ah, &Ah[buf][wr*64 + ma*16 + rsel][kw + wsel]);
                ldsm_x4(al, &Al[buf][wr*64 + ma*16 + rsel][kw + wsel]);
                #pragma unroll
                for (int na = 0; na < 4; na++) {
                    mma_f16(acc[ma][na], ah, bh[na]);
                    mma_f16(acc[ma][na], ah, bl[na]);
                    mma_f16(acc[ma][na], al, bh[na]);
                }
            }
        }
    }

    #pragma unroll
    for (int ma = 0; ma < 4; ma++) {
        int row0 = bm + wr*64 + ma*16 + g;
        #pragma unroll
        for (int na = 0; na < 4; na++) {
            int col = bn + wc*32 + na*8 + 2*t;
            float b0 = bias[col], b1 = bias[col+1];
            #pragma unroll
            for (int hh = 0; hh < 2; hh++) {
                int row = row0 + hh*8;
                if (row >= M) continue;
                *reinterpret_cast<float2*>(C + (long)row*ldc + col) =
                    make_float2(acc[ma][na][hh*2+0] + b0, acc[ma][na][hh*2+1] + b1);
            }
        }
    }
}

// ---------------- double-fp16 (3-MMA) TN body, ldmatrix A+B ----------------
__device__ __forceinline__ void hmma3_tn_body(
    uint32_t (*Ah)[TBM][W20], uint32_t (*Al)[TBM][W20],
    uint32_t (*Bh)[TBM][W20], uint32_t (*Bl)[TBM][W20],
    const __half* __restrict__ Axh, const __half* __restrict__ Axl,
    const __half* __restrict__ Bxh, const __half* __restrict__ Bxl,
    float* __restrict__ C, int M, int N, int K,
    const float* __restrict__ posb, int bm, int bn)
{
    int tid = threadIdx.x, wid = tid >> 5, lane = tid & 31;
    int wr = wid & 1, wc = wid >> 1, g = lane >> 2, t = lane & 3;
    int rsel  = (lane & 7) + ((lane >> 3) & 1)*8;
    int wsel  = (lane >> 4)*4;
    int rsel2 = lane & 7;
    int wsel2 = ((lane >> 3) & 1)*4;

    float acc[4][4][4];
    #pragma unroll
    for (int i = 0; i < 4; i++)
        #pragma unroll
        for (int j = 0; j < 4; j++)
            #pragma unroll
            for (int r = 0; r < 4; r++) acc[i][j][r] = 0.f;

    auto load_stage = [&](int buf, int k0) {
        #pragma unroll
        for (int i = 0; i < 2; i++) {
            int id = i*256 + tid;
            int row = id >> 2, c = id & 3;
            int m = bm + row;
            cp16(&Ah[buf][row][c*4], Axh + (long)m*K + k0 + c*8, m < M ? 16 : 0);
            cp16(&Al[buf][row][c*4], Axl + (long)m*K + k0 + c*8, m < M ? 16 : 0);
        }
        #pragma unroll
        for (int i = 0; i < 2; i++) {
            int id = i*256 + tid;
            int row = id >> 2, c = id & 3;
            int n = bn + row;
            cp16(&Bh[buf][row][c*4], Bxh + (long)n*K + k0 + c*8, n < N ? 16 : 0);
            cp16(&Bl[buf][row][c*4], Bxl + (long)n*K + k0 + c*8, n < N ? 16 : 0);
        }
        asm volatile("cp.async.commit_group;");
    };

    int KT = K >> 5;
    load_stage(0, 0);
    for (int kt = 0; kt < KT; kt++) {
        asm volatile("cp.async.wait_group 0;");
        __syncthreads();
        if (kt + 1 < KT) load_stage((kt+1)&1, (kt+1)*TBK);
        int buf = kt & 1;

        #pragma unroll
        for (int ka = 0; ka < 2; ka++) {
            int kw = ka*8;
            uint32_t bh[4][2], bl[4][2];
            #pragma unroll
            for (int na = 0; na < 4; na++) {
                ldsm_x2(bh[na], &Bh[buf][wc*32 + na*8 + rsel2][kw + wsel2]);
                ldsm_x2(bl[na], &Bl[buf][wc*32 + na*8 + rsel2][kw + wsel2]);
            }
            #pragma unroll
            for (int ma = 0; ma < 4; ma++) {
                uint32_t ah[4], al[4];
                ldsm_x4(ah, &Ah[buf][wr*64 + ma*16 + rsel][kw + wsel]);
                ldsm_x4(al, &Al[buf][wr*64 + ma*16 + rsel][kw + wsel]);
                #pragma unroll
                for (int na = 0; na < 4; na++) {
                    mma_f16(acc[ma][na], ah, bh[na]);
                    mma_f16(acc[ma][na], ah, bl[na]);
                    mma_f16(acc[ma][na], al, bh[na]);
                }
            }
        }
    }

    #pragma unroll
    for (int ma = 0; ma < 4; ma++) {
        int row0 = bm + wr*64 + ma*16 + g;
        #pragma unroll
        for (int na = 0; na < 4; na++) {
            int col = bn + wc*32 + na*8 + 2*t;
            if (col >= N) continue;
            #pragma unroll
            for (int hh = 0; hh < 2; hh++) {
                int row = row0 + hh*8;
                if (row >= M) continue;
                float v0 = acc[ma][na][hh*2+0] + posb[(long)row*N + col];
                float v1 = acc[ma][na][hh*2+1] + posb[(long)row*N + col + 1];
                if (row == col)   v0 = -1e9f;
                if (row == col+1) v1 = -1e9f;
                *reinterpret_cast<float2*>(C + (long)row*N + col) =
                    make_float2(v0*TEMP_INV, v1*TEMP_INV);
            }
        }
    }
}

// ---------------- shared-memory aggregates (16B aligned) -------------------
union __align__(16) Smem1 {
    struct { uint32_t As[3][TBM][W20]; uint32_t Bs[3][16][W136]; } h;
    struct { uint32_t Ah[2][TBM][W20]; uint32_t Al[2][TBM][W20];
             uint32_t Bh[2][16][W136]; uint32_t Bl[2][16][W136]; } h3;
};
struct __align__(16) Smem2 {
    uint32_t Ah[2][TBM][W20]; uint32_t Al[2][TBM][W20];
    uint32_t Bh[2][TBM][W20]; uint32_t Bl[2][TBM][W20];
};

// ---------------- standalone fp16 GEMM (proj/mlp) ----------------
template<int EPI>
__global__ __launch_bounds__(256, 2) void hmma_nn_kernel(
    const __half* __restrict__ A, const __half* __restrict__ B2,
    void* __restrict__ C, int M, int N, int K, int lda,
    const float* __restrict__ bias, const float* __restrict__ resid)
{
    __shared__ Smem1 sm;
    hmma_body<EPI>(sm.h.As, sm.h.Bs, A, B2, C, M, N, K, lda, bias, resid,
                   blockIdx.y*TBM, blockIdx.x*TBN);
}

// ---------------- CLS attention body ----------------
__device__ void cls_attn_body(const float* __restrict__ qkv,
                              __half* __restrict__ attn, int blk)
{
    int b = blk / HH, h = blk % HH;
    const float* base = qkv + (long)b*SS*3*DD;
    int tid = threadIdx.x;
    __shared__ float qv[HDIM];
    __shared__ float sc[SS];
    __shared__ float red[256];
    __shared__ float m_s, z_s;
    if (tid < HDIM) qv[tid] = base[h*HDIM + tid];
    __syncthreads();

    float lmax = -INFINITY;
    for (int k = tid; k < SS; k += 256) {
        const float* kr = base + (long)k*3*DD + DD + h*HDIM;
        float dot = 0.f;
        #pragma unroll
        for (int d = 0; d < HDIM; d++) dot = fmaf(qv[d], kr[d], dot);
        float s = dot * SCALE_ATT;
        sc[k] = s;
        lmax = fmaxf(lmax, s);
    }
    red[tid] = lmax;
    __syncthreads();
    for (int o = 128; o > 0; o >>= 1) {
        if (tid < o) red[tid] = fmaxf(red[tid], red[tid+o]);
        __syncthreads();
    }
    if (tid == 0) m_s = red[0];
    __syncthreads();
    float m = m_s, lsum = 0.f;
    for (int k = tid; k < SS; k += 256) {
        float e = expf(sc[k]-m); sc[k] = e; lsum += e;
    }
    red[tid] = lsum;
    __syncthreads();
    for (int o = 128; o > 0; o >>= 1) {
        if (tid < o) red[tid] += red[tid+o];
        __syncthreads();
    }
    if (tid == 0) z_s = red[0];
    __syncthreads();
    float zinv = 1.0f / z_s;

    int d = tid & 63, part = tid >> 6;
    float acc = 0.f;
    for (int k = part; k < SS; k += 4)
        acc = fmaf(sc[k], base[(long)k*3*DD + 2*DD + h*HDIM + d], acc);
    __shared__ float ro[4][HDIM];
    ro[part][d] = acc;
    __syncthreads();
    if (tid < HDIM)
        attn[((long)b*SS)*DD + h*HDIM + tid] =
            __float2half((ro[0][tid]+ro[1][tid]+ro[2][tid]+ro[3][tid]) * zinv);
}

// ---------------- fused: routing scores (hmma3 TN) + CLS attention ---------
#define SC_NX ((PP+127)/128)                  // 5
#define SC_MY ((PP+127)/128)                  // 5
#define SC_BLKS (SC_NX*SC_MY*BB)              // 200

__global__ __launch_bounds__(256, 2) void fused_scores_cls_kernel(
    const __half* __restrict__ qh, const __half* __restrict__ ql,
    const __half* __restrict__ kh, const __half* __restrict__ kl,
    float* __restrict__ scores, const float* __restrict__ posb,
    const float* __restrict__ qkv, __half* __restrict__ attn)
{
    int bx = blockIdx.x;
    if (bx < SC_BLKS) {
        __shared__ Smem2 sm;
        int nx = bx % SC_NX;
        int my = (bx / SC_NX) % SC_MY;
        int bz = bx / (SC_NX*SC_MY);
        hmma3_tn_body(sm.Ah, sm.Al, sm.Bh, sm.Bl,
                      qh + (long)bz*PP*DD, ql + (long)bz*PP*DD,
                      kh + (long)bz*PP*DD, kl + (long)bz*PP*DD,
                      scores + (long)bz*PP*PP, PP, PP, DD,
                      posb, my*128, nx*128);
    } else {
        cls_attn_body(qkv, attn, bx - SC_BLKS);
    }
}

// ---------------- fused: q||k routing proj (3-MMA, FIRST) + QKV (hmma) -----
#define QKV_NX  (3*DD/TBN)                    // 18
#define QKV_MY  ((NROWS+TBM-1)/TBM)           // 37
#define QKV_BLKS (QKV_NX*QKV_MY)              // 666
#define QK2_NX  (2*DD/TBN)                    // 12
#define QK2_MY  ((PP+TBM-1)/TBM)              // 5
#define QK2_BLKS (QK2_NX*QK2_MY*BB)           // 480

__global__ __launch_bounds__(256, 2) void fused_qkv_qkproj_kernel(
    const __half* __restrict__ xnh, const __half* __restrict__ xnl,
    const __half* __restrict__ rqkv, const float* __restrict__ b_qkv,
    float* __restrict__ qkvb,
    const __half* __restrict__ wqkh, const __half* __restrict__ wqkl,
    const float* __restrict__ bqk, float* __restrict__ qk)
{
    __shared__ Smem1 sm;
    int bx = blockIdx.x;
    if (bx < QK2_BLKS) {
        // LPT: slow 3-MMA routing blocks scheduled first
        int nx = bx % QK2_NX;
        int my = (bx / QK2_NX) % QK2_MY;
        int bz = bx / (QK2_NX*QK2_MY);
        hmma3_nn_body(sm.h3.Ah, sm.h3.Al, sm.h3.Bh, sm.h3.Bl,
                      xnh + (long)bz*SS*DD + DD,
                      xnl + (long)bz*SS*DD + DD,
                      wqkh, wqkl,
                      qk + (long)bz*PP*2*DD, PP, 2*DD, DD, DD, 2*DD,
                      bqk, my*128, nx*128);
    } else {
        int rel = bx - QK2_BLKS;
        int bn = (rel % QKV_NX)*TBN, bm = (rel / QKV_NX)*TBM;
        hmma_body<0>(sm.h.As, sm.h.Bs, xnh, rqkv, qkvb,
                     NROWS, 3*DD, DD, DD, b_qkv, nullptr, bm, bn);
    }
}

// ---------------- warp-per-row top-32 + log-softmax weights ----------------
__global__ __launch_bounds__(256) void topk_warp_kernel(
    const float* __restrict__ scores, int* __restrict__ routes,
    float* __restrict__ logw)
{
    int warp = blockIdx.x*8 + (threadIdx.x >> 5);
    int lane = threadIdx.x & 31;
    const float* srw = scores + (long)warp*PP;
    float v[18];
    #pragma unroll
    for (int j = 0; j < 18; j++) v[j] = srw[j*32 + lane];

    float myTop = 0.f;
    for (int tt = 0; tt < KWIN; tt++) {
        float bv = -INFINITY; int bj = 0;
        #pragma unroll
        for (int j = 0; j < 18; j++)
            if (v[j] > bv) { bv = v[j]; bj = j; }
        int bi = bj*32 + lane;
        #pragma unroll
        for (int o = 16; o > 0; o >>= 1) {
            float ov = __shfl_xor_sync(0xffffffffu, bv, o);
            int   oi = __shfl_xor_sync(0xffffffffu, bi, o);
            if (ov > bv || (ov == bv && oi < bi)) { bv = ov; bi = oi; }
        }
        if (lane == (bi & 31)) v[bi >> 5] = -INFINITY;
        if (lane == tt) myTop = bv;
        if (lane == 0)  routes[(long)warp*KWIN + tt] = bi;
    }
    float m = __shfl_sync(0xffffffffu, myTop, 0);
    float e = expf(myTop - m);
    float z = e;
    #pragma unroll
    for (int o = 16; o > 0; o >>= 1) z += __shfl_xor_sync(0xffffffffu, z, o);
    float lse = m + logf(z);
    logw[(long)warp*KWIN + lane] = fmaxf(myTop - lse, -10.0f);
}

// ---------------- Patch attention: 4 heads per 256-thread block ------------
__global__ __launch_bounds__(256) void patch_attn_kernel(
    const float* __restrict__ qkv, const int* __restrict__ routes,
    const float* __restrict__ logw, __half* __restrict__ attn)
{
    int id = blockIdx.x;                  // (b*PP + p)*3 + head-group
    int hg = id % 3;
    int bp = id / 3;
    int p = bp % PP;
    int b = bp / PP;
    const float* base = qkv + (long)b*SS*3*DD;
    int tid = threadIdx.x;
    int sub = tid >> 6;                   // 0..3 head within group
    int t64 = tid & 63;
    int h = hg*4 + sub;

    __shared__ float qs[4][HDIM];
    __shared__ int   sr[KWIN];
    __shared__ float slw[KWIN];
    __shared__ float sa[4][KWIN];
    __shared__ float part[4][2][KWIN];

    qs[sub][t64] = base[(long)(p+1)*3*DD + h*HDIM + t64];
    if (tid < KWIN)                 sr[tid]      = routes[((long)bp)*KWIN + tid];
    else if (tid >= 32 && tid < 64) slw[tid-32]  = logw[((long)bp)*KWIN + tid-32];
    __syncthreads();

    int k = t64 & 31, half_ = t64 >> 5;
    const float* kr = base + (long)(sr[k]+1)*3*DD + DD + h*HDIM + half_*32;
    float dot = 0.f;
    #pragma unroll
    for (int d = 0; d < 32; d++) dot = fmaf(qs[sub][half_*32+d], kr[d], dot);
    part[sub][half_][k] = dot;
    __syncthreads();

    if (t64 < KWIN) {                    // warps 0,2,4,6 — one full warp per head
        float s = (part[sub][0][k]+part[sub][1][k]) * SCALE_ATT + slw[k];
        float m = s;
        #pragma unroll
        for (int o = 16; o > 0; o >>= 1) m = fmaxf(m, __shfl_xor_sync(0xffffffffu, m, o));
        float e = expf(s-m);
        float z = e;
        #pragma unroll
        for (int o = 16; o > 0; o >>= 1) z += __shfl_xor_sync(0xffffffffu, z, o);
        sa[sub][k] = e / z;
    }
    __syncthreads();

    float acc = 0.f;
    #pragma unroll 8
    for (int kk = 0; kk < KWIN; kk++)
        acc = fmaf(sa[sub][kk], base[(long)(sr[kk]+1)*3*DD + 2*DD + h*HDIM + t64], acc);
    attn[((long)b*SS + p+1)*DD + h*HDIM + t64] = __float2half(acc);
}

// ---------------- launcher ----------------
extern "C" void kernel_launch(void* const* d_in, const int* in_sizes, int n_in,
                              void* d_out, int out_size)
{
    const float* x      = (const float*)d_in[0];
    const float* g1     = (const float*)d_in[1];
    const float* b1     = (const float*)d_in[2];
    const float* wq     = (const float*)d_in[3];
    const float* bq     = (const float*)d_in[4];
    const float* wk     = (const float*)d_in[5];
    const float* bk     = (const float*)d_in[6];
    const float* posb   = (const float*)d_in[7];
    const float* w_qkv  = (const float*)d_in[8];
    const float* b_qkv  = (const float*)d_in[9];
    const float* w_proj = (const float*)d_in[10];
    const float* b_proj = (const float*)d_in[11];
    const float* g2     = (const float*)d_in[12];
    const float* b2     = (const float*)d_in[13];
    const float* w_mlp1 = (const float*)d_in[14];
    const float* b_mlp1 = (const float*)d_in[15];
    const float* w_mlp2 = (const float*)d_in[16];
    const float* b_mlp2 = (const float*)d_in[17];
    float* out = (float*)d_out;

    float *qk, *scores, *logw, *qkvb, *x1, *bqk;
    __half *xnh, *xnl, *qh, *ql, *kh, *kl, *attn, *xn2, *hbuf;
    __half *rqkv, *rproj, *rm1, *rm2, *wqkh, *wqkl;
    int *routes;
    cudaGetSymbolAddress((void**)&xnh,    g_xnh);
    cudaGetSymbolAddress((void**)&xnl,    g_xnl);
    cudaGetSymbolAddress((void**)&qk,     g_qk);
    cudaGetSymbolAddress((void**)&qh,     g_qh);
    cudaGetSymbolAddress((void**)&ql,     g_ql);
    cudaGetSymbolAddress((void**)&kh,     g_kh);
    cudaGetSymbolAddress((void**)&kl,     g_kl);
    cudaGetSymbolAddress((void**)&scores, g_scores);
    cudaGetSymbolAddress((void**)&routes, g_routes);
    cudaGetSymbolAddress((void**)&logw,   g_logw);
    cudaGetSymbolAddress((void**)&qkvb,   g_qkv);
    cudaGetSymbolAddress((void**)&attn,   g_attn);
    cudaGetSymbolAddress((void**)&x1,     g_x1);
    cudaGetSymbolAddress((void**)&xn2,    g_xn2);
    cudaGetSymbolAddress((void**)&hbuf,   g_h);
    cudaGetSymbolAddress((void**)&rqkv,   g_rqkv);
    cudaGetSymbolAddress((void**)&rproj,  g_rproj);
    cudaGetSymbolAddress((void**)&rm1,    g_rm1);
    cudaGetSymbolAddress((void**)&rm2,    g_rm2);
    cudaGetSymbolAddress((void**)&wqkh,   g_wqkh);
    cudaGetSymbolAddress((void**)&wqkl,   g_wqkl);
    cudaGetSymbolAddress((void**)&bqk,    g_bqk);

    // 0. weight prep
    pack_all_kernel<<<PK_BLKS, 256>>>(w_qkv, rqkv, w_proj, rproj,
                                      w_mlp1, rm1, w_mlp2, rm2);
    pack_qk_kernel<<<PKQK_W_B + 1, 256>>>(wq, wk, bq, bk, wqkh, wqkl, bqk);

    // 1. LN1 -> hi + lo fp16
    ln_kernel<<<NROWS, 256>>>(x, g1, b1, xnh, xnl);

    // 2. FUSED: q||k routing proj (3-MMA, slow blocks first) + QKV (fp16 HMMA)
    fused_qkv_qkproj_kernel<<<QKV_BLKS + QK2_BLKS, 256>>>(
        xnh, xnl, rqkv, b_qkv, qkvb, wqkh, wqkl, bqk, qk);

    // 3. l2 normalize + split q,k into hi/lo fp16
    l2norm_split_kernel<<<2*BB*PP, 256>>>(qk, qh, ql, kh, kl);

    // 4. FUSED: routing scores (double-fp16 TN) + CLS attention
    fused_scores_cls_kernel<<<SC_BLKS + BB*HH, 256>>>(
        qh, ql, kh, kl, scores, posb, qkvb, attn);

    // 5. top-32 + log-softmax weights (warp per row)
    topk_warp_kernel<<<BB*PP/8, 256>>>(scores, routes, logw);

    // 6. patch attention (4 heads per block)
    patch_attn_kernel<<<BB*PP*3, 256>>>(qkvb, routes, logw, attn);

    // 7. proj + residual x (fp16 HMMA, fp32 out)
    {
        dim3 grid(DD/TBN, (NROWS+TBM-1)/TBM);
        hmma_nn_kernel<2><<<grid, 256>>>(attn, rproj, x1, NROWS, DD, DD, DD,
                                         b_proj, x);
    }
    // 8. LN2 (fp16 hi only, feeds MLP1)
    ln_kernel<<<NROWS, 256>>>(x1, g2, b2, xn2, nullptr);

    // 9. MLP1 + exact GELU (fp16 HMMA, fp16 out)
    {
        dim3 grid(MLPD/TBN, (NROWS+TBM-1)/TBM);
        hmma_nn_kernel<3><<<grid, 256>>>(xn2, rm1, hbuf, NROWS, MLPD, DD, DD,
                                         b_mlp1, nullptr);
    }
    // 10. MLP2 + residual x1 -> out (fp16 HMMA, fp32 out)
    {
        dim3 grid(DD/TBN, (NROWS+TBM-1)/TBM);
        hmma_nn_kernel<2><<<grid, 256>>>(hbuf, rm2, out, NROWS, DD, MLPD, MLPD,
                                         b_mlp2, x1);
    }
}

// round 16
// speedup vs baseline: 1.0852x; 1.0215x over previous
#include <cuda_runtime.h>
#include <cuda_fp16.h>
#include <math.h>
#include <stdint.h>

// ---------------- problem constants ----------------
#define BB   8
#define SS   577
#define DD   768
#define HH   12
#define HDIM 64
#define PP   576
#define KWIN 32
#define MLPD 3072
#define NROWS (BB*SS)        // 4616
#define SCALE_ATT 0.125f
#define TEMP_INV  10.0f

#define TBM 128
#define TBN 128
#define TBK 32
#define W20  20
#define W136 136

__device__ __forceinline__ void cp16(void* dst_smem, const void* src, int srcsize) {
    uint32_t d = (uint32_t)__cvta_generic_to_shared(dst_smem);
    asm volatile("cp.async.cg.shared.global [%0], [%1], 16, %2;"
                 :: "r"(d), "l"(src), "r"(srcsize));
}
__device__ __forceinline__ void mma_f16(float* d, const uint32_t* a, const uint32_t* b) {
    asm volatile(
        "mma.sync.aligned.m16n8k16.row.col.f32.f16.f16.f32 "
        "{%0,%1,%2,%3}, {%4,%5,%6,%7}, {%8,%9}, {%0,%1,%2,%3};"
        : "+f"(d[0]), "+f"(d[1]), "+f"(d[2]), "+f"(d[3])
        : "r"(a[0]), "r"(a[1]), "r"(a[2]), "r"(a[3]), "r"(b[0]), "r"(b[1]));
}
__device__ __forceinline__ void ldsm_x4(uint32_t* r, const void* smem_ptr) {
    uint32_t a = (uint32_t)__cvta_generic_to_shared(smem_ptr);
    asm volatile("ldmatrix.sync.aligned.m8n8.x4.shared.b16 {%0,%1,%2,%3}, [%4];"
                 : "=r"(r[0]), "=r"(r[1]), "=r"(r[2]), "=r"(r[3]) : "r"(a));
}
__device__ __forceinline__ void ldsm_x2(uint32_t* r, const void* smem_ptr) {
    uint32_t a = (uint32_t)__cvta_generic_to_shared(smem_ptr);
    asm volatile("ldmatrix.sync.aligned.m8n8.x2.shared.b16 {%0,%1}, [%2];"
                 : "=r"(r[0]), "=r"(r[1]) : "r"(a));
}
__device__ __forceinline__ void split1(float v, __half& h, __half& l) {
    h = __float2half(v);
    l = __float2half(v - __half2float(h));
}

// ---------------- scratch (device globals) ----------------
__device__ __half g_xnh  [(size_t)BB*SS*DD];
__device__ __half g_xnl  [(size_t)BB*SS*DD];
__device__ float  g_qk   [(size_t)BB*PP*2*DD];
__device__ __half g_qh   [(size_t)BB*PP*DD];
__device__ __half g_ql   [(size_t)BB*PP*DD];
__device__ __half g_kh   [(size_t)BB*PP*DD];
__device__ __half g_kl   [(size_t)BB*PP*DD];
__device__ float  g_scores[(size_t)BB*PP*PP];
__device__ int    g_routes[(size_t)BB*PP*KWIN];
__device__ float  g_logw  [(size_t)BB*PP*KWIN];
__device__ float  g_qkv  [(size_t)BB*SS*3*DD];
__device__ __half g_attn [(size_t)BB*SS*DD];
__device__ float  g_x1   [(size_t)BB*SS*DD];
__device__ __half g_xn2  [(size_t)BB*SS*DD];
__device__ __half g_h    [(size_t)BB*SS*MLPD];
__device__ __half g_rqkv [(size_t)DD*3*DD];
__device__ __half g_rproj[(size_t)DD*DD];
__device__ __half g_rm1  [(size_t)DD*MLPD];
__device__ __half g_rm2  [(size_t)MLPD*DD];
__device__ __half g_wqkh [(size_t)DD*2*DD];
__device__ __half g_wqkl [(size_t)DD*2*DD];
__device__ float  g_bqk  [(size_t)2*DD];

// ---------------- pack big-gemm weights ------------
#define PK_QKV_B  (DD*3*DD/2048)
#define PK_PROJ_B (DD*DD/2048)
#define PK_M1_B   (DD*MLPD/2048)
#define PK_M2_B   (MLPD*DD/2048)
#define PK_BLKS   (PK_QKV_B+PK_PROJ_B+PK_M1_B+PK_M2_B)

__global__ __launch_bounds__(256) void pack_all_kernel(
    const float* __restrict__ wqkv, __half* __restrict__ rqkv,
    const float* __restrict__ wproj, __half* __restrict__ rproj,
    const float* __restrict__ wm1, __half* __restrict__ rm1,
    const float* __restrict__ wm2, __half* __restrict__ rm2)
{
    int bx = blockIdx.x;
    const float* src; __half* dst; int N; long base;
    if (bx < PK_QKV_B)                       { src = wqkv;  dst = rqkv;  N = 3*DD; base = bx; }
    else if (bx < PK_QKV_B+PK_PROJ_B)        { src = wproj; dst = rproj; N = DD;   base = bx-PK_QKV_B; }
    else if (bx < PK_QKV_B+PK_PROJ_B+PK_M1_B){ src = wm1;   dst = rm1;   N = MLPD; base = bx-PK_QKV_B-PK_PROJ_B; }
    else                                     { src = wm2;   dst = rm2;   N = DD;   base = bx-PK_QKV_B-PK_PROJ_B-PK_M1_B; }
    long id = base*256 + threadIdx.x;
    int npg = N/4;
    long k2 = id / npg;
    int  n  = (int)(id % npg) * 4;
    float4 e = *reinterpret_cast<const float4*>(src + (2*k2  )*N + n);
    float4 o = *reinterpret_cast<const float4*>(src + (2*k2+1)*N + n);
    __half2 out[4];
    out[0] = __floats2half2_rn(e.x, o.x);
    out[1] = __floats2half2_rn(e.y, o.y);
    out[2] = __floats2half2_rn(e.z, o.z);
    out[3] = __floats2half2_rn(e.w, o.w);
    *reinterpret_cast<uint4*>(dst + (k2*N + n)*2) = *reinterpret_cast<uint4*>(out);
}

// ---------------- pack routing weights ----------------
#define PKQK_W_B ((DD/2)*(2*DD)/1024)   // 576
__global__ __launch_bounds__(256) void pack_qk_kernel(
    const float* __restrict__ wq, const float* __restrict__ wk,
    const float* __restrict__ bq, const float* __restrict__ bk,
    __half* __restrict__ wh, __half* __restrict__ wl, float* __restrict__ bqk)
{
    int bx = blockIdx.x;
    if (bx == PKQK_W_B) {
        for (int i = threadIdx.x; i < 2*DD; i += 256)
            bqk[i] = (i < DD) ? bq[i] : bk[i - DD];
        return;
    }
    const int N2 = 2*DD;
    long id = (long)bx*256 + threadIdx.x;
    long k2 = id / (N2/4);
    int  n  = (int)(id % (N2/4)) * 4;
    const float* src = (n < DD) ? wq : wk;
    int nn = (n < DD) ? n : n - DD;
    float4 e = *reinterpret_cast<const float4*>(src + (2*k2  )*DD + nn);
    float4 o = *reinterpret_cast<const float4*>(src + (2*k2+1)*DD + nn);
    __half2 oh[4], ol[4];
    #pragma unroll
    for (int u = 0; u < 4; u++) {
        float ev = (&e.x)[u], ov = (&o.x)[u];
        __half eh, el, ohh, oll;
        split1(ev, eh, el); split1(ov, ohh, oll);
        oh[u] = __halves2half2(eh, ohh);
        ol[u] = __halves2half2(el, oll);
    }
    *reinterpret_cast<uint4*>(wh + (k2*N2 + n)*2) = *reinterpret_cast<uint4*>(oh);
    *reinterpret_cast<uint4*>(wl + (k2*N2 + n)*2) = *reinterpret_cast<uint4*>(ol);
}

// ---------------- LayerNorm: fp16 hi out + optional fp16 lo out ------------
__global__ __launch_bounds__(256) void ln_kernel(
    const float* __restrict__ x, const float* __restrict__ g,
    const float* __restrict__ b, __half* __restrict__ yh,
    __half* __restrict__ yl)
{
    int row = blockIdx.x;
    const float* xr = x + (long)row*DD;
    float s = 0.f, sq = 0.f;
    for (int d = threadIdx.x; d < DD; d += 256) {
        float v = xr[d]; s += v; sq += v*v;
    }
    __shared__ float rs[256], rq[256];
    rs[threadIdx.x] = s; rq[threadIdx.x] = sq;
    __syncthreads();
    for (int o = 128; o > 0; o >>= 1) {
        if (threadIdx.x < o) { rs[threadIdx.x] += rs[threadIdx.x+o]; rq[threadIdx.x] += rq[threadIdx.x+o]; }
        __syncthreads();
    }
    __shared__ float mean_s, rstd_s;
    if (threadIdx.x == 0) {
        float mean = rs[0] / (float)DD;
        float var  = rq[0] / (float)DD - mean*mean;
        mean_s = mean;
        rstd_s = rsqrtf(var + 1e-5f);
    }
    __syncthreads();
    float mean = mean_s, rstd = rstd_s;
    __half* yhb = yh + (long)row*DD;
    __half* ylb = yl ? (yl + (long)row*DD) : nullptr;
    for (int d = threadIdx.x; d < DD; d += 256) {
        float v = (xr[d]-mean)*rstd*g[d] + b[d];
        __half h = __float2half(v);
        yhb[d] = h;
        if (ylb) ylb[d] = __float2half(v - __half2float(h));
    }
}

// ---------------- L2 normalize q||k rows + split into hi/lo fp16 -----------
__global__ __launch_bounds__(256) void l2norm_split_kernel(
    const float* __restrict__ qk,
    __half* __restrict__ qh, __half* __restrict__ ql,
    __half* __restrict__ kh, __half* __restrict__ kl)
{
    int row = blockIdx.x;
    int isK = row >= BB*PP;
    int r   = isK ? row - BB*PP : row;
    const float* xr = qk + (long)r*(2*DD) + (isK ? DD : 0);
    float sq = 0.f;
    for (int d = threadIdx.x; d < DD; d += 256) { float v = xr[d]; sq += v*v; }
    __shared__ float rq[256];
    rq[threadIdx.x] = sq;
    __syncthreads();
    for (int o = 128; o > 0; o >>= 1) {
        if (threadIdx.x < o) rq[threadIdx.x] += rq[threadIdx.x+o];
        __syncthreads();
    }
    __shared__ float inv_s;
    if (threadIdx.x == 0) inv_s = 1.0f / fmaxf(sqrtf(rq[0]), 1e-12f);
    __syncthreads();
    float inv = inv_s;
    __half* oh = (isK ? kh : qh) + (long)r*DD;
    __half* ol = (isK ? kl : ql) + (long)r*DD;
    for (int d = threadIdx.x; d < DD; d += 256) {
        float v = xr[d]*inv;
        __half h = __float2half(v);
        oh[d] = h;
        ol[d] = __float2half(v - __half2float(h));
    }
}

// ---------------- fp16 HMMA body: TBM=128, TBK=32, 3-stage (fused QKV) -----
template<int EPI>
__device__ __forceinline__ void hmma_body(
    uint32_t (*As)[TBM][W20], uint32_t (*Bs)[16][W136],
    const __half* __restrict__ A, const __half* __restrict__ B2,
    void* __restrict__ Cv, int M, int N, int K, int lda,
    const float* __restrict__ bias, const float* __restrict__ resid,
    int bm, int bn)
{
    int tid  = threadIdx.x;
    int wid  = tid >> 5, lane = tid & 31;
    int wr   = wid & 1;
    int wc   = wid >> 1;
    int g    = lane >> 2;
    int t    = lane & 3;
    int rsel = (lane & 7) + ((lane >> 3) & 1)*8;
    int wsel = (lane >> 4)*4;

    float acc[4][4][4];
    #pragma unroll
    for (int i = 0; i < 4; i++)
        #pragma unroll
        for (int j = 0; j < 4; j++)
            #pragma unroll
            for (int r = 0; r < 4; r++) acc[i][j][r] = 0.f;

    auto load_stage = [&](int buf, int k0) {
        #pragma unroll
        for (int i = 0; i < 2; i++) {
            int id = i*256 + tid;
            int row = id >> 2, c = id & 3;
            int m = bm + row;
            cp16(&As[buf][row][c*4], A + (long)m*lda + k0 + c*8, m < M ? 16 : 0);
        }
        #pragma unroll
        for (int i = 0; i < 2; i++) {
            int id = i*256 + tid;
            int row = id >> 5, c = id & 31;
            cp16(&Bs[buf][row][c*4],
                 B2 + ((long)((k0>>1) + row)*N + bn + c*4)*2, 16);
        }
        asm volatile("cp.async.commit_group;");
    };

    int KT = K >> 5;
    load_stage(0, 0);
    load_stage(1, TBK);
    for (int kt = 0; kt < KT; kt++) {
        if (kt + 2 < KT) asm volatile("cp.async.wait_group 1;");
        else             asm volatile("cp.async.wait_group 0;");
        __syncthreads();
        if (kt + 2 < KT) load_stage((kt+2)%3, (kt+2)*TBK);
        int buf = kt % 3;

        #pragma unroll
        for (int ka = 0; ka < 2; ka++) {
            int kw = ka*8;
            uint32_t afrag[4][4];
            #pragma unroll
            for (int ma = 0; ma < 4; ma++)
                ldsm_x4(afrag[ma], &As[buf][wr*64 + ma*16 + rsel][kw + wsel]);
            uint32_t bfrag[4][2];
            #pragma unroll
            for (int na = 0; na < 4; na++) {
                int c = wc*32 + na*8 + g;
                bfrag[na][0] = Bs[buf][kw + t    ][c];
                bfrag[na][1] = Bs[buf][kw + t + 4][c];
            }
            #pragma unroll
            for (int ma = 0; ma < 4; ma++)
                #pragma unroll
                for (int na = 0; na < 4; na++)
                    mma_f16(acc[ma][na], afrag[ma], bfrag[na]);
        }
    }

    #pragma unroll
    for (int ma = 0; ma < 4; ma++) {
        int row0 = bm + wr*64 + ma*16 + g;
        #pragma unroll
        for (int na = 0; na < 4; na++) {
            int col = bn + wc*32 + na*8 + 2*t;
            float b0 = bias[col], b1 = bias[col+1];
            #pragma unroll
            for (int hh = 0; hh < 2; hh++) {
                int row = row0 + hh*8;
                if (row >= M) continue;
                float v0 = acc[ma][na][hh*2+0] + b0;
                float v1 = acc[ma][na][hh*2+1] + b1;
                if (EPI == 3) {
                    v0 = 0.5f*v0*(1.0f + erff(v0*0.7071067811865475f));
                    v1 = 0.5f*v1*(1.0f + erff(v1*0.7071067811865475f));
                    *reinterpret_cast<__half2*>((__half*)Cv + (long)row*N + col) =
                        __floats2half2_rn(v0, v1);
                } else {
                    if (EPI == 2) {
                        v0 += resid[(long)row*N + col];
                        v1 += resid[(long)row*N + col + 1];
                    }
                    *reinterpret_cast<float2*>((float*)Cv + (long)row*N + col) =
                        make_float2(v0, v1);
                }
            }
        }
    }
}

// ---------------- fp16 HMMA body: TBM=64 (3 CTAs/SM, standalone GEMMs) -----
struct __align__(16) Smem64 {
    uint32_t As[3][64][W20];     // 15360 B
    uint32_t Bs[3][16][W136];    // 26112 B  -> 41472 B total
};

template<int EPI>
__global__ __launch_bounds__(256, 3) void hmma64_nn_kernel(
    const __half* __restrict__ A, const __half* __restrict__ B2,
    void* __restrict__ Cv, int M, int N, int K, int lda,
    const float* __restrict__ bias, const float* __restrict__ resid)
{
    __shared__ Smem64 sm;
    int tid  = threadIdx.x;
    int wid  = tid >> 5, lane = tid & 31;
    int wr   = wid & 1;          // 2 x 32 rows
    int wc   = wid >> 1;         // 4 x 32 cols
    int g    = lane >> 2;
    int t    = lane & 3;
    int rsel = (lane & 7) + ((lane >> 3) & 1)*8;
    int wsel = (lane >> 4)*4;
    int bm   = blockIdx.y*64;
    int bn   = blockIdx.x*TBN;

    float acc[2][4][4];
    #pragma unroll
    for (int i = 0; i < 2; i++)
        #pragma unroll
        for (int j = 0; j < 4; j++)
            #pragma unroll
            for (int r = 0; r < 4; r++) acc[i][j][r] = 0.f;

    auto load_stage = [&](int buf, int k0) {
        {   // A: 64 rows x 16 words = 256 chunks (one pass)
            int row = tid >> 2, c = tid & 3;
            int m = bm + row;
            cp16(&sm.As[buf][row][c*4], A + (long)m*lda + k0 + c*8, m < M ? 16 : 0);
        }
        #pragma unroll
        for (int i = 0; i < 2; i++) {
            int id = i*256 + tid;
            int row = id >> 5, c = id & 31;
            cp16(&sm.Bs[buf][row][c*4],
                 B2 + ((long)((k0>>1) + row)*N + bn + c*4)*2, 16);
        }
        asm volatile("cp.async.commit_group;");
    };

    int KT = K >> 5;
    load_stage(0, 0);
    load_stage(1, TBK);
    for (int kt = 0; kt < KT; kt++) {
        if (kt + 2 < KT) asm volatile("cp.async.wait_group 1;");
        else             asm volatile("cp.async.wait_group 0;");
        __syncthreads();
        if (kt + 2 < KT) load_stage((kt+2)%3, (kt+2)*TBK);
        int buf = kt % 3;

        #pragma unroll
        for (int ka = 0; ka < 2; ka++) {
            int kw = ka*8;
            uint32_t afrag[2][4];
            #pragma unroll
            for (int ma = 0; ma < 2; ma++)
                ldsm_x4(afrag[ma], &sm.As[buf][wr*32 + ma*16 + rsel][kw + wsel]);
            uint32_t bfrag[4][2];
            #pragma unroll
            for (int na = 0; na < 4; na++) {
                int c = wc*32 + na*8 + g;
                bfrag[na][0] = sm.Bs[buf][kw + t    ][c];
                bfrag[na][1] = sm.Bs[buf][kw + t + 4][c];
            }
            #pragma unroll
            for (int ma = 0; ma < 2; ma++)
                #pragma unroll
                for (int na = 0; na < 4; na++)
                    mma_f16(acc[ma][na], afrag[ma], bfrag[na]);
        }
    }

    #pragma unroll
    for (int ma = 0; ma < 2; ma++) {
        int row0 = bm + wr*32 + ma*16 + g;
        #pragma unroll
        for (int na = 0; na < 4; na++) {
            int col = bn + wc*32 + na*8 + 2*t;
            float b0 = bias[col], b1 = bias[col+1];
            #pragma unroll
            for (int hh = 0; hh < 2; hh++) {
                int row = row0 + hh*8;
                if (row >= M) continue;
                float v0 = acc[ma][na][hh*2+0] + b0;
                float v1 = acc[ma][na][hh*2+1] + b1;
                if (EPI == 3) {
                    v0 = 0.5f*v0*(1.0f + erff(v0*0.7071067811865475f));
                    v1 = 0.5f*v1*(1.0f + erff(v1*0.7071067811865475f));
                    *reinterpret_cast<__half2*>((__half*)Cv + (long)row*N + col) =
                        __floats2half2_rn(v0, v1);
                } else {
                    if (EPI == 2) {
                        v0 += resid[(long)row*N + col];
                        v1 += resid[(long)row*N + col + 1];
                    }
                    *reinterpret_cast<float2*>((float*)Cv + (long)row*N + col) =
                        make_float2(v0, v1);
                }
            }
        }
    }
}

// ---------------- double-fp16 (3-MMA) NN body, ldmatrix A ------------------
__device__ __forceinline__ void hmma3_nn_body(
    uint32_t (*Ah)[TBM][W20], uint32_t (*Al)[TBM][W20],
    uint32_t (*Bh)[16][W136], uint32_t (*Bl)[16][W136],
    const __half* __restrict__ Axh, const __half* __restrict__ Axl,
    const __half* __restrict__ Bwh, const __half* __restrict__ Bwl,
    float* __restrict__ C, int M, int N, int K, int lda, int ldc,
    const float* __restrict__ bias, int bm, int bn)
{
    int tid = threadIdx.x, wid = tid >> 5, lane = tid & 31;
    int wr = wid & 1, wc = wid >> 1, g = lane >> 2, t = lane & 3;
    int rsel = (lane & 7) + ((lane >> 3) & 1)*8;
    int wsel = (lane >> 4)*4;

    float acc[4][4][4];
    #pragma unroll
    for (int i = 0; i < 4; i++)
        #pragma unroll
        for (int j = 0; j < 4; j++)
            #pragma unroll
            for (int r = 0; r < 4; r++) acc[i][j][r] = 0.f;

    auto load_stage = [&](int buf, int k0) {
        #pragma unroll
        for (int i = 0; i < 2; i++) {
            int id = i*256 + tid;
            int row = id >> 2, c = id & 3;
            int m = bm + row;
            cp16(&Ah[buf][row][c*4], Axh + (long)m*lda + k0 + c*8, m < M ? 16 : 0);
            cp16(&Al[buf][row][c*4], Axl + (long)m*lda + k0 + c*8, m < M ? 16 : 0);
        }
        #pragma unroll
        for (int i = 0; i < 2; i++) {
            int id = i*256 + tid;
            int row = id >> 5, c = id & 31;
            long off = ((long)((k0>>1) + row)*N + bn + c*4)*2;
            cp16(&Bh[buf][row][c*4], Bwh + off, 16);
            cp16(&Bl[buf][row][c*4], Bwl + off, 16);
        }
        asm volatile("cp.async.commit_group;");
    };

    int KT = K >> 5;
    load_stage(0, 0);
    for (int kt = 0; kt < KT; kt++) {
        asm volatile("cp.async.wait_group 0;");
        __syncthreads();
        if (kt + 1 < KT) load_stage((kt+1)&1, (kt+1)*TBK);
        int buf = kt & 1;

        #pragma unroll
        for (int ka = 0; ka < 2; ka++) {
            int kw = ka*8;
            uint32_t bh[4][2], bl[4][2];
            #pragma unroll
            for (int na = 0; na < 4; na++) {
                int c = wc*32 + na*8 + g;
                bh[na][0] = Bh[buf][kw + t][c];  bh[na][1] = Bh[buf][kw + t + 4][c];
                bl[na][0] = Bl[buf][kw + t][c];  bl[na][1] = Bl[buf][kw + t + 4][c];
            }
            #pragma unroll
            for (int ma = 0; ma < 4; ma++) {
                uint32_t ah[4], al[4];
                ldsm_x4(ah, &Ah[buf][wr*64 + ma*16 + rsel][kw + wsel]);
                ldsm_x4(al, &Al[buf][wr*64 + ma*16 + rsel][kw + wsel]);
                #pragma unroll
                for (int na = 0; na < 4; na++) {
                    mma_f16(acc[ma][na], ah, bh[na]);
                    mma_f16(acc[ma][na], ah, bl[na]);
                    mma_f16(acc[ma][na], al, bh[na]);
                }
            }
        }
    }

    #pragma unroll
    for (int ma = 0; ma < 4; ma++) {
        int row0 = bm + wr*64 + ma*16 + g;
        #pragma unroll
        for (int na = 0; na < 4; na++) {
            int col = bn + wc*32 + na*8 + 2*t;
            float b0 = bias[col], b1 = bias[col+1];
            #pragma unroll
            for (int hh = 0; hh < 2; hh++) {
                int row = row0 + hh*8;
                if (row >= M) continue;
                *reinterpret_cast<float2*>(C + (long)row*ldc + col) =
                    make_float2(acc[ma][na][hh*2+0] + b0, acc[ma][na][hh*2+1] + b1);
            }
        }
    }
}

// ---------------- double-fp16 (3-MMA) TN body, ldmatrix A+B ----------------
__device__ __forceinline__ void hmma3_tn_body(
    uint32_t (*Ah)[TBM][W20], uint32_t (*Al)[TBM][W20],
    uint32_t (*Bh)[TBM][W20], uint32_t (*Bl)[TBM][W20],
    const __half* __restrict__ Axh, const __half* __restrict__ Axl,
    const __half* __restrict__ Bxh, const __half* __restrict__ Bxl,
    float* __restrict__ C, int M, int N, int K,
    const float* __restrict__ posb, int bm, int bn)
{
    int tid = threadIdx.x, wid = tid >> 5, lane = tid & 31;
    int wr = wid & 1, wc = wid >> 1, g = lane >> 2, t = lane & 3;
    int rsel  = (lane & 7) + ((lane >> 3) & 1)*8;
    int wsel  = (lane >> 4)*4;
    int rsel2 = lane & 7;
    int wsel2 = ((lane >> 3) & 1)*4;

    float acc[4][4][4];
    #pragma unroll
    for (int i = 0; i < 4; i++)
        #pragma unroll
        for (int j = 0; j < 4; j++)
            #pragma unroll
            for (int r = 0; r < 4; r++) acc[i][j][r] = 0.f;

    auto load_stage = [&](int buf, int k0) {
        #pragma unroll
        for (int i = 0; i < 2; i++) {
            int id = i*256 + tid;
            int row = id >> 2, c = id & 3;
            int m = bm + row;
            cp16(&Ah[buf][row][c*4], Axh + (long)m*K + k0 + c*8, m < M ? 16 : 0);
            cp16(&Al[buf][row][c*4], Axl + (long)m*K + k0 + c*8, m < M ? 16 : 0);
        }
        #pragma unroll
        for (int i = 0; i < 2; i++) {
            int id = i*256 + tid;
            int row = id >> 2, c = id & 3;
            int n = bn + row;
            cp16(&Bh[buf][row][c*4], Bxh + (long)n*K + k0 + c*8, n < N ? 16 : 0);
            cp16(&Bl[buf][row][c*4], Bxl + (long)n*K + k0 + c*8, n < N ? 16 : 0);
        }
        asm volatile("cp.async.commit_group;");
    };

    int KT = K >> 5;
    load_stage(0, 0);
    for (int kt = 0; kt < KT; kt++) {
        asm volatile("cp.async.wait_group 0;");
        __syncthreads();
        if (kt + 1 < KT) load_stage((kt+1)&1, (kt+1)*TBK);
        int buf = kt & 1;

        #pragma unroll
        for (int ka = 0; ka < 2; ka++) {
            int kw = ka*8;
            uint32_t bh[4][2], bl[4][2];
            #pragma unroll
            for (int na = 0; na < 4; na++) {
                ldsm_x2(bh[na], &Bh[buf][wc*32 + na*8 + rsel2][kw + wsel2]);
                ldsm_x2(bl[na], &Bl[buf][wc*32 + na*8 + rsel2][kw + wsel2]);
            }
            #pragma unroll
            for (int ma = 0; ma < 4; ma++) {
                uint32_t ah[4], al[4];
                ldsm_x4(ah, &Ah[buf][wr*64 + ma*16 + rsel][kw + wsel]);
                ldsm_x4(al, &Al[buf][wr*64 + ma*16 + rsel][kw + wsel]);
                #pragma unroll
                for (int na = 0; na < 4; na++) {
                    mma_f16(acc[ma][na], ah, bh[na]);
                    mma_f16(acc[ma][na], ah, bl[na]);
                    mma_f16(acc[ma][na], al, bh[na]);
                }
            }
        }
    }

    #pragma unroll
    for (int ma = 0; ma < 4; ma++) {
        int row0 = bm + wr*64 + ma*16 + g;
        #pragma unroll
        for (int na = 0; na < 4; na++) {
            int col = bn + wc*32 + na*8 + 2*t;
            if (col >= N) continue;
            #pragma unroll
            for (int hh = 0; hh < 2; hh++) {
                int row = row0 + hh*8;
                if (row >= M) continue;
                float v0 = acc[ma][na][hh*2+0] + posb[(long)row*N + col];
                float v1 = acc[ma][na][hh*2+1] + posb[(long)row*N + col + 1];
                if (row == col)   v0 = -1e9f;
                if (row == col+1) v1 = -1e9f;
                *reinterpret_cast<float2*>(C + (long)row*N + col) =
                    make_float2(v0*TEMP_INV, v1*TEMP_INV);
            }
        }
    }
}

// ---------------- shared-memory aggregates (16B aligned) -------------------
union __align__(16) Smem1 {
    struct { uint32_t As[3][TBM][W20]; uint32_t Bs[3][16][W136]; } h;
    struct { uint32_t Ah[2][TBM][W20]; uint32_t Al[2][TBM][W20];
             uint32_t Bh[2][16][W136]; uint32_t Bl[2][16][W136]; } h3;
};
struct __align__(16) Smem2 {
    uint32_t Ah[2][TBM][W20]; uint32_t Al[2][TBM][W20];
    uint32_t Bh[2][TBM][W20]; uint32_t Bl[2][TBM][W20];
};

// ---------------- CLS attention body ----------------
__device__ void cls_attn_body(const float* __restrict__ qkv,
                              __half* __restrict__ attn, int blk)
{
    int b = blk / HH, h = blk % HH;
    const float* base = qkv + (long)b*SS*3*DD;
    int tid = threadIdx.x;
    __shared__ float qv[HDIM];
    __shared__ float sc[SS];
    __shared__ float red[256];
    __shared__ float m_s, z_s;
    if (tid < HDIM) qv[tid] = base[h*HDIM + tid];
    __syncthreads();

    float lmax = -INFINITY;
    for (int k = tid; k < SS; k += 256) {
        const float* kr = base + (long)k*3*DD + DD + h*HDIM;
        float dot = 0.f;
        #pragma unroll
        for (int d = 0; d < HDIM; d++) dot = fmaf(qv[d], kr[d], dot);
        float s = dot * SCALE_ATT;
        sc[k] = s;
        lmax = fmaxf(lmax, s);
    }
    red[tid] = lmax;
    __syncthreads();
    for (int o = 128; o > 0; o >>= 1) {
        if (tid < o) red[tid] = fmaxf(red[tid], red[tid+o]);
        __syncthreads();
    }
    if (tid == 0) m_s = red[0];
    __syncthreads();
    float m = m_s, lsum = 0.f;
    for (int k = tid; k < SS; k += 256) {
        float e = expf(sc[k]-m); sc[k] = e; lsum += e;
    }
    red[tid] = lsum;
    __syncthreads();
    for (int o = 128; o > 0; o >>= 1) {
        if (tid < o) red[tid] += red[tid+o];
        __syncthreads();
    }
    if (tid == 0) z_s = red[0];
    __syncthreads();
    float zinv = 1.0f / z_s;

    int d = tid & 63, part = tid >> 6;
    float acc = 0.f;
    for (int k = part; k < SS; k += 4)
        acc = fmaf(sc[k], base[(long)k*3*DD + 2*DD + h*HDIM + d], acc);
    __shared__ float ro[4][HDIM];
    ro[part][d] = acc;
    __syncthreads();
    if (tid < HDIM)
        attn[((long)b*SS)*DD + h*HDIM + tid] =
            __float2half((ro[0][tid]+ro[1][tid]+ro[2][tid]+ro[3][tid]) * zinv);
}

// ---------------- fused: routing scores (hmma3 TN) + CLS attention ---------
#define SC_NX ((PP+127)/128)                  // 5
#define SC_MY ((PP+127)/128)                  // 5
#define SC_BLKS (SC_NX*SC_MY*BB)              // 200

__global__ __launch_bounds__(256, 2) void fused_scores_cls_kernel(
    const __half* __restrict__ qh, const __half* __restrict__ ql,
    const __half* __restrict__ kh, const __half* __restrict__ kl,
    float* __restrict__ scores, const float* __restrict__ posb,
    const float* __restrict__ qkv, __half* __restrict__ attn)
{
    int bx = blockIdx.x;
    if (bx < SC_BLKS) {
        __shared__ Smem2 sm;
        int nx = bx % SC_NX;
        int my = (bx / SC_NX) % SC_MY;
        int bz = bx / (SC_NX*SC_MY);
        hmma3_tn_body(sm.Ah, sm.Al, sm.Bh, sm.Bl,
                      qh + (long)bz*PP*DD, ql + (long)bz*PP*DD,
                      kh + (long)bz*PP*DD, kl + (long)bz*PP*DD,
                      scores + (long)bz*PP*PP, PP, PP, DD,
                      posb, my*128, nx*128);
    } else {
        cls_attn_body(qkv, attn, bx - SC_BLKS);
    }
}

// ---------------- fused: q||k routing proj (3-MMA, FIRST) + QKV (hmma) -----
#define QKV_NX  (3*DD/TBN)                    // 18
#define QKV_MY  ((NROWS+TBM-1)/TBM)           // 37
#define QKV_BLKS (QKV_NX*QKV_MY)              // 666
#define QK2_NX  (2*DD/TBN)                    // 12
#define QK2_MY  ((PP+TBM-1)/TBM)              // 5
#define QK2_BLKS (QK2_NX*QK2_MY*BB)           // 480

__global__ __launch_bounds__(256, 2) void fused_qkv_qkproj_kernel(
    const __half* __restrict__ xnh, const __half* __restrict__ xnl,
    const __half* __restrict__ rqkv, const float* __restrict__ b_qkv,
    float* __restrict__ qkvb,
    const __half* __restrict__ wqkh, const __half* __restrict__ wqkl,
    const float* __restrict__ bqk, float* __restrict__ qk)
{
    __shared__ Smem1 sm;
    int bx = blockIdx.x;
    if (bx < QK2_BLKS) {
        int nx = bx % QK2_NX;
        int my = (bx / QK2_NX) % QK2_MY;
        int bz = bx / (QK2_NX*QK2_MY);
        hmma3_nn_body(sm.h3.Ah, sm.h3.Al, sm.h3.Bh, sm.h3.Bl,
                      xnh + (long)bz*SS*DD + DD,
                      xnl + (long)bz*SS*DD + DD,
                      wqkh, wqkl,
                      qk + (long)bz*PP*2*DD, PP, 2*DD, DD, DD, 2*DD,
                      bqk, my*128, nx*128);
    } else {
        int rel = bx - QK2_BLKS;
        int bn = (rel % QKV_NX)*TBN, bm = (rel / QKV_NX)*TBM;
        hmma_body<0>(sm.h.As, sm.h.Bs, xnh, rqkv, qkvb,
                     NROWS, 3*DD, DD, DD, b_qkv, nullptr, bm, bn);
    }
}

// ---------------- warp-per-row top-32 + log-softmax weights ----------------
__global__ __launch_bounds__(256) void topk_warp_kernel(
    const float* __restrict__ scores, int* __restrict__ routes,
    float* __restrict__ logw)
{
    int warp = blockIdx.x*8 + (threadIdx.x >> 5);
    int lane = threadIdx.x & 31;
    const float* srw = scores + (long)warp*PP;
    float v[18];
    #pragma unroll
    for (int j = 0; j < 18; j++) v[j] = srw[j*32 + lane];

    float myTop = 0.f;
    for (int tt = 0; tt < KWIN; tt++) {
        float bv = -INFINITY; int bj = 0;
        #pragma unroll
        for (int j = 0; j < 18; j++)
            if (v[j] > bv) { bv = v[j]; bj = j; }
        int bi = bj*32 + lane;
        #pragma unroll
        for (int o = 16; o > 0; o >>= 1) {
            float ov = __shfl_xor_sync(0xffffffffu, bv, o);
            int   oi = __shfl_xor_sync(0xffffffffu, bi, o);
            if (ov > bv || (ov == bv && oi < bi)) { bv = ov; bi = oi; }
        }
        if (lane == (bi & 31)) v[bi >> 5] = -INFINITY;
        if (lane == tt) myTop = bv;
        if (lane == 0)  routes[(long)warp*KWIN + tt] = bi;
    }
    float m = __shfl_sync(0xffffffffu, myTop, 0);
    float e = expf(myTop - m);
    float z = e;
    #pragma unroll
    for (int o = 16; o > 0; o >>= 1) z += __shfl_xor_sync(0xffffffffu, z, o);
    float lse = m + logf(z);
    logw[(long)warp*KWIN + lane] = fmaxf(myTop - lse, -10.0f);
}

// ---------------- Patch attention: 4 heads per 256-thread block ------------
__global__ __launch_bounds__(256) void patch_attn_kernel(
    const float* __restrict__ qkv, const int* __restrict__ routes,
    const float* __restrict__ logw, __half* __restrict__ attn)
{
    int id = blockIdx.x;
    int hg = id % 3;
    int bp = id / 3;
    int p = bp % PP;
    int b = bp / PP;
    const float* base = qkv + (long)b*SS*3*DD;
    int tid = threadIdx.x;
    int sub = tid >> 6;
    int t64 = tid & 63;
    int h = hg*4 + sub;

    __shared__ float qs[4][HDIM];
    __shared__ int   sr[KWIN];
    __shared__ float slw[KWIN];
    __shared__ float sa[4][KWIN];
    __shared__ float part[4][2][KWIN];

    qs[sub][t64] = base[(long)(p+1)*3*DD + h*HDIM + t64];
    if (tid < KWIN)                 sr[tid]      = routes[((long)bp)*KWIN + tid];
    else if (tid >= 32 && tid < 64) slw[tid-32]  = logw[((long)bp)*KWIN + tid-32];
    __syncthreads();

    int k = t64 & 31, half_ = t64 >> 5;
    const float* kr = base + (long)(sr[k]+1)*3*DD + DD + h*HDIM + half_*32;
    float dot = 0.f;
    #pragma unroll
    for (int d = 0; d < 32; d++) dot = fmaf(qs[sub][half_*32+d], kr[d], dot);
    part[sub][half_][k] = dot;
    __syncthreads();

    if (t64 < KWIN) {
        float s = (part[sub][0][k]+part[sub][1][k]) * SCALE_ATT + slw[k];
        float m = s;
        #pragma unroll
        for (int o = 16; o > 0; o >>= 1) m = fmaxf(m, __shfl_xor_sync(0xffffffffu, m, o));
        float e = expf(s-m);
        float z = e;
        #pragma unroll
        for (int o = 16; o > 0; o >>= 1) z += __shfl_xor_sync(0xffffffffu, z, o);
        sa[sub][k] = e / z;
    }
    __syncthreads();

    float acc = 0.f;
    #pragma unroll 8
    for (int kk = 0; kk < KWIN; kk++)
        acc = fmaf(sa[sub][kk], base[(long)(sr[kk]+1)*3*DD + 2*DD + h*HDIM + t64], acc);
    attn[((long)b*SS + p+1)*DD + h*HDIM + t64] = __float2half(acc);
}

// ---------------- launcher ----------------
extern "C" void kernel_launch(void* const* d_in, const int* in_sizes, int n_in,
                              void* d_out, int out_size)
{
    const float* x      = (const float*)d_in[0];
    const float* g1     = (const float*)d_in[1];
    const float* b1     = (const float*)d_in[2];
    const float* wq     = (const float*)d_in[3];
    const float* bq     = (const float*)d_in[4];
    const float* wk     = (const float*)d_in[5];
    const float* bk     = (const float*)d_in[6];
    const float* posb   = (const float*)d_in[7];
    const float* w_qkv  = (const float*)d_in[8];
    const float* b_qkv  = (const float*)d_in[9];
    const float* w_proj = (const float*)d_in[10];
    const float* b_proj = (const float*)d_in[11];
    const float* g2     = (const float*)d_in[12];
    const float* b2     = (const float*)d_in[13];
    const float* w_mlp1 = (const float*)d_in[14];
    const float* b_mlp1 = (const float*)d_in[15];
    const float* w_mlp2 = (const float*)d_in[16];
    const float* b_mlp2 = (const float*)d_in[17];
    float* out = (float*)d_out;

    float *qk, *scores, *logw, *qkvb, *x1, *bqk;
    __half *xnh, *xnl, *qh, *ql, *kh, *kl, *attn, *xn2, *hbuf;
    __half *rqkv, *rproj, *rm1, *rm2, *wqkh, *wqkl;
    int *routes;
    cudaGetSymbolAddress((void**)&xnh,    g_xnh);
    cudaGetSymbolAddress((void**)&xnl,    g_xnl);
    cudaGetSymbolAddress((void**)&qk,     g_qk);
    cudaGetSymbolAddress((void**)&qh,     g_qh);
    cudaGetSymbolAddress((void**)&ql,     g_ql);
    cudaGetSymbolAddress((void**)&kh,     g_kh);
    cudaGetSymbolAddress((void**)&kl,     g_kl);
    cudaGetSymbolAddress((void**)&scores, g_scores);
    cudaGetSymbolAddress((void**)&routes, g_routes);
    cudaGetSymbolAddress((void**)&logw,   g_logw);
    cudaGetSymbolAddress((void**)&qkvb,   g_qkv);
    cudaGetSymbolAddress((void**)&attn,   g_attn);
    cudaGetSymbolAddress((void**)&x1,     g_x1);
    cudaGetSymbolAddress((void**)&xn2,    g_xn2);
    cudaGetSymbolAddress((void**)&hbuf,   g_h);
    cudaGetSymbolAddress((void**)&rqkv,   g_rqkv);
    cudaGetSymbolAddress((void**)&rproj,  g_rproj);
    cudaGetSymbolAddress((void**)&rm1,    g_rm1);
    cudaGetSymbolAddress((void**)&rm2,    g_rm2);
    cudaGetSymbolAddress((void**)&wqkh,   g_wqkh);
    cudaGetSymbolAddress((void**)&wqkl,   g_wqkl);
    cudaGetSymbolAddress((void**)&bqk,    g_bqk);

    // 0. weight prep
    pack_all_kernel<<<PK_BLKS, 256>>>(w_qkv, rqkv, w_proj, rproj,
                                      w_mlp1, rm1, w_mlp2, rm2);
    pack_qk_kernel<<<PKQK_W_B + 1, 256>>>(wq, wk, bq, bk, wqkh, wqkl, bqk);

    // 1. LN1 -> hi + lo fp16
    ln_kernel<<<NROWS, 256>>>(x, g1, b1, xnh, xnl);

    // 2. FUSED: q||k routing proj (3-MMA, slow blocks first) + QKV (fp16 HMMA)
    fused_qkv_qkproj_kernel<<<QKV_BLKS + QK2_BLKS, 256>>>(
        xnh, xnl, rqkv, b_qkv, qkvb, wqkh, wqkl, bqk, qk);

    // 3. l2 normalize + split q,k into hi/lo fp16
    l2norm_split_kernel<<<2*BB*PP, 256>>>(qk, qh, ql, kh, kl);

    // 4. FUSED: routing scores (double-fp16 TN) + CLS attention
    fused_scores_cls_kernel<<<SC_BLKS + BB*HH, 256>>>(
        qh, ql, kh, kl, scores, posb, qkvb, attn);

    // 5. top-32 + log-softmax weights (warp per row)
    topk_warp_kernel<<<BB*PP/8, 256>>>(scores, routes, logw);

    // 6. patch attention (4 heads per block)
    patch_attn_kernel<<<BB*PP*3, 256>>>(qkvb, routes, logw, attn);

    // 7. proj + residual x (fp16 HMMA TBM=64, 3 CTA/SM)
    {
        dim3 grid(DD/TBN, (NROWS+63)/64);
        hmma64_nn_kernel<2><<<grid, 256>>>(attn, rproj, x1, NROWS, DD, DD, DD,
                                           b_proj, x);
    }
    // 8. LN2 (fp16 hi only, feeds MLP1)
    ln_kernel<<<NROWS, 256>>>(x1, g2, b2, xn2, nullptr);

    // 9. MLP1 + exact GELU (fp16 HMMA TBM=64)
    {
        dim3 grid(MLPD/TBN, (NROWS+63)/64);
        hmma64_nn_kernel<3><<<grid, 256>>>(xn2, rm1, hbuf, NROWS, MLPD, DD, DD,
                                           b_mlp1, nullptr);
    }
    // 10. MLP2 + residual x1 -> out (fp16 HMMA TBM=64)
    {
        dim3 grid(DD/TBN, (NROWS+63)/64);
        hmma64_nn_kernel<2><<<grid, 256>>>(hbuf, rm2, out, NROWS, DD, MLPD, MLPD,
                                           b_mlp2, x1);
    }
}

// round 17
// speedup vs baseline: 1.1055x; 1.0187x over previous
#include <cuda_runtime.h>
#include <cuda_fp16.h>
#include <math.h>
#include <stdint.h>

// ---------------- problem constants ----------------
#define BB   8
#define SS   577
#define DD   768
#define HH   12
#define HDIM 64
#define PP   576
#define KWIN 32
#define MLPD 3072
#define NROWS (BB*SS)        // 4616
#define SCALE_ATT 0.125f
#define TEMP_INV  10.0f

#define TBM 128
#define TBN 128
#define TBK 32
#define W20  20
#define W136 136

__device__ __forceinline__ void cp16(void* dst_smem, const void* src, int srcsize) {
    uint32_t d = (uint32_t)__cvta_generic_to_shared(dst_smem);
    asm volatile("cp.async.cg.shared.global [%0], [%1], 16, %2;"
                 :: "r"(d), "l"(src), "r"(srcsize));
}
__device__ __forceinline__ void mma_f16(float* d, const uint32_t* a, const uint32_t* b) {
    asm volatile(
        "mma.sync.aligned.m16n8k16.row.col.f32.f16.f16.f32 "
        "{%0,%1,%2,%3}, {%4,%5,%6,%7}, {%8,%9}, {%0,%1,%2,%3};"
        : "+f"(d[0]), "+f"(d[1]), "+f"(d[2]), "+f"(d[3])
        : "r"(a[0]), "r"(a[1]), "r"(a[2]), "r"(a[3]), "r"(b[0]), "r"(b[1]));
}
__device__ __forceinline__ void ldsm_x4(uint32_t* r, const void* smem_ptr) {
    uint32_t a = (uint32_t)__cvta_generic_to_shared(smem_ptr);
    asm volatile("ldmatrix.sync.aligned.m8n8.x4.shared.b16 {%0,%1,%2,%3}, [%4];"
                 : "=r"(r[0]), "=r"(r[1]), "=r"(r[2]), "=r"(r[3]) : "r"(a));
}
__device__ __forceinline__ void ldsm_x2(uint32_t* r, const void* smem_ptr) {
    uint32_t a = (uint32_t)__cvta_generic_to_shared(smem_ptr);
    asm volatile("ldmatrix.sync.aligned.m8n8.x2.shared.b16 {%0,%1}, [%2];"
                 : "=r"(r[0]), "=r"(r[1]) : "r"(a));
}
__device__ __forceinline__ void split1(float v, __half& h, __half& l) {
    h = __float2half(v);
    l = __float2half(v - __half2float(h));
}

// ---------------- scratch (device globals) ----------------
__device__ __half g_xnh  [(size_t)BB*SS*DD];
__device__ __half g_xnl  [(size_t)BB*SS*DD];
__device__ float  g_qk   [(size_t)BB*PP*2*DD];
__device__ __half g_qh   [(size_t)BB*PP*DD];
__device__ __half g_ql   [(size_t)BB*PP*DD];
__device__ __half g_kh   [(size_t)BB*PP*DD];
__device__ __half g_kl   [(size_t)BB*PP*DD];
__device__ float  g_scores[(size_t)BB*PP*PP];
__device__ int    g_routes[(size_t)BB*PP*KWIN];
__device__ float  g_logw  [(size_t)BB*PP*KWIN];
__device__ __half g_qkvh [(size_t)BB*SS*3*DD];   // fp16 QKV
__device__ __half g_attn [(size_t)BB*SS*DD];
__device__ float  g_x1   [(size_t)BB*SS*DD];
__device__ __half g_xn2  [(size_t)BB*SS*DD];
__device__ __half g_h    [(size_t)BB*SS*MLPD];
__device__ __half g_rqkv [(size_t)DD*3*DD];
__device__ __half g_rproj[(size_t)DD*DD];
__device__ __half g_rm1  [(size_t)DD*MLPD];
__device__ __half g_rm2  [(size_t)MLPD*DD];
__device__ __half g_wqkh [(size_t)DD*2*DD];
__device__ __half g_wqkl [(size_t)DD*2*DD];
__device__ float  g_bqk  [(size_t)2*DD];

// ---------------- merged weight prep (all packs in one launch) ------------
#define PK_QKV_B  (DD*3*DD/2048)
#define PK_PROJ_B (DD*DD/2048)
#define PK_M1_B   (DD*MLPD/2048)
#define PK_M2_B   (MLPD*DD/2048)
#define PK_BLKS   (PK_QKV_B+PK_PROJ_B+PK_M1_B+PK_M2_B)
#define PKQK_W_B  ((DD/2)*(2*DD)/1024)   // 576
#define PK_ALL    (PK_BLKS + PKQK_W_B + 1)

__global__ __launch_bounds__(256) void pack_combined_kernel(
    const float* __restrict__ wqkv, __half* __restrict__ rqkv,
    const float* __restrict__ wproj, __half* __restrict__ rproj,
    const float* __restrict__ wm1, __half* __restrict__ rm1,
    const float* __restrict__ wm2, __half* __restrict__ rm2,
    const float* __restrict__ wq, const float* __restrict__ wk,
    const float* __restrict__ bq, const float* __restrict__ bk,
    __half* __restrict__ wh, __half* __restrict__ wl, float* __restrict__ bqk)
{
    int bx = blockIdx.x;
    if (bx < PK_BLKS) {
        const float* src; __half* dst; int N; long base;
        if (bx < PK_QKV_B)                       { src = wqkv;  dst = rqkv;  N = 3*DD; base = bx; }
        else if (bx < PK_QKV_B+PK_PROJ_B)        { src = wproj; dst = rproj; N = DD;   base = bx-PK_QKV_B; }
        else if (bx < PK_QKV_B+PK_PROJ_B+PK_M1_B){ src = wm1;   dst = rm1;   N = MLPD; base = bx-PK_QKV_B-PK_PROJ_B; }
        else                                     { src = wm2;   dst = rm2;   N = DD;   base = bx-PK_QKV_B-PK_PROJ_B-PK_M1_B; }
        long id = base*256 + threadIdx.x;
        int npg = N/4;
        long k2 = id / npg;
        int  n  = (int)(id % npg) * 4;
        float4 e = *reinterpret_cast<const float4*>(src + (2*k2  )*N + n);
        float4 o = *reinterpret_cast<const float4*>(src + (2*k2+1)*N + n);
        __half2 out[4];
        out[0] = __floats2half2_rn(e.x, o.x);
        out[1] = __floats2half2_rn(e.y, o.y);
        out[2] = __floats2half2_rn(e.z, o.z);
        out[3] = __floats2half2_rn(e.w, o.w);
        *reinterpret_cast<uint4*>(dst + (k2*N + n)*2) = *reinterpret_cast<uint4*>(out);
        return;
    }
    int qx = bx - PK_BLKS;
    if (qx == PKQK_W_B) {
        for (int i = threadIdx.x; i < 2*DD; i += 256)
            bqk[i] = (i < DD) ? bq[i] : bk[i - DD];
        return;
    }
    const int N2 = 2*DD;
    long id = (long)qx*256 + threadIdx.x;
    long k2 = id / (N2/4);
    int  n  = (int)(id % (N2/4)) * 4;
    const float* src = (n < DD) ? wq : wk;
    int nn = (n < DD) ? n : n - DD;
    float4 e = *reinterpret_cast<const float4*>(src + (2*k2  )*DD + nn);
    float4 o = *reinterpret_cast<const float4*>(src + (2*k2+1)*DD + nn);
    __half2 oh[4], ol[4];
    #pragma unroll
    for (int u = 0; u < 4; u++) {
        float ev = (&e.x)[u], ov = (&o.x)[u];
        __half eh, el, ohh, oll;
        split1(ev, eh, el); split1(ov, ohh, oll);
        oh[u] = __halves2half2(eh, ohh);
        ol[u] = __halves2half2(el, oll);
    }
    *reinterpret_cast<uint4*>(wh + (k2*N2 + n)*2) = *reinterpret_cast<uint4*>(oh);
    *reinterpret_cast<uint4*>(wl + (k2*N2 + n)*2) = *reinterpret_cast<uint4*>(ol);
}

// ---------------- LayerNorm: fp16 hi out + optional fp16 lo out ------------
__global__ __launch_bounds__(256) void ln_kernel(
    const float* __restrict__ x, const float* __restrict__ g,
    const float* __restrict__ b, __half* __restrict__ yh,
    __half* __restrict__ yl)
{
    int row = blockIdx.x;
    const float* xr = x + (long)row*DD;
    float s = 0.f, sq = 0.f;
    for (int d = threadIdx.x; d < DD; d += 256) {
        float v = xr[d]; s += v; sq += v*v;
    }
    __shared__ float rs[256], rq[256];
    rs[threadIdx.x] = s; rq[threadIdx.x] = sq;
    __syncthreads();
    for (int o = 128; o > 0; o >>= 1) {
        if (threadIdx.x < o) { rs[threadIdx.x] += rs[threadIdx.x+o]; rq[threadIdx.x] += rq[threadIdx.x+o]; }
        __syncthreads();
    }
    __shared__ float mean_s, rstd_s;
    if (threadIdx.x == 0) {
        float mean = rs[0] / (float)DD;
        float var  = rq[0] / (float)DD - mean*mean;
        mean_s = mean;
        rstd_s = rsqrtf(var + 1e-5f);
    }
    __syncthreads();
    float mean = mean_s, rstd = rstd_s;
    __half* yhb = yh + (long)row*DD;
    __half* ylb = yl ? (yl + (long)row*DD) : nullptr;
    for (int d = threadIdx.x; d < DD; d += 256) {
        float v = (xr[d]-mean)*rstd*g[d] + b[d];
        __half h = __float2half(v);
        yhb[d] = h;
        if (ylb) ylb[d] = __float2half(v - __half2float(h));
    }
}

// ---------------- L2 normalize: one block does q+k of one row --------------
__global__ __launch_bounds__(256) void l2norm_split_kernel(
    const float* __restrict__ qk,
    __half* __restrict__ qh, __half* __restrict__ ql,
    __half* __restrict__ kh, __half* __restrict__ kl)
{
    int r = blockIdx.x;
    __shared__ float rq[256];
    __shared__ float inv_s;
    #pragma unroll
    for (int which = 0; which < 2; which++) {
        const float* xr = qk + (long)r*(2*DD) + which*DD;
        float sq = 0.f;
        for (int d = threadIdx.x; d < DD; d += 256) { float v = xr[d]; sq += v*v; }
        rq[threadIdx.x] = sq;
        __syncthreads();
        for (int o = 128; o > 0; o >>= 1) {
            if (threadIdx.x < o) rq[threadIdx.x] += rq[threadIdx.x+o];
            __syncthreads();
        }
        if (threadIdx.x == 0) inv_s = 1.0f / fmaxf(sqrtf(rq[0]), 1e-12f);
        __syncthreads();
        float inv = inv_s;
        __half* oh = (which ? kh : qh) + (long)r*DD;
        __half* ol = (which ? kl : ql) + (long)r*DD;
        for (int d = threadIdx.x; d < DD; d += 256) {
            float v = xr[d]*inv;
            __half h = __float2half(v);
            oh[d] = h;
            ol[d] = __float2half(v - __half2float(h));
        }
        __syncthreads();
    }
}

// ---------------- fp16 HMMA body: TBM=128, TBK=32, 3-stage (fused QKV) -----
// EPI: 1 = +bias (fp16 C) ; 2 = +bias+resid (fp32 C) ; 3 = +bias+GELU (fp16 C)
template<int EPI>
__device__ __forceinline__ void hmma_body(
    uint32_t (*As)[TBM][W20], uint32_t (*Bs)[16][W136],
    const __half* __restrict__ A, const __half* __restrict__ B2,
    void* __restrict__ Cv, int M, int N, int K, int lda,
    const float* __restrict__ bias, const float* __restrict__ resid,
    int bm, int bn)
{
    int tid  = threadIdx.x;
    int wid  = tid >> 5, lane = tid & 31;
    int wr   = wid & 1;
    int wc   = wid >> 1;
    int g    = lane >> 2;
    int t    = lane & 3;
    int rsel = (lane & 7) + ((lane >> 3) & 1)*8;
    int wsel = (lane >> 4)*4;

    float acc[4][4][4];
    #pragma unroll
    for (int i = 0; i < 4; i++)
        #pragma unroll
        for (int j = 0; j < 4; j++)
            #pragma unroll
            for (int r = 0; r < 4; r++) acc[i][j][r] = 0.f;

    auto load_stage = [&](int buf, int k0) {
        #pragma unroll
        for (int i = 0; i < 2; i++) {
            int id = i*256 + tid;
            int row = id >> 2, c = id & 3;
            int m = bm + row;
            cp16(&As[buf][row][c*4], A + (long)m*lda + k0 + c*8, m < M ? 16 : 0);
        }
        #pragma unroll
        for (int i = 0; i < 2; i++) {
            int id = i*256 + tid;
            int row = id >> 5, c = id & 31;
            cp16(&Bs[buf][row][c*4],
                 B2 + ((long)((k0>>1) + row)*N + bn + c*4)*2, 16);
        }
        asm volatile("cp.async.commit_group;");
    };

    int KT = K >> 5;
    load_stage(0, 0);
    load_stage(1, TBK);
    for (int kt = 0; kt < KT; kt++) {
        if (kt + 2 < KT) asm volatile("cp.async.wait_group 1;");
        else             asm volatile("cp.async.wait_group 0;");
        __syncthreads();
        if (kt + 2 < KT) load_stage((kt+2)%3, (kt+2)*TBK);
        int buf = kt % 3;

        #pragma unroll
        for (int ka = 0; ka < 2; ka++) {
            int kw = ka*8;
            uint32_t afrag[4][4];
            #pragma unroll
            for (int ma = 0; ma < 4; ma++)
                ldsm_x4(afrag[ma], &As[buf][wr*64 + ma*16 + rsel][kw + wsel]);
            uint32_t bfrag[4][2];
            #pragma unroll
            for (int na = 0; na < 4; na++) {
                int c = wc*32 + na*8 + g;
                bfrag[na][0] = Bs[buf][kw + t    ][c];
                bfrag[na][1] = Bs[buf][kw + t + 4][c];
            }
            #pragma unroll
            for (int ma = 0; ma < 4; ma++)
                #pragma unroll
                for (int na = 0; na < 4; na++)
                    mma_f16(acc[ma][na], afrag[ma], bfrag[na]);
        }
    }

    #pragma unroll
    for (int ma = 0; ma < 4; ma++) {
        int row0 = bm + wr*64 + ma*16 + g;
        #pragma unroll
        for (int na = 0; na < 4; na++) {
            int col = bn + wc*32 + na*8 + 2*t;
            float b0 = bias[col], b1 = bias[col+1];
            #pragma unroll
            for (int hh = 0; hh < 2; hh++) {
                int row = row0 + hh*8;
                if (row >= M) continue;
                float v0 = acc[ma][na][hh*2+0] + b0;
                float v1 = acc[ma][na][hh*2+1] + b1;
                if (EPI == 1) {
                    *reinterpret_cast<__half2*>((__half*)Cv + (long)row*N + col) =
                        __floats2half2_rn(v0, v1);
                } else if (EPI == 3) {
                    v0 = 0.5f*v0*(1.0f + erff(v0*0.7071067811865475f));
                    v1 = 0.5f*v1*(1.0f + erff(v1*0.7071067811865475f));
                    *reinterpret_cast<__half2*>((__half*)Cv + (long)row*N + col) =
                        __floats2half2_rn(v0, v1);
                } else {
                    if (EPI == 2) {
                        v0 += resid[(long)row*N + col];
                        v1 += resid[(long)row*N + col + 1];
                    }
                    *reinterpret_cast<float2*>((float*)Cv + (long)row*N + col) =
                        make_float2(v0, v1);
                }
            }
        }
    }
}

// ---------------- fp16 HMMA body: TBM=64, 4-stage (3 CTAs/SM) --------------
struct __align__(16) Smem64 {
    uint32_t As[4][64][W20];     // 20480 B
    uint32_t Bs[4][16][W136];    // 34816 B  -> 55296 B total
};

template<int EPI>
__global__ __launch_bounds__(256, 3) void hmma64_nn_kernel(
    const __half* __restrict__ A, const __half* __restrict__ B2,
    void* __restrict__ Cv, int M, int N, int K, int lda,
    const float* __restrict__ bias, const float* __restrict__ resid)
{
    __shared__ Smem64 sm;
    int tid  = threadIdx.x;
    int wid  = tid >> 5, lane = tid & 31;
    int wr   = wid & 1;
    int wc   = wid >> 1;
    int g    = lane >> 2;
    int t    = lane & 3;
    int rsel = (lane & 7) + ((lane >> 3) & 1)*8;
    int wsel = (lane >> 4)*4;
    int bm   = blockIdx.y*64;
    int bn   = blockIdx.x*TBN;

    float acc[2][4][4];
    #pragma unroll
    for (int i = 0; i < 2; i++)
        #pragma unroll
        for (int j = 0; j < 4; j++)
            #pragma unroll
            for (int r = 0; r < 4; r++) acc[i][j][r] = 0.f;

    auto load_stage = [&](int buf, int k0) {
        {
            int row = tid >> 2, c = tid & 3;
            int m = bm + row;
            cp16(&sm.As[buf][row][c*4], A + (long)m*lda + k0 + c*8, m < M ? 16 : 0);
        }
        #pragma unroll
        for (int i = 0; i < 2; i++) {
            int id = i*256 + tid;
            int row = id >> 5, c = id & 31;
            cp16(&sm.Bs[buf][row][c*4],
                 B2 + ((long)((k0>>1) + row)*N + bn + c*4)*2, 16);
        }
        asm volatile("cp.async.commit_group;");
    };

    int KT = K >> 5;
    load_stage(0, 0);
    load_stage(1, TBK);
    load_stage(2, 2*TBK);
    for (int kt = 0; kt < KT; kt++) {
        if (kt + 3 < KT) asm volatile("cp.async.wait_group 2;");
        else             asm volatile("cp.async.wait_group 0;");
        __syncthreads();
        if (kt + 3 < KT) load_stage((kt+3)&3, (kt+3)*TBK);
        int buf = kt & 3;

        #pragma unroll
        for (int ka = 0; ka < 2; ka++) {
            int kw = ka*8;
            uint32_t afrag[2][4];
            #pragma unroll
            for (int ma = 0; ma < 2; ma++)
                ldsm_x4(afrag[ma], &sm.As[buf][wr*32 + ma*16 + rsel][kw + wsel]);
            uint32_t bfrag[4][2];
            #pragma unroll
            for (int na = 0; na < 4; na++) {
                int c = wc*32 + na*8 + g;
                bfrag[na][0] = sm.Bs[buf][kw + t    ][c];
                bfrag[na][1] = sm.Bs[buf][kw + t + 4][c];
            }
            #pragma unroll
            for (int ma = 0; ma < 2; ma++)
                #pragma unroll
                for (int na = 0; na < 4; na++)
                    mma_f16(acc[ma][na], afrag[ma], bfrag[na]);
        }
    }

    #pragma unroll
    for (int ma = 0; ma < 2; ma++) {
        int row0 = bm + wr*32 + ma*16 + g;
        #pragma unroll
        for (int na = 0; na < 4; na++) {
            int col = bn + wc*32 + na*8 + 2*t;
            float b0 = bias[col], b1 = bias[col+1];
            #pragma unroll
            for (int hh = 0; hh < 2; hh++) {
                int row = row0 + hh*8;
                if (row >= M) continue;
                float v0 = acc[ma][na][hh*2+0] + b0;
                float v1 = acc[ma][na][hh*2+1] + b1;
                if (EPI == 3) {
                    v0 = 0.5f*v0*(1.0f + erff(v0*0.7071067811865475f));
                    v1 = 0.5f*v1*(1.0f + erff(v1*0.7071067811865475f));
                    *reinterpret_cast<__half2*>((__half*)Cv + (long)row*N + col) =
                        __floats2half2_rn(v0, v1);
                } else {
                    if (EPI == 2) {
                        v0 += resid[(long)row*N + col];
                        v1 += resid[(long)row*N + col + 1];
                    }
                    *reinterpret_cast<float2*>((float*)Cv + (long)row*N + col) =
                        make_float2(v0, v1);
                }
            }
        }
    }
}

// ---------------- double-fp16 (3-MMA) NN body, ldmatrix A ------------------
__device__ __forceinline__ void hmma3_nn_body(
    uint32_t (*Ah)[TBM][W20], uint32_t (*Al)[TBM][W20],
    uint32_t (*Bh)[16][W136], uint32_t (*Bl)[16][W136],
    const __half* __restrict__ Axh, const __half* __restrict__ Axl,
    const __half* __restrict__ Bwh, const __half* __restrict__ Bwl,
    float* __restrict__ C, int M, int N, int K, int lda, int ldc,
    const float* __restrict__ bias, int bm, int bn)
{
    int tid = threadIdx.x, wid = tid >> 5, lane = tid & 31;
    int wr = wid & 1, wc = wid >> 1, g = lane >> 2, t = lane & 3;
    int rsel = (lane & 7) + ((lane >> 3) & 1)*8;
    int wsel = (lane >> 4)*4;

    float acc[4][4][4];
    #pragma unroll
    for (int i = 0; i < 4; i++)
        #pragma unroll
        for (int j = 0; j < 4; j++)
            #pragma unroll
            for (int r = 0; r < 4; r++) acc[i][j][r] = 0.f;

    auto load_stage = [&](int buf, int k0) {
        #pragma unroll
        for (int i = 0; i < 2; i++) {
            int id = i*256 + tid;
            int row = id >> 2, c = id & 3;
            int m = bm + row;
            cp16(&Ah[buf][row][c*4], Axh + (long)m*lda + k0 + c*8, m < M ? 16 : 0);
            cp16(&Al[buf][row][c*4], Axl + (long)m*lda + k0 + c*8, m < M ? 16 : 0);
        }
        #pragma unroll
        for (int i = 0; i < 2; i++) {
            int id = i*256 + tid;
            int row = id >> 5, c = id & 31;
            long off = ((long)((k0>>1) + row)*N + bn + c*4)*2;
            cp16(&Bh[buf][row][c*4], Bwh + off, 16);
            cp16(&Bl[buf][row][c*4], Bwl + off, 16);
        }
        asm volatile("cp.async.commit_group;");
    };

    int KT = K >> 5;
    load_stage(0, 0);
    for (int kt = 0; kt < KT; kt++) {
        asm volatile("cp.async.wait_group 0;");
        __syncthreads();
        if (kt + 1 < KT) load_stage((kt+1)&1, (kt+1)*TBK);
        int buf = kt & 1;

        #pragma unroll
        for (int ka = 0; ka < 2; ka++) {
            int kw = ka*8;
            uint32_t bh[4][2], bl[4][2];
            #pragma unroll
            for (int na = 0; na < 4; na++) {
                int c = wc*32 + na*8 + g;
                bh[na][0] = Bh[buf][kw + t][c];  bh[na][1] = Bh[buf][kw + t + 4][c];
                bl[na][0] = Bl[buf][kw + t][c];  bl[na][1] = Bl[buf][kw + t + 4][c];
            }
            #pragma unroll
            for (int ma = 0; ma < 4; ma++) {
                uint32_t ah[4], al[4];
                ldsm_x4(ah, &Ah[buf][wr*64 + ma*16 + rsel][kw + wsel]);
                ldsm_x4(al, &Al[buf][wr*64 + ma*16 + rsel][kw + wsel]);
                #pragma unroll
                for (int na = 0; na < 4; na++) {
                    mma_f16(acc[ma][na], ah, bh[na]);
                    mma_f16(acc[ma][na], ah, bl[na]);
                    mma_f16(acc[ma][na], al, bh[na]);
                }
            }
        }
    }

    #pragma unroll
    for (int ma = 0; ma < 4; ma++) {
        int row0 = bm + wr*64 + ma*16 + g;
        #pragma unroll
        for (int na = 0; na < 4; na++) {
            int col = bn + wc*32 + na*8 + 2*t;
            float b0 = bias[col], b1 = bias[col+1];
            #pragma unroll
            for (int hh = 0; hh < 2; hh++) {
                int row = row0 + hh*8;
                if (row >= M) continue;
                *reinterpret_cast<float2*>(C + (long)row*ldc + col) =
                    make_float2(acc[ma][na][hh*2+0] + b0, acc[ma][na][hh*2+1] + b1);
            }
        }
    }
}

// ---------------- double-fp16 (3-MMA) TN body, ldmatrix A+B ----------------
__device__ __forceinline__ void hmma3_tn_body(
    uint32_t (*Ah)[TBM][W20], uint32_t (*Al)[TBM][W20],
    uint32_t (*Bh)[TBM][W20], uint32_t (*Bl)[TBM][W20],
    const __half* __restrict__ Axh, const __half* __restrict__ Axl,
    const __half* __restrict__ Bxh, const __half* __restrict__ Bxl,
    float* __restrict__ C, int M, int N, int K,
    const float* __restrict__ posb, int bm, int bn)
{
    int tid = threadIdx.x, wid = tid >> 5, lane = tid & 31;
    int wr = wid & 1, wc = wid >> 1, g = lane >> 2, t = lane & 3;
    int rsel  = (lane & 7) + ((lane >> 3) & 1)*8;
    int wsel  = (lane >> 4)*4;
    int rsel2 = lane & 7;
    int wsel2 = ((lane >> 3) & 1)*4;

    float acc[4][4][4];
    #pragma unroll
    for (int i = 0; i < 4; i++)
        #pragma unroll
        for (int j = 0; j < 4; j++)
            #pragma unroll
            for (int r = 0; r < 4; r++) acc[i][j][r] = 0.f;

    auto load_stage = [&](int buf, int k0) {
        #pragma unroll
        for (int i = 0; i < 2; i++) {
            int id = i*256 + tid;
            int row = id >> 2, c = id & 3;
            int m = bm + row;
            cp16(&Ah[buf][row][c*4], Axh + (long)m*K + k0 + c*8, m < M ? 16 : 0);
            cp16(&Al[buf][row][c*4], Axl + (long)m*K + k0 + c*8, m < M ? 16 : 0);
        }
        #pragma unroll
        for (int i = 0; i < 2; i++) {
            int id = i*256 + tid;
            int row = id >> 2, c = id & 3;
            int n = bn + row;
            cp16(&Bh[buf][row][c*4], Bxh + (long)n*K + k0 + c*8, n < N ? 16 : 0);
            cp16(&Bl[buf][row][c*4], Bxl + (long)n*K + k0 + c*8, n < N ? 16 : 0);
        }
        asm volatile("cp.async.commit_group;");
    };

    int KT = K >> 5;
    load_stage(0, 0);
    for (int kt = 0; kt < KT; kt++) {
        asm volatile("cp.async.wait_group 0;");
        __syncthreads();
        if (kt + 1 < KT) load_stage((kt+1)&1, (kt+1)*TBK);
        int buf = kt & 1;

        #pragma unroll
        for (int ka = 0; ka < 2; ka++) {
            int kw = ka*8;
            uint32_t bh[4][2], bl[4][2];
            #pragma unroll
            for (int na = 0; na < 4; na++) {
                ldsm_x2(bh[na], &Bh[buf][wc*32 + na*8 + rsel2][kw + wsel2]);
                ldsm_x2(bl[na], &Bl[buf][wc*32 + na*8 + rsel2][kw + wsel2]);
            }
            #pragma unroll
            for (int ma = 0; ma < 4; ma++) {
                uint32_t ah[4], al[4];
                ldsm_x4(ah, &Ah[buf][wr*64 + ma*16 + rsel][kw + wsel]);
                ldsm_x4(al, &Al[buf][wr*64 + ma*16 + rsel][kw + wsel]);
                #pragma unroll
                for (int na = 0; na < 4; na++) {
                    mma_f16(acc[ma][na], ah, bh[na]);
                    mma_f16(acc[ma][na], ah, bl[na]);
                    mma_f16(acc[ma][na], al, bh[na]);
                }
            }
        }
    }

    #pragma unroll
    for (int ma = 0; ma < 4; ma++) {
        int row0 = bm + wr*64 + ma*16 + g;
        #pragma unroll
        for (int na = 0; na < 4; na++) {
            int col = bn + wc*32 + na*8 + 2*t;
            if (col >= N) continue;
            #pragma unroll
            for (int hh = 0; hh < 2; hh++) {
                int row = row0 + hh*8;
                if (row >= M) continue;
                float v0 = acc[ma][na][hh*2+0] + posb[(long)row*N + col];
                float v1 = acc[ma][na][hh*2+1] + posb[(long)row*N + col + 1];
                if (row == col)   v0 = -1e9f;
                if (row == col+1) v1 = -1e9f;
                *reinterpret_cast<float2*>(C + (long)row*N + col) =
                    make_float2(v0*TEMP_INV, v1*TEMP_INV);
            }
        }
    }
}

// ---------------- shared-memory aggregates (16B aligned) -------------------
union __align__(16) Smem1 {
    struct { uint32_t As[3][TBM][W20]; uint32_t Bs[3][16][W136]; } h;
    struct { uint32_t Ah[2][TBM][W20]; uint32_t Al[2][TBM][W20];
             uint32_t Bh[2][16][W136]; uint32_t Bl[2][16][W136]; } h3;
};
struct __align__(16) Smem2 {
    uint32_t Ah[2][TBM][W20]; uint32_t Al[2][TBM][W20];
    uint32_t Bh[2][TBM][W20]; uint32_t Bl[2][TBM][W20];
};

// ---------------- CLS attention body (fp16 qkv) ----------------
__device__ void cls_attn_body(const __half* __restrict__ qkv,
                              __half* __restrict__ attn, int blk)
{
    int b = blk / HH, h = blk % HH;
    const __half* base = qkv + (long)b*SS*3*DD;
    int tid = threadIdx.x;
    __shared__ float qv[HDIM];
    __shared__ float sc[SS];
    __shared__ float red[256];
    __shared__ float m_s, z_s;
    if (tid < HDIM) qv[tid] = __half2float(base[h*HDIM + tid]);
    __syncthreads();

    float lmax = -INFINITY;
    for (int k = tid; k < SS; k += 256) {
        const __half* kr = base + (long)k*3*DD + DD + h*HDIM;
        float dot = 0.f;
        #pragma unroll
        for (int d = 0; d < HDIM; d++) dot = fmaf(qv[d], __half2float(kr[d]), dot);
        float s = dot * SCALE_ATT;
        sc[k] = s;
        lmax = fmaxf(lmax, s);
    }
    red[tid] = lmax;
    __syncthreads();
    for (int o = 128; o > 0; o >>= 1) {
        if (tid < o) red[tid] = fmaxf(red[tid], red[tid+o]);
        __syncthreads();
    }
    if (tid == 0) m_s = red[0];
    __syncthreads();
    float m = m_s, lsum = 0.f;
    for (int k = tid; k < SS; k += 256) {
        float e = expf(sc[k]-m); sc[k] = e; lsum += e;
    }
    red[tid] = lsum;
    __syncthreads();
    for (int o = 128; o > 0; o >>= 1) {
        if (tid < o) red[tid] += red[tid+o];
        __syncthreads();
    }
    if (tid == 0) z_s = red[0];
    __syncthreads();
    float zinv = 1.0f / z_s;

    int d = tid & 63, part = tid >> 6;
    float acc = 0.f;
    for (int k = part; k < SS; k += 4)
        acc = fmaf(sc[k], __half2float(base[(long)k*3*DD + 2*DD + h*HDIM + d]), acc);
    __shared__ float ro[4][HDIM];
    ro[part][d] = acc;
    __syncthreads();
    if (tid < HDIM)
        attn[((long)b*SS)*DD + h*HDIM + tid] =
            __float2half((ro[0][tid]+ro[1][tid]+ro[2][tid]+ro[3][tid]) * zinv);
}

// ---------------- fused: routing scores (hmma3 TN) + CLS attention ---------
#define SC_NX ((PP+127)/128)                  // 5
#define SC_MY ((PP+127)/128)                  // 5
#define SC_BLKS (SC_NX*SC_MY*BB)              // 200

__global__ __launch_bounds__(256, 2) void fused_scores_cls_kernel(
    const __half* __restrict__ qh, const __half* __restrict__ ql,
    const __half* __restrict__ kh, const __half* __restrict__ kl,
    float* __restrict__ scores, const float* __restrict__ posb,
    const __half* __restrict__ qkv, __half* __restrict__ attn)
{
    int bx = blockIdx.x;
    if (bx < SC_BLKS) {
        __shared__ Smem2 sm;
        int nx = bx % SC_NX;
        int my = (bx / SC_NX) % SC_MY;
        int bz = bx / (SC_NX*SC_MY);
        hmma3_tn_body(sm.Ah, sm.Al, sm.Bh, sm.Bl,
                      qh + (long)bz*PP*DD, ql + (long)bz*PP*DD,
                      kh + (long)bz*PP*DD, kl + (long)bz*PP*DD,
                      scores + (long)bz*PP*PP, PP, PP, DD,
                      posb, my*128, nx*128);
    } else {
        cls_attn_body(qkv, attn, bx - SC_BLKS);
    }
}

// ---------------- fused: q||k routing proj (3-MMA, FIRST) + QKV (hmma) -----
#define QKV_NX  (3*DD/TBN)                    // 18
#define QKV_MY  ((NROWS+TBM-1)/TBM)           // 37
#define QKV_BLKS (QKV_NX*QKV_MY)              // 666
#define QK2_NX  (2*DD/TBN)                    // 12
#define QK2_MY  ((PP+TBM-1)/TBM)              // 5
#define QK2_BLKS (QK2_NX*QK2_MY*BB)           // 480

__global__ __launch_bounds__(256, 2) void fused_qkv_qkproj_kernel(
    const __half* __restrict__ xnh, const __half* __restrict__ xnl,
    const __half* __restrict__ rqkv, const float* __restrict__ b_qkv,
    __half* __restrict__ qkvb,
    const __half* __restrict__ wqkh, const __half* __restrict__ wqkl,
    const float* __restrict__ bqk, float* __restrict__ qk)
{
    __shared__ Smem1 sm;
    int bx = blockIdx.x;
    if (bx < QK2_BLKS) {
        int nx = bx % QK2_NX;
        int my = (bx / QK2_NX) % QK2_MY;
        int bz = bx / (QK2_NX*QK2_MY);
        hmma3_nn_body(sm.h3.Ah, sm.h3.Al, sm.h3.Bh, sm.h3.Bl,
                      xnh + (long)bz*SS*DD + DD,
                      xnl + (long)bz*SS*DD + DD,
                      wqkh, wqkl,
                      qk + (long)bz*PP*2*DD, PP, 2*DD, DD, DD, 2*DD,
                      bqk, my*128, nx*128);
    } else {
        int rel = bx - QK2_BLKS;
        int bn = (rel % QKV_NX)*TBN, bm = (rel / QKV_NX)*TBM;
        hmma_body<1>(sm.h.As, sm.h.Bs, xnh, rqkv, qkvb,
                     NROWS, 3*DD, DD, DD, b_qkv, nullptr, bm, bn);
    }
}

// ---------------- warp-per-row top-32 + log-softmax weights ----------------
__global__ __launch_bounds__(256) void topk_warp_kernel(
    const float* __restrict__ scores, int* __restrict__ routes,
    float* __restrict__ logw)
{
    int warp = blockIdx.x*8 + (threadIdx.x >> 5);
    int lane = threadIdx.x & 31;
    const float* srw = scores + (long)warp*PP;
    float v[18];
    #pragma unroll
    for (int j = 0; j < 18; j++) v[j] = srw[j*32 + lane];

    float myTop = 0.f;
    for (int tt = 0; tt < KWIN; tt++) {
        float bv = -INFINITY; int bj = 0;
        #pragma unroll
        for (int j = 0; j < 18; j++)
            if (v[j] > bv) { bv = v[j]; bj = j; }
        int bi = bj*32 + lane;
        #pragma unroll
        for (int o = 16; o > 0; o >>= 1) {
            float ov = __shfl_xor_sync(0xffffffffu, bv, o);
            int   oi = __shfl_xor_sync(0xffffffffu, bi, o);
            if (ov > bv || (ov == bv && oi < bi)) { bv = ov; bi = oi; }
        }
        if (lane == (bi & 31)) v[bi >> 5] = -INFINITY;
        if (lane == tt) myTop = bv;
        if (lane == 0)  routes[(long)warp*KWIN + tt] = bi;
    }
    float m = __shfl_sync(0xffffffffu, myTop, 0);
    float e = expf(myTop - m);
    float z = e;
    #pragma unroll
    for (int o = 16; o > 0; o >>= 1) z += __shfl_xor_sync(0xffffffffu, z, o);
    float lse = m + logf(z);
    logw[(long)warp*KWIN + lane] = fmaxf(myTop - lse, -10.0f);
}

// ---------------- Patch attention: 4 heads per block, fp16 qkv -------------
__global__ __launch_bounds__(256) void patch_attn_kernel(
    const __half* __restrict__ qkv, const int* __restrict__ routes,
    const float* __restrict__ logw, __half* __restrict__ attn)
{
    int id = blockIdx.x;
    int hg = id % 3;
    int bp = id / 3;
    int p = bp % PP;
    int b = bp / PP;
    const __half* base = qkv + (long)b*SS*3*DD;
    int tid = threadIdx.x;
    int sub = tid >> 6;
    int t64 = tid & 63;
    int h = hg*4 + sub;

    __shared__ float qs[4][HDIM];
    __shared__ int   sr[KWIN];
    __shared__ float slw[KWIN];
    __shared__ float sa[4][KWIN];
    __shared__ float part[4][2][KWIN];

    qs[sub][t64] = __half2float(base[(long)(p+1)*3*DD + h*HDIM + t64]);
    if (tid < KWIN)                 sr[tid]      = routes[((long)bp)*KWIN + tid];
    else if (tid >= 32 && tid < 64) slw[tid-32]  = logw[((long)bp)*KWIN + tid-32];
    __syncthreads();

    int k = t64 & 31, half_ = t64 >> 5;
    const __half* kr = base + (long)(sr[k]+1)*3*DD + DD + h*HDIM + half_*32;
    float dot = 0.f;
    #pragma unroll
    for (int d = 0; d < 32; d++) dot = fmaf(qs[sub][half_*32+d], __half2float(kr[d]), dot);
    part[sub][half_][k] = dot;
    __syncthreads();

    if (t64 < KWIN) {
        float s = (part[sub][0][k]+part[sub][1][k]) * SCALE_ATT + slw[k];
        float m = s;
        #pragma unroll
        for (int o = 16; o > 0; o >>= 1) m = fmaxf(m, __shfl_xor_sync(0xffffffffu, m, o));
        float e = expf(s-m);
        float z = e;
        #pragma unroll
        for (int o = 16; o > 0; o >>= 1) z += __shfl_xor_sync(0xffffffffu, z, o);
        sa[sub][k] = e / z;
    }
    __syncthreads();

    float acc = 0.f;
    #pragma unroll 8
    for (int kk = 0; kk < KWIN; kk++)
        acc = fmaf(sa[sub][kk],
                   __half2float(base[(long)(sr[kk]+1)*3*DD + 2*DD + h*HDIM + t64]), acc);
    attn[((long)b*SS + p+1)*DD + h*HDIM + t64] = __float2half(acc);
}

// ---------------- launcher ----------------
extern "C" void kernel_launch(void* const* d_in, const int* in_sizes, int n_in,
                              void* d_out, int out_size)
{
    const float* x      = (const float*)d_in[0];
    const float* g1     = (const float*)d_in[1];
    const float* b1     = (const float*)d_in[2];
    const float* wq     = (const float*)d_in[3];
    const float* bq     = (const float*)d_in[4];
    const float* wk     = (const float*)d_in[5];
    const float* bk     = (const float*)d_in[6];
    const float* posb   = (const float*)d_in[7];
    const float* w_qkv  = (const float*)d_in[8];
    const float* b_qkv  = (const float*)d_in[9];
    const float* w_proj = (const float*)d_in[10];
    const float* b_proj = (const float*)d_in[11];
    const float* g2     = (const float*)d_in[12];
    const float* b2     = (const float*)d_in[13];
    const float* w_mlp1 = (const float*)d_in[14];
    const float* b_mlp1 = (const float*)d_in[15];
    const float* w_mlp2 = (const float*)d_in[16];
    const float* b_mlp2 = (const float*)d_in[17];
    float* out = (float*)d_out;

    float *qk, *scores, *logw, *x1, *bqk;
    __half *xnh, *xnl, *qh, *ql, *kh, *kl, *qkvb, *attn, *xn2, *hbuf;
    __half *rqkv, *rproj, *rm1, *rm2, *wqkh, *wqkl;
    int *routes;
    cudaGetSymbolAddress((void**)&xnh,    g_xnh);
    cudaGetSymbolAddress((void**)&xnl,    g_xnl);
    cudaGetSymbolAddress((void**)&qk,     g_qk);
    cudaGetSymbolAddress((void**)&qh,     g_qh);
    cudaGetSymbolAddress((void**)&ql,     g_ql);
    cudaGetSymbolAddress((void**)&kh,     g_kh);
    cudaGetSymbolAddress((void**)&kl,     g_kl);
    cudaGetSymbolAddress((void**)&scores, g_scores);
    cudaGetSymbolAddress((void**)&routes, g_routes);
    cudaGetSymbolAddress((void**)&logw,   g_logw);
    cudaGetSymbolAddress((void**)&qkvb,   g_qkvh);
    cudaGetSymbolAddress((void**)&attn,   g_attn);
    cudaGetSymbolAddress((void**)&x1,     g_x1);
    cudaGetSymbolAddress((void**)&xn2,    g_xn2);
    cudaGetSymbolAddress((void**)&hbuf,   g_h);
    cudaGetSymbolAddress((void**)&rqkv,   g_rqkv);
    cudaGetSymbolAddress((void**)&rproj,  g_rproj);
    cudaGetSymbolAddress((void**)&rm1,    g_rm1);
    cudaGetSymbolAddress((void**)&rm2,    g_rm2);
    cudaGetSymbolAddress((void**)&wqkh,   g_wqkh);
    cudaGetSymbolAddress((void**)&wqkl,   g_wqkl);
    cudaGetSymbolAddress((void**)&bqk,    g_bqk);

    // 0. weight prep (single launch)
    pack_combined_kernel<<<PK_ALL, 256>>>(w_qkv, rqkv, w_proj, rproj,
                                          w_mlp1, rm1, w_mlp2, rm2,
                                          wq, wk, bq, bk, wqkh, wqkl, bqk);

    // 1. LN1 -> hi + lo fp16
    ln_kernel<<<NROWS, 256>>>(x, g1, b1, xnh, xnl);

    // 2. FUSED: q||k routing proj (3-MMA, slow blocks first) + QKV (fp16 out)
    fused_qkv_qkproj_kernel<<<QKV_BLKS + QK2_BLKS, 256>>>(
        xnh, xnl, rqkv, b_qkv, qkvb, wqkh, wqkl, bqk, qk);

    // 3. l2 normalize + split q,k (one block per row)
    l2norm_split_kernel<<<BB*PP, 256>>>(qk, qh, ql, kh, kl);

    // 4. FUSED: routing scores (double-fp16 TN) + CLS attention
    fused_scores_cls_kernel<<<SC_BLKS + BB*HH, 256>>>(
        qh, ql, kh, kl, scores, posb, qkvb, attn);

    // 5. top-32 + log-softmax weights (warp per row)
    topk_warp_kernel<<<BB*PP/8, 256>>>(scores, routes, logw);

    // 6. patch attention (4 heads per block, fp16 gather)
    patch_attn_kernel<<<BB*PP*3, 256>>>(qkvb, routes, logw, attn);

    // 7. proj + residual x (fp16 HMMA TBM=64, 4-stage)
    {
        dim3 grid(DD/TBN, (NROWS+63)/64);
        hmma64_nn_kernel<2><<<grid, 256>>>(attn, rproj, x1, NROWS, DD, DD, DD,
                                           b_proj, x);
    }
    // 8. LN2 (fp16 hi only, feeds MLP1)
    ln_kernel<<<NROWS, 256>>>(x1, g2, b2, xn2, nullptr);

    // 9. MLP1 + exact GELU (fp16 HMMA TBM=64, 4-stage)
    {
        dim3 grid(MLPD/TBN, (NROWS+63)/64);
        hmma64_nn_kernel<3><<<grid, 256>>>(xn2, rm1, hbuf, NROWS, MLPD, DD, DD,
                                           b_mlp1, nullptr);
    }
    // 10. MLP2 + residual x1 -> out (fp16 HMMA TBM=64, 4-stage)
    {
        dim3 grid(DD/TBN, (NROWS+63)/64);
        hmma64_nn_kernel<2><<<grid, 256>>>(hbuf, rm2, out, NROWS, DD, MLPD, MLPD,
                                           b_mlp2, x1);
    }
}